// round 8
// baseline (speedup 1.0000x reference)
#include <cuda_runtime.h>
#include <cstddef>

#define DIMN 1024
#define NH   16
#define DK   64
#define BATCH 4
#define QL   1024
#define KL   1024

// Scratch (device globals: allocation-free rule)
__device__ float g_Qh[BATCH*NH*QL*DK];   // [b*16+h][q][d], pre-scaled by 1/8
__device__ float g_Kh[BATCH*NH*KL*DK];
__device__ float g_Vh[BATCH*NH*KL*DK];
__device__ float g_vals[BATCH*QL*DIMN];  // attention out, [b,q, d*16+h]
__device__ float g_W2[DIMN*DIMN];        // Wout @ Wout
__device__ unsigned char g_mask8[BATCH*QL*KL];
__device__ int g_isByte;
__device__ int g_allTrue;

// ---------------------------------------------------------------------------
__device__ __forceinline__ unsigned f2tf(float x) {
    unsigned r;
    asm("cvt.rna.tf32.f32 %0, %1;" : "=r"(r) : "f"(x));
    return r;
}

__device__ __forceinline__ void mma_tf32(float c[4], const unsigned a[4], const unsigned b[2]) {
    asm("mma.sync.aligned.m16n8k8.row.col.f32.tf32.tf32.f32 "
        "{%0,%1,%2,%3}, {%4,%5,%6,%7}, {%8,%9}, {%0,%1,%2,%3};"
        : "+f"(c[0]), "+f"(c[1]), "+f"(c[2]), "+f"(c[3])
        : "r"(a[0]), "r"(a[1]), "r"(a[2]), "r"(a[3]), "r"(b[0]), "r"(b[1]));
}

// ---------------------------------------------------------------------------
// Mask dtype detect (int32 vs byte)
// ---------------------------------------------------------------------------
__global__ void mask_detect_kernel(const unsigned char* __restrict__ m)
{
    __shared__ int found;
    if (threadIdx.x == 0) { found = 0; g_allTrue = 1; }
    __syncthreads();
    for (int i = threadIdx.x; i < 16384; i += blockDim.x)
        if ((i & 3) && m[i]) found = 1;
    __syncthreads();
    if (threadIdx.x == 0) g_isByte = found;
}

__global__ void mask_convert_kernel(const unsigned char* __restrict__ m, int n)
{
    int i = blockIdx.x * blockDim.x + threadIdx.x;
    int v = 1;
    if (i < n) {
        v = g_isByte ? (m[i] ? 1 : 0) : (((const unsigned*)m)[i] ? 1 : 0);
        g_mask8[i] = (unsigned char)v;
    }
    int all = __syncthreads_and(v);
    if (!all && threadIdx.x == 0) g_allTrue = 0;
}

// ---------------------------------------------------------------------------
// GEMM core: BM=BN=128, BK=32, 128 threads = 4 warps (2M x 2N), warp 64x64.
// SMEM row-major stride 36 (conflict-free frag loads: bank = 4*g + t).
// Double-buffered (2 x 36KB dynamic) with register prefetch: LDG for tile
// kt+1 issued before compute(kt); cvt+STS after compute; one sync per iter.
// ---------------------------------------------------------------------------
#define LDS_T 36
#define BUFW (128 * LDS_T)          // words per matrix buffer
#define GEMM_SMEM (4 * BUFW * 4)    // A0,B0,A1,B1 = 73728 B

__device__ __forceinline__ void loadTile(float4 r[8], const float* __restrict__ P,
                                         int ld, int kk, int tid) {
#pragma unroll
    for (int i = 0; i < 8; i++) {
        int f = tid + i * 128;
        int row = f >> 3, kq = (f & 7) * 4;
        r[i] = *(const float4*)&P[(size_t)row * ld + kk + kq];
    }
}
__device__ __forceinline__ void storeTile(unsigned* __restrict__ S, const float4 r[8], int tid) {
#pragma unroll
    for (int i = 0; i < 8; i++) {
        int f = tid + i * 128;
        int row = f >> 3, kq = (f & 7) * 4;
        unsigned* d = &S[row * LDS_T + kq];
        d[0] = f2tf(r[i].x); d[1] = f2tf(r[i].y); d[2] = f2tf(r[i].z); d[3] = f2tf(r[i].w);
    }
}
// transposed-B staging (W row-major [K][N], want Bs[n][k]) — W2 only
__device__ __forceinline__ void stageBT(unsigned* Bs, const float* __restrict__ W,
                                        int n0, int kk, int ldn, int tid) {
#pragma unroll
    for (int i = 0; i < 8; i++) {
        int f = tid + i * 128;
        int kr = f >> 5, nq = (f & 31) * 4;
        float4 v = *(const float4*)&W[(size_t)(kk + kr) * ldn + n0 + nq];
        Bs[(nq + 0) * LDS_T + kr] = f2tf(v.x);
        Bs[(nq + 1) * LDS_T + kr] = f2tf(v.y);
        Bs[(nq + 2) * LDS_T + kr] = f2tf(v.z);
        Bs[(nq + 3) * LDS_T + kr] = f2tf(v.w);
    }
}

__device__ __forceinline__ void compute_tile(const unsigned* __restrict__ As,
                                             const unsigned* __restrict__ Bs,
                                             float c[4][8][4], int wm, int wn, int g, int t) {
#pragma unroll
    for (int ks = 0; ks < 4; ks++) {
        const int k8 = ks * 8;
        unsigned a[4][4];
#pragma unroll
        for (int mt = 0; mt < 4; mt++) {
            int r = wm * 64 + mt * 16;
            a[mt][0] = As[(r + g) * LDS_T + k8 + t];
            a[mt][1] = As[(r + 8 + g) * LDS_T + k8 + t];
            a[mt][2] = As[(r + g) * LDS_T + k8 + 4 + t];
            a[mt][3] = As[(r + 8 + g) * LDS_T + k8 + 4 + t];
        }
#pragma unroll
        for (int nt = 0; nt < 8; nt++) {
            int cx = wn * 64 + nt * 8;
            unsigned bf[2];
            bf[0] = Bs[(cx + g) * LDS_T + k8 + t];
            bf[1] = Bs[(cx + g) * LDS_T + k8 + 4 + t];
#pragma unroll
            for (int mt = 0; mt < 4; mt++)
                mma_tf32(c[mt][nt], a[mt], bf);
        }
    }
}

// ---------------------------------------------------------------------------
// MODE 0: C = A @ W^T (plain store, double-buffered prefetch)
// MODE 3: C = A @ W   (transposed-B, simple sync loop; W2 only, small)
// ---------------------------------------------------------------------------
template<int MODE>
__global__ __launch_bounds__(128, 2)
void mma_gemm(const float* __restrict__ A, const float* __restrict__ W,
              float* __restrict__ C, int M, int N, int K)
{
    extern __shared__ unsigned sh[];
    unsigned* Abuf[2] = { sh,            sh + 2 * BUFW };
    unsigned* Bbuf[2] = { sh + BUFW,     sh + 3 * BUFW };

    const int tid = threadIdx.x;
    const int m0 = blockIdx.y * 128, n0 = blockIdx.x * 128;
    const int warp = tid >> 5, lane = tid & 31;
    const int wm = warp & 1, wn = warp >> 1;
    const int g = lane >> 2, t = lane & 3;

    float c[4][8][4];
#pragma unroll
    for (int mt = 0; mt < 4; mt++)
#pragma unroll
        for (int nt = 0; nt < 8; nt++)
#pragma unroll
            for (int i = 0; i < 4; i++) c[mt][nt][i] = 0.f;

    if (MODE == 3) {
        for (int kk = 0; kk < K; kk += 32) {
            float4 ra[8];
            loadTile(ra, A + (size_t)m0 * K, K, kk, tid);
            storeTile(Abuf[0], ra, tid);
            stageBT(Bbuf[0], W, n0, kk, N, tid);
            __syncthreads();
            compute_tile(Abuf[0], Bbuf[0], c, wm, wn, g, t);
            __syncthreads();
        }
    } else {
        const float* Ap = A + (size_t)m0 * K;
        const float* Wp = W + (size_t)n0 * K;
        float4 ra[8], rb[8];
        loadTile(ra, Ap, K, 0, tid);
        loadTile(rb, Wp, K, 0, tid);
        storeTile(Abuf[0], ra, tid);
        storeTile(Bbuf[0], rb, tid);
        __syncthreads();
        int cur = 0;
        for (int kk = 32; kk < K; kk += 32) {
            loadTile(ra, Ap, K, kk, tid);
            loadTile(rb, Wp, K, kk, tid);
            compute_tile(Abuf[cur], Bbuf[cur], c, wm, wn, g, t);
            cur ^= 1;
            storeTile(Abuf[cur], ra, tid);
            storeTile(Bbuf[cur], rb, tid);
            __syncthreads();
        }
        compute_tile(Abuf[cur], Bbuf[cur], c, wm, wn, g, t);
    }

#pragma unroll
    for (int mt = 0; mt < 4; mt++) {
        int r0 = m0 + wm * 64 + mt * 16 + g;
        int r1 = r0 + 8;
#pragma unroll
        for (int nt = 0; nt < 8; nt++) {
            int col = n0 + wn * 64 + nt * 8 + 2 * t;
            *(float2*)&C[(size_t)r0 * N + col] = make_float2(c[mt][nt][0], c[mt][nt][1]);
            *(float2*)&C[(size_t)r1 * N + col] = make_float2(c[mt][nt][2], c[mt][nt][3]);
        }
    }
}

// ---------------------------------------------------------------------------
// Merged projections (double-buffered prefetch):
//  grid.x 0..7  -> Q proj (dec@Wq^T, scaled per-head scatter)
//  grid.x 8..23 -> KV proj (enc@Wkv^T, K/V per-head scatter)
// ---------------------------------------------------------------------------
__global__ __launch_bounds__(128, 2)
void proj_gemm(const float* __restrict__ dec, const float* __restrict__ enc,
               const float* __restrict__ Wq, const float* __restrict__ Wkv)
{
    extern __shared__ unsigned sh[];
    unsigned* Abuf[2] = { sh,            sh + 2 * BUFW };
    unsigned* Bbuf[2] = { sh + BUFW,     sh + 3 * BUFW };

    const int tid = threadIdx.x;
    const bool isQ = blockIdx.x < 8;
    const float* A = isQ ? dec : enc;
    const float* W = isQ ? Wq : Wkv;
    const int n0 = (isQ ? blockIdx.x : (blockIdx.x - 8)) * 128;
    const int m0 = blockIdx.y * 128;
    const int K = DIMN;
    const int warp = tid >> 5, lane = tid & 31;
    const int wm = warp & 1, wn = warp >> 1;
    const int g = lane >> 2, t = lane & 3;

    float c[4][8][4];
#pragma unroll
    for (int mt = 0; mt < 4; mt++)
#pragma unroll
        for (int nt = 0; nt < 8; nt++)
#pragma unroll
            for (int i = 0; i < 4; i++) c[mt][nt][i] = 0.f;

    const float* Ap = A + (size_t)m0 * K;
    const float* Wp = W + (size_t)n0 * K;
    float4 ra[8], rb[8];
    loadTile(ra, Ap, K, 0, tid);
    loadTile(rb, Wp, K, 0, tid);
    storeTile(Abuf[0], ra, tid);
    storeTile(Bbuf[0], rb, tid);
    __syncthreads();
    int cur = 0;
    for (int kk = 32; kk < K; kk += 32) {
        loadTile(ra, Ap, K, kk, tid);
        loadTile(rb, Wp, K, kk, tid);
        compute_tile(Abuf[cur], Bbuf[cur], c, wm, wn, g, t);
        cur ^= 1;
        storeTile(Abuf[cur], ra, tid);
        storeTile(Bbuf[cur], rb, tid);
        __syncthreads();
    }
    compute_tile(Abuf[cur], Bbuf[cur], c, wm, wn, g, t);

    // scatter epilogue (validated R3/R5/R6)
#pragma unroll
    for (int mt = 0; mt < 4; mt++) {
        int r0 = wm * 64 + mt * 16 + g;
        int r1 = r0 + 8;
#pragma unroll
        for (int nt = 0; nt < 8; nt++) {
            int col = n0 + wn * 64 + nt * 8 + 2 * t;
#pragma unroll
            for (int e = 0; e < 4; e++) {
                int m = m0 + ((e < 2) ? r0 : r1);
                int n = col + (e & 1);
                float v = c[mt][nt][e];
                int b = m >> 10, q = m & 1023;
                if (isQ) {
                    int h = n & 15, d = n >> 4;
                    g_Qh[(((size_t)(b * NH + h) * QL + q) * DK) + d] = v * 0.125f;
                } else if (n < DIMN) {
                    int h = n & 15, d = n >> 4;
                    g_Kh[(((size_t)(b * NH + h) * KL + q) * DK) + d] = v;
                } else {
                    int nn = n - DIMN;
                    int h = nn & 15, d = nn >> 4;
                    g_Vh[(((size_t)(b * NH + h) * KL + q) * DK) + d] = v;
                }
            }
        }
    }
}

// ---------------------------------------------------------------------------
// Fused attention (unchanged — bit-identical numerics to R3/R5/R6)
// ---------------------------------------------------------------------------
#define ATT_LD 68
#define SMEM_ATTN (4 * 64 * ATT_LD * 4 + 64 * 64)

__global__ __launch_bounds__(128)
void attn_kernel(float* __restrict__ vals)
{
    extern __shared__ unsigned smU[];
    unsigned* Qs = smU;
    unsigned* Ks = Qs + 64 * ATT_LD;
    unsigned* Vt = Ks + 64 * ATT_LD;
    unsigned* Ps = Vt + 64 * ATT_LD;
    unsigned char* Ms = (unsigned char*)(Ps + 64 * ATT_LD);

    const int head = blockIdx.y;
    const int b = head >> 4, h = head & 15;
    const int q0 = blockIdx.x * 64;
    const int tid = threadIdx.x;
    const int w = tid >> 5, lane = tid & 31;
    const int g = lane >> 2, t = lane & 3;
    const int wq0 = w * 16;
    const int allTrue = g_allTrue;

    const float* Qp = g_Qh + (size_t)head * QL * DK;
    const float* Kp = g_Kh + (size_t)head * KL * DK;
    const float* Vp = g_Vh + (size_t)head * KL * DK;

#pragma unroll
    for (int i = 0; i < 8; i++) {
        int f = tid + i * 128;
        int row = f >> 4, dq = (f & 15) * 4;
        float4 qv = *(const float4*)&Qp[(size_t)(q0 + row) * DK + dq];
        unsigned* d = &Qs[row * ATT_LD + dq];
        d[0] = f2tf(qv.x); d[1] = f2tf(qv.y); d[2] = f2tf(qv.z); d[3] = f2tf(qv.w);
    }

    float o[8][4];
#pragma unroll
    for (int nt = 0; nt < 8; nt++)
#pragma unroll
        for (int i = 0; i < 4; i++) o[nt][i] = 0.f;
    float l0 = 0.f, l1 = 0.f;

    for (int k0 = 0; k0 < KL; k0 += 64) {
#pragma unroll
        for (int i = 0; i < 8; i++) {
            int f = tid + i * 128;
            int row = f >> 4, dq = (f & 15) * 4;
            float4 kv = *(const float4*)&Kp[(size_t)(k0 + row) * DK + dq];
            unsigned* d = &Ks[row * ATT_LD + dq];
            d[0] = f2tf(kv.x); d[1] = f2tf(kv.y); d[2] = f2tf(kv.z); d[3] = f2tf(kv.w);
            float4 vv = *(const float4*)&Vp[(size_t)(k0 + row) * DK + dq];
            Vt[(dq + 0) * ATT_LD + row] = f2tf(vv.x);
            Vt[(dq + 1) * ATT_LD + row] = f2tf(vv.y);
            Vt[(dq + 2) * ATT_LD + row] = f2tf(vv.z);
            Vt[(dq + 3) * ATT_LD + row] = f2tf(vv.w);
        }
        if (!allTrue) {
            const unsigned* mrow = (const unsigned*)(g_mask8 + ((size_t)(b * QL + q0)) * KL + k0);
#pragma unroll
            for (int i = 0; i < 8; i++) {
                int f = tid + i * 128;
                int qr = f >> 4, kq = f & 15;
                ((unsigned*)Ms)[qr * 16 + kq] =
                    *(const unsigned*)((const unsigned char*)mrow + (size_t)qr * KL + kq * 4);
            }
        }
        __syncthreads();

        float s[8][4];
#pragma unroll
        for (int nt = 0; nt < 8; nt++)
#pragma unroll
            for (int i = 0; i < 4; i++) s[nt][i] = 0.f;

#pragma unroll
        for (int ks = 0; ks < 8; ks++) {
            const int k8 = ks * 8;
            unsigned a[4];
            a[0] = Qs[(wq0 + g) * ATT_LD + k8 + t];
            a[1] = Qs[(wq0 + 8 + g) * ATT_LD + k8 + t];
            a[2] = Qs[(wq0 + g) * ATT_LD + k8 + 4 + t];
            a[3] = Qs[(wq0 + 8 + g) * ATT_LD + k8 + 4 + t];
#pragma unroll
            for (int nt = 0; nt < 8; nt++) {
                unsigned bf[2];
                bf[0] = Ks[(nt * 8 + g) * ATT_LD + k8 + t];
                bf[1] = Ks[(nt * 8 + g) * ATT_LD + k8 + 4 + t];
                mma_tf32(s[nt], a, bf);
            }
        }

        int qr0 = wq0 + g, qr1 = wq0 + 8 + g;
        float rs0 = 0.f, rs1 = 0.f;
#pragma unroll
        for (int nt = 0; nt < 8; nt++) {
            int kc = nt * 8 + 2 * t;
            float p00, p01, p10, p11;
            if (allTrue) {
                p00 = __expf(s[nt][0]); p01 = __expf(s[nt][1]);
                p10 = __expf(s[nt][2]); p11 = __expf(s[nt][3]);
            } else {
                p00 = Ms[qr0 * 64 + kc]     ? __expf(s[nt][0]) : 0.f;
                p01 = Ms[qr0 * 64 + kc + 1] ? __expf(s[nt][1]) : 0.f;
                p10 = Ms[qr1 * 64 + kc]     ? __expf(s[nt][2]) : 0.f;
                p11 = Ms[qr1 * 64 + kc + 1] ? __expf(s[nt][3]) : 0.f;
            }
            rs0 += p00 + p01;
            rs1 += p10 + p11;
            *(uint2*)&Ps[qr0 * ATT_LD + kc] = make_uint2(f2tf(p00), f2tf(p01));
            *(uint2*)&Ps[qr1 * ATT_LD + kc] = make_uint2(f2tf(p10), f2tf(p11));
        }
        rs0 += __shfl_xor_sync(0xffffffffu, rs0, 1);
        rs0 += __shfl_xor_sync(0xffffffffu, rs0, 2);
        rs1 += __shfl_xor_sync(0xffffffffu, rs1, 1);
        rs1 += __shfl_xor_sync(0xffffffffu, rs1, 2);
        l0 += rs0;
        l1 += rs1;
        __syncwarp();

#pragma unroll
        for (int ks = 0; ks < 8; ks++) {
            const int k8 = ks * 8;
            unsigned a[4];
            a[0] = Ps[(wq0 + g) * ATT_LD + k8 + t];
            a[1] = Ps[(wq0 + 8 + g) * ATT_LD + k8 + t];
            a[2] = Ps[(wq0 + g) * ATT_LD + k8 + 4 + t];
            a[3] = Ps[(wq0 + 8 + g) * ATT_LD + k8 + 4 + t];
#pragma unroll
            for (int nt = 0; nt < 8; nt++) {
                unsigned bf[2];
                bf[0] = Vt[(nt * 8 + g) * ATT_LD + k8 + t];
                bf[1] = Vt[(nt * 8 + g) * ATT_LD + k8 + 4 + t];
                mma_tf32(o[nt], a, bf);
            }
        }
        __syncthreads();
    }

    float inv0 = 1.f / l0, inv1 = 1.f / l1;
    int qa = q0 + wq0 + g, qb = qa + 8;
#pragma unroll
    for (int nt = 0; nt < 8; nt++) {
        int d = nt * 8 + 2 * t;
        float* base0 = &g_vals[((size_t)(b * QL + qa)) * DIMN + d * NH + h];
        float* base1 = &g_vals[((size_t)(b * QL + qb)) * DIMN + d * NH + h];
        base0[0]  = o[nt][0] * inv0;
        base0[NH] = o[nt][1] * inv0;
        base1[0]  = o[nt][2] * inv1;
        base1[NH] = o[nt][3] * inv1;
    }
    (void)vals;
}

// ---------------------------------------------------------------------------
extern "C" void kernel_launch(void* const* d_in, const int* in_sizes, int n_in,
                              void* d_out, int out_size)
{
    const float* dec  = (const float*)d_in[0];
    const float* enc  = (const float*)d_in[1];
    const unsigned char* mask = (const unsigned char*)d_in[2];
    const float* Wq   = (const float*)d_in[3];
    const float* Wkv  = (const float*)d_in[4];
    const float* Wout = (const float*)d_in[5];
    float* out = (float*)d_out;

    float *vals_p, *w2_p;
    cudaGetSymbolAddress((void**)&vals_p, g_vals);
    cudaGetSymbolAddress((void**)&w2_p, g_W2);

    cudaFuncSetAttribute(mma_gemm<0>, cudaFuncAttributeMaxDynamicSharedMemorySize, GEMM_SMEM);
    cudaFuncSetAttribute(mma_gemm<3>, cudaFuncAttributeMaxDynamicSharedMemorySize, GEMM_SMEM);
    cudaFuncSetAttribute(proj_gemm,   cudaFuncAttributeMaxDynamicSharedMemorySize, GEMM_SMEM);
    cudaFuncSetAttribute(attn_kernel, cudaFuncAttributeMaxDynamicSharedMemorySize, SMEM_ATTN);

    const int M = BATCH * QL; // 4096
    const int NMASK = BATCH * QL * KL;
    dim3 blk(128);

    mask_detect_kernel<<<1, 256>>>(mask);
    mask_convert_kernel<<<(NMASK + 255) / 256, 256>>>(mask, NMASK);

    // W2 = Wout @ Wout  (transposed-B staging)
    mma_gemm<3><<<dim3(8, 8), blk, GEMM_SMEM>>>(Wout, Wout, w2_p, DIMN, DIMN, DIMN);
    // merged Q + KV projections (scattered per-head)
    proj_gemm<<<dim3(24, M / 128), blk, GEMM_SMEM>>>(dec, enc, Wq, Wkv);
    // fused attention -> g_vals
    attn_kernel<<<dim3(QL / 64, BATCH * NH), dim3(128), SMEM_ATTN>>>(vals_p);
    // out = vals @ W2^T
    mma_gemm<0><<<dim3(8, M / 128), blk, GEMM_SMEM>>>(vals_p, w2_p, out, M, DIMN, DIMN);
}

// round 9
// speedup vs baseline: 1.1536x; 1.1536x over previous
#include <cuda_runtime.h>
#include <cstddef>
#include <cstdint>

#define DIMN 1024
#define NH   16
#define DK   64
#define BATCH 4
#define QL   1024
#define KL   1024

// Scratch (device globals: allocation-free rule)
__device__ float g_Qh[BATCH*NH*QL*DK];   // tf32-rounded, pre-scaled by 1/8
__device__ float g_Kh[BATCH*NH*KL*DK];   // tf32-rounded
__device__ float g_Vh[BATCH*NH*KL*DK];   // tf32-rounded
__device__ float g_vals[BATCH*QL*DIMN];  // attention out, tf32-rounded
__device__ float g_W2[DIMN*DIMN];        // Wout @ Wout, tf32-rounded
__device__ float g_decT[BATCH*QL*DIMN];  // tf32-rounded dec
__device__ float g_encT[BATCH*KL*DIMN];  // tf32-rounded enc
__device__ float g_WqT[DIMN*DIMN];       // tf32-rounded Wq
__device__ float g_WkvT[2*DIMN*DIMN];    // tf32-rounded Wkv
__device__ unsigned char g_mask8[BATCH*QL*KL];
__device__ int g_isByte;
__device__ int g_allTrue;

// ---------------------------------------------------------------------------
__device__ __forceinline__ unsigned f2tf(float x) {
    unsigned r;
    asm("cvt.rna.tf32.f32 %0, %1;" : "=r"(r) : "f"(x));
    return r;
}

__device__ __forceinline__ void mma_tf32(float c[4], const unsigned a[4], const unsigned b[2]) {
    asm("mma.sync.aligned.m16n8k8.row.col.f32.tf32.tf32.f32 "
        "{%0,%1,%2,%3}, {%4,%5,%6,%7}, {%8,%9}, {%0,%1,%2,%3};"
        : "+f"(c[0]), "+f"(c[1]), "+f"(c[2]), "+f"(c[3])
        : "r"(a[0]), "r"(a[1]), "r"(a[2]), "r"(a[3]), "r"(b[0]), "r"(b[1]));
}

__device__ __forceinline__ void cpasync16(uint32_t dst, const void* src) {
    asm volatile("cp.async.cg.shared.global [%0], [%1], 16;" :: "r"(dst), "l"(src));
}
#define CP_COMMIT()  asm volatile("cp.async.commit_group;" ::: "memory")
#define CP_WAIT(n)   asm volatile("cp.async.wait_group %0;" :: "n"(n) : "memory")

// ---------------------------------------------------------------------------
// tf32 pre-round prep (vectorized streaming)
// ---------------------------------------------------------------------------
__global__ void cvt_tf32_kernel(const float* __restrict__ src, float* __restrict__ dst, int n)
{
    int i = (blockIdx.x * blockDim.x + threadIdx.x) * 4;
    if (i < n) {
        float4 v = *(const float4*)&src[i];
        uint4 u = make_uint4(f2tf(v.x), f2tf(v.y), f2tf(v.z), f2tf(v.w));
        *(uint4*)&dst[i] = u;
    }
}

// ---------------------------------------------------------------------------
// Mask dtype detect (int32 vs byte)
// ---------------------------------------------------------------------------
__global__ void mask_detect_kernel(const unsigned char* __restrict__ m)
{
    __shared__ int found;
    if (threadIdx.x == 0) { found = 0; g_allTrue = 1; }
    __syncthreads();
    for (int i = threadIdx.x; i < 16384; i += blockDim.x)
        if ((i & 3) && m[i]) found = 1;
    __syncthreads();
    if (threadIdx.x == 0) g_isByte = found;
}

__global__ void mask_convert_kernel(const unsigned char* __restrict__ m, int n)
{
    int i = blockIdx.x * blockDim.x + threadIdx.x;
    int v = 1;
    if (i < n) {
        v = g_isByte ? (m[i] ? 1 : 0) : (((const unsigned*)m)[i] ? 1 : 0);
        g_mask8[i] = (unsigned char)v;
    }
    int all = __syncthreads_and(v);
    if (!all && threadIdx.x == 0) g_allTrue = 0;
}

// ---------------------------------------------------------------------------
// GEMM core: BM=BN=128, BK=32, 128 threads = 4 warps (2M x 2N), warp 64x64.
// SMEM stride 36 words (conflict-free frags: bank = 4*g + t).
// Staging via cp.async (sources pre-rounded to tf32) — zero RF, 2-stage pipe.
// ---------------------------------------------------------------------------
#define LDS_T 36
#define BUFW (128 * LDS_T)
#define GEMM_SMEM (4 * BUFW * 4)    // A0,B0,A1,B1 = 73728 B

__device__ __forceinline__ void issueTile(uint32_t Sb, const float* __restrict__ P,
                                          int ld, int kk, int tid) {
#pragma unroll
    for (int i = 0; i < 8; i++) {
        int f = tid + i * 128;
        int row = f >> 3, kq = (f & 7) * 4;
        cpasync16(Sb + (uint32_t)(row * LDS_T + kq) * 4, P + (size_t)row * ld + kk + kq);
    }
}

// RF staging (cvt path) — W2 kernel only
__device__ __forceinline__ void stageRF(unsigned* S, const float* __restrict__ P,
                                        int ld, int kk, int tid) {
#pragma unroll
    for (int i = 0; i < 8; i++) {
        int f = tid + i * 128;
        int row = f >> 3, kq = (f & 7) * 4;
        float4 v = *(const float4*)&P[(size_t)row * ld + kk + kq];
        unsigned* d = &S[row * LDS_T + kq];
        d[0] = f2tf(v.x); d[1] = f2tf(v.y); d[2] = f2tf(v.z); d[3] = f2tf(v.w);
    }
}
// transposed-B staging (W row-major [K][N], want Bs[n][k]) — W2 only
__device__ __forceinline__ void stageBT(unsigned* Bs, const float* __restrict__ W,
                                        int n0, int kk, int ldn, int tid) {
#pragma unroll
    for (int i = 0; i < 8; i++) {
        int f = tid + i * 128;
        int kr = f >> 5, nq = (f & 31) * 4;
        float4 v = *(const float4*)&W[(size_t)(kk + kr) * ldn + n0 + nq];
        Bs[(nq + 0) * LDS_T + kr] = f2tf(v.x);
        Bs[(nq + 1) * LDS_T + kr] = f2tf(v.y);
        Bs[(nq + 2) * LDS_T + kr] = f2tf(v.z);
        Bs[(nq + 3) * LDS_T + kr] = f2tf(v.w);
    }
}

__device__ __forceinline__ void compute_tile(const unsigned* __restrict__ As,
                                             const unsigned* __restrict__ Bs,
                                             float c[4][8][4], int wm, int wn, int g, int t) {
#pragma unroll
    for (int ks = 0; ks < 4; ks++) {
        const int k8 = ks * 8;
        unsigned a[4][4];
#pragma unroll
        for (int mt = 0; mt < 4; mt++) {
            int r = wm * 64 + mt * 16;
            a[mt][0] = As[(r + g) * LDS_T + k8 + t];
            a[mt][1] = As[(r + 8 + g) * LDS_T + k8 + t];
            a[mt][2] = As[(r + g) * LDS_T + k8 + 4 + t];
            a[mt][3] = As[(r + 8 + g) * LDS_T + k8 + 4 + t];
        }
#pragma unroll
        for (int nt = 0; nt < 8; nt++) {
            int cx = wn * 64 + nt * 8;
            unsigned bf[2];
            bf[0] = Bs[(cx + g) * LDS_T + k8 + t];
            bf[1] = Bs[(cx + g) * LDS_T + k8 + 4 + t];
#pragma unroll
            for (int mt = 0; mt < 4; mt++)
                mma_tf32(c[mt][nt], a[mt], bf);
        }
    }
}

// cp.async pipelined mainloop over K (both operands K-major, pre-rounded)
__device__ __forceinline__ void pipe_loop(uint32_t shb, const float* __restrict__ Ap,
                                          const float* __restrict__ Wp, int K,
                                          unsigned* sh, float c[4][8][4],
                                          int wm, int wn, int g, int t, int tid)
{
    const uint32_t Ab[2] = { shb, shb + 2 * BUFW * 4 };
    const uint32_t Bb[2] = { shb + BUFW * 4, shb + 3 * BUFW * 4 };
    unsigned* Abp[2] = { sh, sh + 2 * BUFW };
    unsigned* Bbp[2] = { sh + BUFW, sh + 3 * BUFW };
    const int NIT = K / 32;

    issueTile(Ab[0], Ap, K, 0, tid);
    issueTile(Bb[0], Wp, K, 0, tid);
    CP_COMMIT();
    int cur = 0;
    for (int kt = 0; kt < NIT - 1; kt++) {
        int nxt = cur ^ 1;
        issueTile(Ab[nxt], Ap, K, (kt + 1) * 32, tid);
        issueTile(Bb[nxt], Wp, K, (kt + 1) * 32, tid);
        CP_COMMIT();
        CP_WAIT(1);
        __syncthreads();
        compute_tile(Abp[cur], Bbp[cur], c, wm, wn, g, t);
        __syncthreads();
        cur = nxt;
    }
    CP_WAIT(0);
    __syncthreads();
    compute_tile(Abp[cur], Bbp[cur], c, wm, wn, g, t);
}

// ---------------------------------------------------------------------------
// Final GEMM: C = A @ W^T, plain store (A=g_vals, W=g_W2, both pre-rounded)
// ---------------------------------------------------------------------------
__global__ __launch_bounds__(128, 2)
void final_gemm(const float* __restrict__ A, const float* __restrict__ W,
                float* __restrict__ C, int M, int N, int K)
{
    extern __shared__ unsigned sh[];
    uint32_t shb = (uint32_t)__cvta_generic_to_shared(sh);
    const int tid = threadIdx.x;
    const int m0 = blockIdx.y * 128, n0 = blockIdx.x * 128;
    const int warp = tid >> 5, lane = tid & 31;
    const int wm = warp & 1, wn = warp >> 1;
    const int g = lane >> 2, t = lane & 3;

    float c[4][8][4];
#pragma unroll
    for (int mt = 0; mt < 4; mt++)
#pragma unroll
        for (int nt = 0; nt < 8; nt++)
#pragma unroll
            for (int i = 0; i < 4; i++) c[mt][nt][i] = 0.f;

    pipe_loop(shb, A + (size_t)m0 * K, W + (size_t)n0 * K, K, sh, c, wm, wn, g, t, tid);

#pragma unroll
    for (int mt = 0; mt < 4; mt++) {
        int r0 = m0 + wm * 64 + mt * 16 + g;
        int r1 = r0 + 8;
#pragma unroll
        for (int nt = 0; nt < 8; nt++) {
            int col = n0 + wn * 64 + nt * 8 + 2 * t;
            *(float2*)&C[(size_t)r0 * N + col] = make_float2(c[mt][nt][0], c[mt][nt][1]);
            *(float2*)&C[(size_t)r1 * N + col] = make_float2(c[mt][nt][2], c[mt][nt][3]);
        }
    }
}

// ---------------------------------------------------------------------------
// W2 = Wout @ Wout (small; RF-staged sync loop). Epilogue pre-rounds to tf32.
// ---------------------------------------------------------------------------
__global__ __launch_bounds__(128, 2)
void w2_gemm(const float* __restrict__ Wout, float* __restrict__ C)
{
    extern __shared__ unsigned sh[];
    unsigned* As = sh;
    unsigned* Bs = sh + BUFW;
    const int tid = threadIdx.x;
    const int m0 = blockIdx.y * 128, n0 = blockIdx.x * 128;
    const int warp = tid >> 5, lane = tid & 31;
    const int wm = warp & 1, wn = warp >> 1;
    const int g = lane >> 2, t = lane & 3;
    const int K = DIMN, N = DIMN;

    float c[4][8][4];
#pragma unroll
    for (int mt = 0; mt < 4; mt++)
#pragma unroll
        for (int nt = 0; nt < 8; nt++)
#pragma unroll
            for (int i = 0; i < 4; i++) c[mt][nt][i] = 0.f;

    for (int kk = 0; kk < K; kk += 32) {
        stageRF(As, Wout + (size_t)m0 * K, K, kk, tid);
        stageBT(Bs, Wout, n0, kk, N, tid);
        __syncthreads();
        compute_tile(As, Bs, c, wm, wn, g, t);
        __syncthreads();
    }

#pragma unroll
    for (int mt = 0; mt < 4; mt++) {
        int r0 = m0 + wm * 64 + mt * 16 + g;
        int r1 = r0 + 8;
#pragma unroll
        for (int nt = 0; nt < 8; nt++) {
            int col = n0 + wn * 64 + nt * 8 + 2 * t;
            uint2 v0 = make_uint2(f2tf(c[mt][nt][0]), f2tf(c[mt][nt][1]));
            uint2 v1 = make_uint2(f2tf(c[mt][nt][2]), f2tf(c[mt][nt][3]));
            *(uint2*)&C[(size_t)r0 * N + col] = v0;
            *(uint2*)&C[(size_t)r1 * N + col] = v1;
        }
    }
}

// ---------------------------------------------------------------------------
// Merged projections (cp.async pipeline; sources pre-rounded):
//  grid.x 0..7  -> Q proj, grid.x 8..23 -> KV proj. Epilogue stores tf32.
// ---------------------------------------------------------------------------
__global__ __launch_bounds__(128, 2)
void proj_gemm()
{
    extern __shared__ unsigned sh[];
    uint32_t shb = (uint32_t)__cvta_generic_to_shared(sh);
    const int tid = threadIdx.x;
    const bool isQ = blockIdx.x < 8;
    const float* A = isQ ? g_decT : g_encT;
    const float* W = isQ ? g_WqT : g_WkvT;
    const int n0 = (isQ ? blockIdx.x : (blockIdx.x - 8)) * 128;
    const int m0 = blockIdx.y * 128;
    const int K = DIMN;
    const int warp = tid >> 5, lane = tid & 31;
    const int wm = warp & 1, wn = warp >> 1;
    const int g = lane >> 2, t = lane & 3;

    float c[4][8][4];
#pragma unroll
    for (int mt = 0; mt < 4; mt++)
#pragma unroll
        for (int nt = 0; nt < 8; nt++)
#pragma unroll
            for (int i = 0; i < 4; i++) c[mt][nt][i] = 0.f;

    pipe_loop(shb, A + (size_t)m0 * K, W + (size_t)n0 * K, K, sh, c, wm, wn, g, t, tid);

    // scatter epilogue (validated); store tf32-rounded for downstream cp.async
#pragma unroll
    for (int mt = 0; mt < 4; mt++) {
        int r0 = wm * 64 + mt * 16 + g;
        int r1 = r0 + 8;
#pragma unroll
        for (int nt = 0; nt < 8; nt++) {
            int col = n0 + wn * 64 + nt * 8 + 2 * t;
#pragma unroll
            for (int e = 0; e < 4; e++) {
                int m = m0 + ((e < 2) ? r0 : r1);
                int n = col + (e & 1);
                float v = c[mt][nt][e];
                int b = m >> 10, q = m & 1023;
                if (isQ) {
                    int h = n & 15, d = n >> 4;
                    g_Qh[(((size_t)(b * NH + h) * QL + q) * DK) + d] =
                        __uint_as_float(f2tf(v * 0.125f));
                } else if (n < DIMN) {
                    int h = n & 15, d = n >> 4;
                    g_Kh[(((size_t)(b * NH + h) * KL + q) * DK) + d] =
                        __uint_as_float(f2tf(v));
                } else {
                    int nn = n - DIMN;
                    int h = nn & 15, d = nn >> 4;
                    g_Vh[(((size_t)(b * NH + h) * KL + q) * DK) + d] =
                        __uint_as_float(f2tf(v));
                }
            }
        }
    }
}

// ---------------------------------------------------------------------------
// Fused attention. Inputs pre-rounded tf32 (f2tf at stage = identity, kept
// for safety — numerics identical to R3/R5/R6). Output stored tf32-rounded.
// ---------------------------------------------------------------------------
#define ATT_LD 68
#define SMEM_ATTN (4 * 64 * ATT_LD * 4 + 64 * 64)

__global__ __launch_bounds__(128)
void attn_kernel()
{
    extern __shared__ unsigned smU[];
    unsigned* Qs = smU;
    unsigned* Ks = Qs + 64 * ATT_LD;
    unsigned* Vt = Ks + 64 * ATT_LD;
    unsigned* Ps = Vt + 64 * ATT_LD;
    unsigned char* Ms = (unsigned char*)(Ps + 64 * ATT_LD);

    const int head = blockIdx.y;
    const int b = head >> 4, h = head & 15;
    const int q0 = blockIdx.x * 64;
    const int tid = threadIdx.x;
    const int w = tid >> 5, lane = tid & 31;
    const int g = lane >> 2, t = lane & 3;
    const int wq0 = w * 16;
    const int allTrue = g_allTrue;

    const float* Qp = g_Qh + (size_t)head * QL * DK;
    const float* Kp = g_Kh + (size_t)head * KL * DK;
    const float* Vp = g_Vh + (size_t)head * KL * DK;

#pragma unroll
    for (int i = 0; i < 8; i++) {
        int f = tid + i * 128;
        int row = f >> 4, dq = (f & 15) * 4;
        float4 qv = *(const float4*)&Qp[(size_t)(q0 + row) * DK + dq];
        unsigned* d = &Qs[row * ATT_LD + dq];
        d[0] = f2tf(qv.x); d[1] = f2tf(qv.y); d[2] = f2tf(qv.z); d[3] = f2tf(qv.w);
    }

    float o[8][4];
#pragma unroll
    for (int nt = 0; nt < 8; nt++)
#pragma unroll
        for (int i = 0; i < 4; i++) o[nt][i] = 0.f;
    float l0 = 0.f, l1 = 0.f;

    for (int k0 = 0; k0 < KL; k0 += 64) {
#pragma unroll
        for (int i = 0; i < 8; i++) {
            int f = tid + i * 128;
            int row = f >> 4, dq = (f & 15) * 4;
            float4 kv = *(const float4*)&Kp[(size_t)(k0 + row) * DK + dq];
            unsigned* d = &Ks[row * ATT_LD + dq];
            d[0] = f2tf(kv.x); d[1] = f2tf(kv.y); d[2] = f2tf(kv.z); d[3] = f2tf(kv.w);
            float4 vv = *(const float4*)&Vp[(size_t)(k0 + row) * DK + dq];
            Vt[(dq + 0) * ATT_LD + row] = f2tf(vv.x);
            Vt[(dq + 1) * ATT_LD + row] = f2tf(vv.y);
            Vt[(dq + 2) * ATT_LD + row] = f2tf(vv.z);
            Vt[(dq + 3) * ATT_LD + row] = f2tf(vv.w);
        }
        if (!allTrue) {
            const unsigned* mrow = (const unsigned*)(g_mask8 + ((size_t)(b * QL + q0)) * KL + k0);
#pragma unroll
            for (int i = 0; i < 8; i++) {
                int f = tid + i * 128;
                int qr = f >> 4, kq = f & 15;
                ((unsigned*)Ms)[qr * 16 + kq] =
                    *(const unsigned*)((const unsigned char*)mrow + (size_t)qr * KL + kq * 4);
            }
        }
        __syncthreads();

        float s[8][4];
#pragma unroll
        for (int nt = 0; nt < 8; nt++)
#pragma unroll
            for (int i = 0; i < 4; i++) s[nt][i] = 0.f;

#pragma unroll
        for (int ks = 0; ks < 8; ks++) {
            const int k8 = ks * 8;
            unsigned a[4];
            a[0] = Qs[(wq0 + g) * ATT_LD + k8 + t];
            a[1] = Qs[(wq0 + 8 + g) * ATT_LD + k8 + t];
            a[2] = Qs[(wq0 + g) * ATT_LD + k8 + 4 + t];
            a[3] = Qs[(wq0 + 8 + g) * ATT_LD + k8 + 4 + t];
#pragma unroll
            for (int nt = 0; nt < 8; nt++) {
                unsigned bf[2];
                bf[0] = Ks[(nt * 8 + g) * ATT_LD + k8 + t];
                bf[1] = Ks[(nt * 8 + g) * ATT_LD + k8 + 4 + t];
                mma_tf32(s[nt], a, bf);
            }
        }

        int qr0 = wq0 + g, qr1 = wq0 + 8 + g;
        float rs0 = 0.f, rs1 = 0.f;
#pragma unroll
        for (int nt = 0; nt < 8; nt++) {
            int kc = nt * 8 + 2 * t;
            float p00, p01, p10, p11;
            if (allTrue) {
                p00 = __expf(s[nt][0]); p01 = __expf(s[nt][1]);
                p10 = __expf(s[nt][2]); p11 = __expf(s[nt][3]);
            } else {
                p00 = Ms[qr0 * 64 + kc]     ? __expf(s[nt][0]) : 0.f;
                p01 = Ms[qr0 * 64 + kc + 1] ? __expf(s[nt][1]) : 0.f;
                p10 = Ms[qr1 * 64 + kc]     ? __expf(s[nt][2]) : 0.f;
                p11 = Ms[qr1 * 64 + kc + 1] ? __expf(s[nt][3]) : 0.f;
            }
            rs0 += p00 + p01;
            rs1 += p10 + p11;
            *(uint2*)&Ps[qr0 * ATT_LD + kc] = make_uint2(f2tf(p00), f2tf(p01));
            *(uint2*)&Ps[qr1 * ATT_LD + kc] = make_uint2(f2tf(p10), f2tf(p11));
        }
        rs0 += __shfl_xor_sync(0xffffffffu, rs0, 1);
        rs0 += __shfl_xor_sync(0xffffffffu, rs0, 2);
        rs1 += __shfl_xor_sync(0xffffffffu, rs1, 1);
        rs1 += __shfl_xor_sync(0xffffffffu, rs1, 2);
        l0 += rs0;
        l1 += rs1;
        __syncwarp();

#pragma unroll
        for (int ks = 0; ks < 8; ks++) {
            const int k8 = ks * 8;
            unsigned a[4];
            a[0] = Ps[(wq0 + g) * ATT_LD + k8 + t];
            a[1] = Ps[(wq0 + 8 + g) * ATT_LD + k8 + t];
            a[2] = Ps[(wq0 + g) * ATT_LD + k8 + 4 + t];
            a[3] = Ps[(wq0 + 8 + g) * ATT_LD + k8 + 4 + t];
#pragma unroll
            for (int nt = 0; nt < 8; nt++) {
                unsigned bf[2];
                bf[0] = Vt[(nt * 8 + g) * ATT_LD + k8 + t];
                bf[1] = Vt[(nt * 8 + g) * ATT_LD + k8 + 4 + t];
                mma_tf32(o[nt], a, bf);
            }
        }
        __syncthreads();
    }

    float inv0 = 1.f / l0, inv1 = 1.f / l1;
    int qa = q0 + wq0 + g, qb = qa + 8;
#pragma unroll
    for (int nt = 0; nt < 8; nt++) {
        int d = nt * 8 + 2 * t;
        float* base0 = &g_vals[((size_t)(b * QL + qa)) * DIMN + d * NH + h];
        float* base1 = &g_vals[((size_t)(b * QL + qb)) * DIMN + d * NH + h];
        base0[0]  = __uint_as_float(f2tf(o[nt][0] * inv0));
        base0[NH] = __uint_as_float(f2tf(o[nt][1] * inv0));
        base1[0]  = __uint_as_float(f2tf(o[nt][2] * inv1));
        base1[NH] = __uint_as_float(f2tf(o[nt][3] * inv1));
    }
}

// ---------------------------------------------------------------------------
extern "C" void kernel_launch(void* const* d_in, const int* in_sizes, int n_in,
                              void* d_out, int out_size)
{
    const float* dec  = (const float*)d_in[0];
    const float* enc  = (const float*)d_in[1];
    const unsigned char* mask = (const unsigned char*)d_in[2];
    const float* Wq   = (const float*)d_in[3];
    const float* Wkv  = (const float*)d_in[4];
    const float* Wout = (const float*)d_in[5];
    float* out = (float*)d_out;

    float *vals_p, *w2_p, *decT_p, *encT_p, *wqT_p, *wkvT_p;
    cudaGetSymbolAddress((void**)&vals_p, g_vals);
    cudaGetSymbolAddress((void**)&w2_p, g_W2);
    cudaGetSymbolAddress((void**)&decT_p, g_decT);
    cudaGetSymbolAddress((void**)&encT_p, g_encT);
    cudaGetSymbolAddress((void**)&wqT_p, g_WqT);
    cudaGetSymbolAddress((void**)&wkvT_p, g_WkvT);

    cudaFuncSetAttribute(final_gemm, cudaFuncAttributeMaxDynamicSharedMemorySize, GEMM_SMEM);
    cudaFuncSetAttribute(proj_gemm,  cudaFuncAttributeMaxDynamicSharedMemorySize, GEMM_SMEM);
    cudaFuncSetAttribute(w2_gemm,    cudaFuncAttributeMaxDynamicSharedMemorySize, GEMM_SMEM);
    cudaFuncSetAttribute(attn_kernel, cudaFuncAttributeMaxDynamicSharedMemorySize, SMEM_ATTN);

    const int M = BATCH * QL; // 4096
    const int NMASK = BATCH * QL * KL;
    dim3 blk(128);

    mask_detect_kernel<<<1, 256>>>(mask);
    mask_convert_kernel<<<(NMASK + 255) / 256, 256>>>(mask, NMASK);

    // pre-round activations + weights to tf32 (streaming)
    cvt_tf32_kernel<<<(M * DIMN / 4 + 255) / 256, 256>>>(dec, decT_p, M * DIMN);
    cvt_tf32_kernel<<<(M * DIMN / 4 + 255) / 256, 256>>>(enc, encT_p, M * DIMN);
    cvt_tf32_kernel<<<(DIMN * DIMN / 4 + 255) / 256, 256>>>(Wq, wqT_p, DIMN * DIMN);
    cvt_tf32_kernel<<<(2 * DIMN * DIMN / 4 + 255) / 256, 256>>>(Wkv, wkvT_p, 2 * DIMN * DIMN);

    // W2 = Wout @ Wout (epilogue pre-rounds)
    w2_gemm<<<dim3(8, 8), blk, GEMM_SMEM>>>(Wout, w2_p);
    // merged Q + KV projections (cp.async pipeline)
    proj_gemm<<<dim3(24, M / 128), blk, GEMM_SMEM>>>();
    // fused attention -> g_vals (pre-rounded)
    attn_kernel<<<dim3(QL / 64, BATCH * NH), dim3(128), SMEM_ATTN>>>();
    // out = vals @ W2^T (cp.async pipeline)
    final_gemm<<<dim3(8, M / 128), blk, GEMM_SMEM>>>(vals_p, w2_p, out, M, DIMN, DIMN);
}

// round 10
// speedup vs baseline: 1.2621x; 1.0941x over previous
#include <cuda_runtime.h>
#include <cstddef>
#include <cstdint>

#define DIMN 1024
#define NH   16
#define DK   64
#define BATCH 4
#define QL   1024
#define KL   1024

// Scratch (device globals: allocation-free rule)
__device__ float g_Qh[BATCH*NH*QL*DK];   // tf32-rounded, pre-scaled by 1/8
__device__ float g_Kh[BATCH*NH*KL*DK];   // tf32-rounded
__device__ float g_Vh[BATCH*NH*KL*DK];   // tf32-rounded
__device__ float g_vals[BATCH*QL*DIMN];  // attention out, tf32-rounded
__device__ float g_W2[DIMN*DIMN];        // Wout @ Wout, tf32-rounded
__device__ float g_decT[BATCH*QL*DIMN];
__device__ float g_encT[BATCH*KL*DIMN];
__device__ float g_WqT[DIMN*DIMN];
__device__ float g_WkvT[2*DIMN*DIMN];
__device__ unsigned char g_mask8[BATCH*QL*KL];
__device__ int g_isByte;
__device__ int g_allTrue;

// ---------------------------------------------------------------------------
__device__ __forceinline__ unsigned f2tf(float x) {
    unsigned r;
    asm("cvt.rna.tf32.f32 %0, %1;" : "=r"(r) : "f"(x));
    return r;
}

__device__ __forceinline__ void mma_tf32(float c[4], const unsigned a[4], const unsigned b[2]) {
    asm("mma.sync.aligned.m16n8k8.row.col.f32.tf32.tf32.f32 "
        "{%0,%1,%2,%3}, {%4,%5,%6,%7}, {%8,%9}, {%0,%1,%2,%3};"
        : "+f"(c[0]), "+f"(c[1]), "+f"(c[2]), "+f"(c[3])
        : "r"(a[0]), "r"(a[1]), "r"(a[2]), "r"(a[3]), "r"(b[0]), "r"(b[1]));
}

__device__ __forceinline__ void cpasync16(uint32_t dst, const void* src) {
    asm volatile("cp.async.cg.shared.global [%0], [%1], 16;" :: "r"(dst), "l"(src));
}
#define CP_COMMIT()  asm volatile("cp.async.commit_group;" ::: "memory")
#define CP_WAIT0()   asm volatile("cp.async.wait_all;" ::: "memory")

// ---------------------------------------------------------------------------
// Fused tf32 pre-round prep: dec | enc | Wq | Wkv in one launch
// ---------------------------------------------------------------------------
#define SEG1 4194304L   // dec floats
#define SEG2 8388608L   // + enc
#define SEG3 9437184L   // + Wq
#define SEG4 11534336L  // + Wkv

__global__ void cvt_all_kernel(const float* __restrict__ dec, const float* __restrict__ enc,
                               const float* __restrict__ wq, const float* __restrict__ wkv)
{
    long i = ((long)blockIdx.x * blockDim.x + threadIdx.x) * 4;
    if (i >= SEG4) return;
    const float* src; float* dst; long off;
    if (i < SEG1)      { src = dec; dst = g_decT; off = i; }
    else if (i < SEG2) { src = enc; dst = g_encT; off = i - SEG1; }
    else if (i < SEG3) { src = wq;  dst = g_WqT;  off = i - SEG2; }
    else               { src = wkv; dst = g_WkvT; off = i - SEG3; }
    float4 v = *(const float4*)&src[off];
    uint4 u = make_uint4(f2tf(v.x), f2tf(v.y), f2tf(v.z), f2tf(v.w));
    *(uint4*)&dst[off] = u;
}

// ---------------------------------------------------------------------------
// Mask dtype detect (int32 vs byte)
// ---------------------------------------------------------------------------
__global__ void mask_detect_kernel(const unsigned char* __restrict__ m)
{
    __shared__ int found;
    if (threadIdx.x == 0) { found = 0; g_allTrue = 1; }
    __syncthreads();
    for (int i = threadIdx.x; i < 16384; i += blockDim.x)
        if ((i & 3) && m[i]) found = 1;
    __syncthreads();
    if (threadIdx.x == 0) g_isByte = found;
}

__global__ void mask_convert_kernel(const unsigned char* __restrict__ m, int n)
{
    int i = blockIdx.x * blockDim.x + threadIdx.x;
    int v = 1;
    if (i < n) {
        v = g_isByte ? (m[i] ? 1 : 0) : (((const unsigned*)m)[i] ? 1 : 0);
        g_mask8[i] = (unsigned char)v;
    }
    int all = __syncthreads_and(v);
    if (!all && threadIdx.x == 0) g_allTrue = 0;
}

// ---------------------------------------------------------------------------
// GEMM core: BM=BN=128, BK=32, 128 threads = 4 warps (2M x 2N), warp 64x64.
// SMEM stride 36 words (conflict-free frags: bank = 4*g + t).
// 2-buffer cp.async pipeline, ONE __syncthreads per iteration:
//   wait -> sync -> issue(kt+1 into other buf) -> compute(kt)
// (top sync proves all threads finished reading the other buffer at kt-1)
// ---------------------------------------------------------------------------
#define LDS_T 36
#define BUFW (128 * LDS_T)
#define GEMM_SMEM (4 * BUFW * 4)    // A0,B0,A1,B1 = 73728 B

__device__ __forceinline__ void issueTile(uint32_t Sb, const float* __restrict__ P,
                                          int ld, int kk, int tid) {
#pragma unroll
    for (int i = 0; i < 8; i++) {
        int f = tid + i * 128;
        int row = f >> 3, kq = (f & 7) * 4;
        cpasync16(Sb + (uint32_t)(row * LDS_T + kq) * 4, P + (size_t)row * ld + kk + kq);
    }
}

// RF staging (cvt path) — W2 kernel only
__device__ __forceinline__ void stageRF(unsigned* S, const float* __restrict__ P,
                                        int ld, int kk, int tid) {
#pragma unroll
    for (int i = 0; i < 8; i++) {
        int f = tid + i * 128;
        int row = f >> 3, kq = (f & 7) * 4;
        float4 v = *(const float4*)&P[(size_t)row * ld + kk + kq];
        unsigned* d = &S[row * LDS_T + kq];
        d[0] = f2tf(v.x); d[1] = f2tf(v.y); d[2] = f2tf(v.z); d[3] = f2tf(v.w);
    }
}
__device__ __forceinline__ void stageBT(unsigned* Bs, const float* __restrict__ W,
                                        int n0, int kk, int ldn, int tid) {
#pragma unroll
    for (int i = 0; i < 8; i++) {
        int f = tid + i * 128;
        int kr = f >> 5, nq = (f & 31) * 4;
        float4 v = *(const float4*)&W[(size_t)(kk + kr) * ldn + n0 + nq];
        Bs[(nq + 0) * LDS_T + kr] = f2tf(v.x);
        Bs[(nq + 1) * LDS_T + kr] = f2tf(v.y);
        Bs[(nq + 2) * LDS_T + kr] = f2tf(v.z);
        Bs[(nq + 3) * LDS_T + kr] = f2tf(v.w);
    }
}

__device__ __forceinline__ void compute_tile(const unsigned* __restrict__ As,
                                             const unsigned* __restrict__ Bs,
                                             float c[4][8][4], int wm, int wn, int g, int t) {
#pragma unroll
    for (int ks = 0; ks < 4; ks++) {
        const int k8 = ks * 8;
        unsigned a[4][4];
#pragma unroll
        for (int mt = 0; mt < 4; mt++) {
            int r = wm * 64 + mt * 16;
            a[mt][0] = As[(r + g) * LDS_T + k8 + t];
            a[mt][1] = As[(r + 8 + g) * LDS_T + k8 + t];
            a[mt][2] = As[(r + g) * LDS_T + k8 + 4 + t];
            a[mt][3] = As[(r + 8 + g) * LDS_T + k8 + 4 + t];
        }
#pragma unroll
        for (int nt = 0; nt < 8; nt++) {
            int cx = wn * 64 + nt * 8;
            unsigned bf[2];
            bf[0] = Bs[(cx + g) * LDS_T + k8 + t];
            bf[1] = Bs[(cx + g) * LDS_T + k8 + 4 + t];
#pragma unroll
            for (int mt = 0; mt < 4; mt++)
                mma_tf32(c[mt][nt], a[mt], bf);
        }
    }
}

__device__ __forceinline__ void pipe_loop(uint32_t shb, const float* __restrict__ Ap,
                                          const float* __restrict__ Wp, int K,
                                          unsigned* sh, float c[4][8][4],
                                          int wm, int wn, int g, int t, int tid)
{
    const uint32_t Ab[2] = { shb, shb + 2 * BUFW * 4 };
    const uint32_t Bb[2] = { shb + BUFW * 4, shb + 3 * BUFW * 4 };
    unsigned* Abp[2] = { sh, sh + 2 * BUFW };
    unsigned* Bbp[2] = { sh + BUFW, sh + 3 * BUFW };
    const int NIT = K / 32;

    issueTile(Ab[0], Ap, K, 0, tid);
    issueTile(Bb[0], Wp, K, 0, tid);
    CP_COMMIT();
    for (int kt = 0; kt < NIT; kt++) {
        CP_WAIT0();
        __syncthreads();
        int cur = kt & 1;
        if (kt + 1 < NIT) {
            int nb = cur ^ 1;
            issueTile(Ab[nb], Ap, K, (kt + 1) * 32, tid);
            issueTile(Bb[nb], Wp, K, (kt + 1) * 32, tid);
            CP_COMMIT();
        }
        compute_tile(Abp[cur], Bbp[cur], c, wm, wn, g, t);
    }
}

// ---------------------------------------------------------------------------
// Final GEMM: C = A @ W^T (A=g_vals, W=g_W2, both pre-rounded)
// ---------------------------------------------------------------------------
__global__ __launch_bounds__(128, 2)
void final_gemm(const float* __restrict__ A, const float* __restrict__ W,
                float* __restrict__ C, int M, int N, int K)
{
    extern __shared__ unsigned sh[];
    uint32_t shb = (uint32_t)__cvta_generic_to_shared(sh);
    const int tid = threadIdx.x;
    const int m0 = blockIdx.y * 128, n0 = blockIdx.x * 128;
    const int warp = tid >> 5, lane = tid & 31;
    const int wm = warp & 1, wn = warp >> 1;
    const int g = lane >> 2, t = lane & 3;

    float c[4][8][4];
#pragma unroll
    for (int mt = 0; mt < 4; mt++)
#pragma unroll
        for (int nt = 0; nt < 8; nt++)
#pragma unroll
            for (int i = 0; i < 4; i++) c[mt][nt][i] = 0.f;

    pipe_loop(shb, A + (size_t)m0 * K, W + (size_t)n0 * K, K, sh, c, wm, wn, g, t, tid);

#pragma unroll
    for (int mt = 0; mt < 4; mt++) {
        int r0 = m0 + wm * 64 + mt * 16 + g;
        int r1 = r0 + 8;
#pragma unroll
        for (int nt = 0; nt < 8; nt++) {
            int col = n0 + wn * 64 + nt * 8 + 2 * t;
            *(float2*)&C[(size_t)r0 * N + col] = make_float2(c[mt][nt][0], c[mt][nt][1]);
            *(float2*)&C[(size_t)r1 * N + col] = make_float2(c[mt][nt][2], c[mt][nt][3]);
        }
    }
}

// ---------------------------------------------------------------------------
// W2 = Wout @ Wout (small; RF-staged sync loop). Epilogue pre-rounds to tf32.
// ---------------------------------------------------------------------------
__global__ __launch_bounds__(128, 2)
void w2_gemm(const float* __restrict__ Wout, float* __restrict__ C)
{
    extern __shared__ unsigned sh[];
    unsigned* As = sh;
    unsigned* Bs = sh + BUFW;
    const int tid = threadIdx.x;
    const int m0 = blockIdx.y * 128, n0 = blockIdx.x * 128;
    const int warp = tid >> 5, lane = tid & 31;
    const int wm = warp & 1, wn = warp >> 1;
    const int g = lane >> 2, t = lane & 3;
    const int K = DIMN, N = DIMN;

    float c[4][8][4];
#pragma unroll
    for (int mt = 0; mt < 4; mt++)
#pragma unroll
        for (int nt = 0; nt < 8; nt++)
#pragma unroll
            for (int i = 0; i < 4; i++) c[mt][nt][i] = 0.f;

    for (int kk = 0; kk < K; kk += 32) {
        stageRF(As, Wout + (size_t)m0 * K, K, kk, tid);
        stageBT(Bs, Wout, n0, kk, N, tid);
        __syncthreads();
        compute_tile(As, Bs, c, wm, wn, g, t);
        __syncthreads();
    }

#pragma unroll
    for (int mt = 0; mt < 4; mt++) {
        int r0 = m0 + wm * 64 + mt * 16 + g;
        int r1 = r0 + 8;
#pragma unroll
        for (int nt = 0; nt < 8; nt++) {
            int col = n0 + wn * 64 + nt * 8 + 2 * t;
            uint2 v0 = make_uint2(f2tf(c[mt][nt][0]), f2tf(c[mt][nt][1]));
            uint2 v1 = make_uint2(f2tf(c[mt][nt][2]), f2tf(c[mt][nt][3]));
            *(uint2*)&C[(size_t)r0 * N + col] = v0;
            *(uint2*)&C[(size_t)r1 * N + col] = v1;
        }
    }
}

// ---------------------------------------------------------------------------
// Merged projections (cp.async pipeline; sources pre-rounded):
//  grid.x 0..7 -> Q proj, grid.x 8..23 -> KV proj. Epilogue stores tf32.
// ---------------------------------------------------------------------------
__global__ __launch_bounds__(128, 2)
void proj_gemm()
{
    extern __shared__ unsigned sh[];
    uint32_t shb = (uint32_t)__cvta_generic_to_shared(sh);
    const int tid = threadIdx.x;
    const bool isQ = blockIdx.x < 8;
    const float* A = isQ ? g_decT : g_encT;
    const float* W = isQ ? g_WqT : g_WkvT;
    const int n0 = (isQ ? blockIdx.x : (blockIdx.x - 8)) * 128;
    const int m0 = blockIdx.y * 128;
    const int K = DIMN;
    const int warp = tid >> 5, lane = tid & 31;
    const int wm = warp & 1, wn = warp >> 1;
    const int g = lane >> 2, t = lane & 3;

    float c[4][8][4];
#pragma unroll
    for (int mt = 0; mt < 4; mt++)
#pragma unroll
        for (int nt = 0; nt < 8; nt++)
#pragma unroll
            for (int i = 0; i < 4; i++) c[mt][nt][i] = 0.f;

    pipe_loop(shb, A + (size_t)m0 * K, W + (size_t)n0 * K, K, sh, c, wm, wn, g, t, tid);

#pragma unroll
    for (int mt = 0; mt < 4; mt++) {
        int r0 = wm * 64 + mt * 16 + g;
        int r1 = r0 + 8;
#pragma unroll
        for (int nt = 0; nt < 8; nt++) {
            int col = n0 + wn * 64 + nt * 8 + 2 * t;
#pragma unroll
            for (int e = 0; e < 4; e++) {
                int m = m0 + ((e < 2) ? r0 : r1);
                int n = col + (e & 1);
                float v = c[mt][nt][e];
                int b = m >> 10, q = m & 1023;
                if (isQ) {
                    int h = n & 15, d = n >> 4;
                    g_Qh[(((size_t)(b * NH + h) * QL + q) * DK) + d] =
                        __uint_as_float(f2tf(v * 0.125f));
                } else if (n < DIMN) {
                    int h = n & 15, d = n >> 4;
                    g_Kh[(((size_t)(b * NH + h) * KL + q) * DK) + d] =
                        __uint_as_float(f2tf(v));
                } else {
                    int nn = n - DIMN;
                    int h = nn & 15, d = nn >> 4;
                    g_Vh[(((size_t)(b * NH + h) * KL + q) * DK) + d] =
                        __uint_as_float(f2tf(v));
                }
            }
        }
    }
}

// ---------------------------------------------------------------------------
// Fused attention, cp.async edition. All inputs pre-rounded tf32 (raw-copy =
// identical operand bits to previous passing rounds).
// Smem words: Qs[64x68] @0, K0/K1[64x68] @4352/@8704,
//             V0/V1 row-major [64x72] @13056/@17664, Ps[64x68] @22272.
// V stays row-major: PV B-frag addr (k8+t)*72 + n -> banks 8t+g, conflict-free.
// 2-buffer KV pipeline, one __syncthreads per tile.
// ---------------------------------------------------------------------------
#define ATT_LD 68
#define VLD 72
#define AQOFF 0
#define AKOFF(buf) (4352 + (buf) * 4352)
#define AVOFF(buf) (13056 + (buf) * 4608)
#define APSOFF 22272
#define ATT_SMEM (26624 * 4)

__device__ __forceinline__ void att_issue68(uint32_t shb, int woff,
                                            const float* __restrict__ src, int tid) {
#pragma unroll
    for (int i = 0; i < 8; i++) {
        int cch = tid + i * 128;
        int row = cch >> 4, c16 = cch & 15;
        cpasync16(shb + (uint32_t)(woff + row * ATT_LD + c16 * 4) * 4,
                  src + (size_t)row * DK + c16 * 4);
    }
}
__device__ __forceinline__ void att_issue72(uint32_t shb, int woff,
                                            const float* __restrict__ src, int tid) {
#pragma unroll
    for (int i = 0; i < 8; i++) {
        int cch = tid + i * 128;
        int row = cch >> 4, c16 = cch & 15;
        cpasync16(shb + (uint32_t)(woff + row * VLD + c16 * 4) * 4,
                  src + (size_t)row * DK + c16 * 4);
    }
}

__global__ __launch_bounds__(128, 2)
void attn_kernel()
{
    extern __shared__ unsigned smU[];
    uint32_t shb = (uint32_t)__cvta_generic_to_shared(smU);
    unsigned* Qs = smU + AQOFF;
    unsigned* Ps = smU + APSOFF;

    const int head = blockIdx.y;
    const int b = head >> 4, h = head & 15;
    const int q0 = blockIdx.x * 64;
    const int tid = threadIdx.x;
    const int w = tid >> 5, lane = tid & 31;
    const int g = lane >> 2, t = lane & 3;
    const int wq0 = w * 16;
    const int allTrue = g_allTrue;

    const float* Qp = g_Qh + (size_t)head * QL * DK;
    const float* Kp = g_Kh + (size_t)head * KL * DK;
    const float* Vp = g_Vh + (size_t)head * KL * DK;

    // prologue: Q tile + KV tile 0, one group
    att_issue68(shb, AQOFF, Qp + (size_t)q0 * DK, tid);
    att_issue68(shb, AKOFF(0), Kp, tid);
    att_issue72(shb, AVOFF(0), Vp, tid);
    CP_COMMIT();

    float o[8][4];
#pragma unroll
    for (int nt = 0; nt < 8; nt++)
#pragma unroll
        for (int i = 0; i < 4; i++) o[nt][i] = 0.f;
    float l0 = 0.f, l1 = 0.f;

    const int NKT = KL / 64;  // 16
    for (int kt = 0; kt < NKT; kt++) {
        CP_WAIT0();
        __syncthreads();
        const int cur = kt & 1;
        if (kt + 1 < NKT) {
            att_issue68(shb, AKOFF(cur ^ 1), Kp + (size_t)(kt + 1) * 64 * DK, tid);
            att_issue72(shb, AVOFF(cur ^ 1), Vp + (size_t)(kt + 1) * 64 * DK, tid);
            CP_COMMIT();
        }
        const unsigned* Kc = smU + AKOFF(cur);
        const unsigned* Vc = smU + AVOFF(cur);

        // S = Q @ K^T
        float s[8][4];
#pragma unroll
        for (int nt = 0; nt < 8; nt++)
#pragma unroll
            for (int i = 0; i < 4; i++) s[nt][i] = 0.f;

#pragma unroll
        for (int ks = 0; ks < 8; ks++) {
            const int k8 = ks * 8;
            unsigned a[4];
            a[0] = Qs[(wq0 + g) * ATT_LD + k8 + t];
            a[1] = Qs[(wq0 + 8 + g) * ATT_LD + k8 + t];
            a[2] = Qs[(wq0 + g) * ATT_LD + k8 + 4 + t];
            a[3] = Qs[(wq0 + 8 + g) * ATT_LD + k8 + 4 + t];
#pragma unroll
            for (int nt = 0; nt < 8; nt++) {
                unsigned bf[2];
                bf[0] = Kc[(nt * 8 + g) * ATT_LD + k8 + t];
                bf[1] = Kc[(nt * 8 + g) * ATT_LD + k8 + 4 + t];
                mma_tf32(s[nt], a, bf);
            }
        }

        // mask + exp + rowsum; P -> smem (tf32-rounded, per-warp region)
        int qr0 = wq0 + g, qr1 = wq0 + 8 + g;
        const unsigned char* m0p = g_mask8 + ((size_t)(b * QL + q0 + qr0)) * KL + kt * 64;
        const unsigned char* m1p = g_mask8 + ((size_t)(b * QL + q0 + qr1)) * KL + kt * 64;
        float rs0 = 0.f, rs1 = 0.f;
#pragma unroll
        for (int nt = 0; nt < 8; nt++) {
            int kc = nt * 8 + 2 * t;
            float p00, p01, p10, p11;
            if (allTrue) {
                p00 = __expf(s[nt][0]); p01 = __expf(s[nt][1]);
                p10 = __expf(s[nt][2]); p11 = __expf(s[nt][3]);
            } else {
                p00 = m0p[kc]     ? __expf(s[nt][0]) : 0.f;
                p01 = m0p[kc + 1] ? __expf(s[nt][1]) : 0.f;
                p10 = m1p[kc]     ? __expf(s[nt][2]) : 0.f;
                p11 = m1p[kc + 1] ? __expf(s[nt][3]) : 0.f;
            }
            rs0 += p00 + p01;
            rs1 += p10 + p11;
            *(uint2*)&Ps[qr0 * ATT_LD + kc] = make_uint2(f2tf(p00), f2tf(p01));
            *(uint2*)&Ps[qr1 * ATT_LD + kc] = make_uint2(f2tf(p10), f2tf(p11));
        }
        rs0 += __shfl_xor_sync(0xffffffffu, rs0, 1);
        rs0 += __shfl_xor_sync(0xffffffffu, rs0, 2);
        rs1 += __shfl_xor_sync(0xffffffffu, rs1, 1);
        rs1 += __shfl_xor_sync(0xffffffffu, rs1, 2);
        l0 += rs0;
        l1 += rs1;
        __syncwarp();   // Ps produced & consumed within this warp

        // O += P @ V  (B-frags strided from row-major V, stride 72)
#pragma unroll
        for (int ks = 0; ks < 8; ks++) {
            const int k8 = ks * 8;
            unsigned a[4];
            a[0] = Ps[(wq0 + g) * ATT_LD + k8 + t];
            a[1] = Ps[(wq0 + 8 + g) * ATT_LD + k8 + t];
            a[2] = Ps[(wq0 + g) * ATT_LD + k8 + 4 + t];
            a[3] = Ps[(wq0 + 8 + g) * ATT_LD + k8 + 4 + t];
#pragma unroll
            for (int nt = 0; nt < 8; nt++) {
                unsigned bf[2];
                bf[0] = Vc[(k8 + t) * VLD + nt * 8 + g];
                bf[1] = Vc[(k8 + 4 + t) * VLD + nt * 8 + g];
                mma_tf32(o[nt], a, bf);
            }
        }
    }

    float inv0 = 1.f / l0, inv1 = 1.f / l1;
    int qa = q0 + wq0 + g, qb = qa + 8;
#pragma unroll
    for (int nt = 0; nt < 8; nt++) {
        int d = nt * 8 + 2 * t;
        float* base0 = &g_vals[((size_t)(b * QL + qa)) * DIMN + d * NH + h];
        float* base1 = &g_vals[((size_t)(b * QL + qb)) * DIMN + d * NH + h];
        base0[0]  = __uint_as_float(f2tf(o[nt][0] * inv0));
        base0[NH] = __uint_as_float(f2tf(o[nt][1] * inv0));
        base1[0]  = __uint_as_float(f2tf(o[nt][2] * inv1));
        base1[NH] = __uint_as_float(f2tf(o[nt][3] * inv1));
    }
}

// ---------------------------------------------------------------------------
extern "C" void kernel_launch(void* const* d_in, const int* in_sizes, int n_in,
                              void* d_out, int out_size)
{
    const float* dec  = (const float*)d_in[0];
    const float* enc  = (const float*)d_in[1];
    const unsigned char* mask = (const unsigned char*)d_in[2];
    const float* Wq   = (const float*)d_in[3];
    const float* Wkv  = (const float*)d_in[4];
    const float* Wout = (const float*)d_in[5];
    float* out = (float*)d_out;

    float *vals_p, *w2_p;
    cudaGetSymbolAddress((void**)&vals_p, g_vals);
    cudaGetSymbolAddress((void**)&w2_p, g_W2);

    cudaFuncSetAttribute(final_gemm, cudaFuncAttributeMaxDynamicSharedMemorySize, GEMM_SMEM);
    cudaFuncSetAttribute(proj_gemm,  cudaFuncAttributeMaxDynamicSharedMemorySize, GEMM_SMEM);
    cudaFuncSetAttribute(w2_gemm,    cudaFuncAttributeMaxDynamicSharedMemorySize, GEMM_SMEM);
    cudaFuncSetAttribute(attn_kernel, cudaFuncAttributeMaxDynamicSharedMemorySize, ATT_SMEM);

    const int M = BATCH * QL; // 4096
    const int NMASK = BATCH * QL * KL;
    dim3 blk(128);

    mask_detect_kernel<<<1, 256>>>(mask);
    mask_convert_kernel<<<(NMASK + 255) / 256, 256>>>(mask, NMASK);

    // fused tf32 pre-round of all GEMM inputs
    cvt_all_kernel<<<(int)((SEG4 / 4 + 255) / 256), 256>>>(dec, enc, Wq, Wkv);

    // W2 = Wout @ Wout (epilogue pre-rounds)
    w2_gemm<<<dim3(8, 8), blk, GEMM_SMEM>>>(Wout, w2_p);
    // merged Q + KV projections
    proj_gemm<<<dim3(24, M / 128), blk, GEMM_SMEM>>>();
    // fused attention -> g_vals (pre-rounded)
    attn_kernel<<<dim3(QL / 64, BATCH * NH), dim3(128), ATT_SMEM>>>();
    // out = vals @ W2^T
    final_gemm<<<dim3(8, M / 128), blk, GEMM_SMEM>>>(vals_p, w2_p, out, M, DIMN, DIMN);
}

// round 11
// speedup vs baseline: 1.3890x; 1.1006x over previous
#include <cuda_runtime.h>
#include <cstddef>
#include <cstdint>

#define DIMN 1024
#define NH   16
#define DK   64
#define BATCH 4
#define QL   1024
#define KL   1024

// Scratch (device globals: allocation-free rule)
__device__ float g_Qh[BATCH*NH*QL*DK];   // tf32-rounded, pre-scaled by 1/8
__device__ float g_Kh[BATCH*NH*KL*DK];   // tf32-rounded
__device__ float g_Vh[BATCH*NH*KL*DK];   // tf32-rounded
__device__ float g_vals[BATCH*QL*DIMN];  // attention out, tf32-rounded
__device__ float g_W2[DIMN*DIMN];        // Wout @ Wout, tf32-rounded
__device__ float g_decT[BATCH*QL*DIMN];
__device__ float g_encT[BATCH*KL*DIMN];
__device__ float g_WqT[DIMN*DIMN];
__device__ float g_WkvT[2*DIMN*DIMN];
__device__ float g_WoutT[DIMN*DIMN];
__device__ unsigned char g_mask8[BATCH*QL*KL];
__device__ int g_isByte;
__device__ int g_allTrue;

// ---------------------------------------------------------------------------
__device__ __forceinline__ unsigned f2tf(float x) {
    unsigned r;
    asm("cvt.rna.tf32.f32 %0, %1;" : "=r"(r) : "f"(x));
    return r;
}

__device__ __forceinline__ void mma_tf32(float c[4], const unsigned a[4], const unsigned b[2]) {
    asm("mma.sync.aligned.m16n8k8.row.col.f32.tf32.tf32.f32 "
        "{%0,%1,%2,%3}, {%4,%5,%6,%7}, {%8,%9}, {%0,%1,%2,%3};"
        : "+f"(c[0]), "+f"(c[1]), "+f"(c[2]), "+f"(c[3])
        : "r"(a[0]), "r"(a[1]), "r"(a[2]), "r"(a[3]), "r"(b[0]), "r"(b[1]));
}

__device__ __forceinline__ void cpasync16(uint32_t dst, const void* src) {
    asm volatile("cp.async.cg.shared.global [%0], [%1], 16;" :: "r"(dst), "l"(src));
}
#define CP_COMMIT()  asm volatile("cp.async.commit_group;" ::: "memory")
#define CP_WAIT0()   asm volatile("cp.async.wait_all;" ::: "memory")

// ---------------------------------------------------------------------------
// Fused tf32 pre-round prep: dec | enc | Wq | Wkv | Wout in one launch
// ---------------------------------------------------------------------------
#define SEG1 4194304L    // dec floats
#define SEG2 8388608L    // + enc
#define SEG3 9437184L    // + Wq
#define SEG4 11534336L   // + Wkv
#define SEG5 12582912L   // + Wout

__global__ void cvt_all_kernel(const float* __restrict__ dec, const float* __restrict__ enc,
                               const float* __restrict__ wq, const float* __restrict__ wkv,
                               const float* __restrict__ wout)
{
    long i = ((long)blockIdx.x * blockDim.x + threadIdx.x) * 4;
    if (i >= SEG5) return;
    const float* src; float* dst; long off;
    if (i < SEG1)      { src = dec;  dst = g_decT;  off = i; }
    else if (i < SEG2) { src = enc;  dst = g_encT;  off = i - SEG1; }
    else if (i < SEG3) { src = wq;   dst = g_WqT;   off = i - SEG2; }
    else if (i < SEG4) { src = wkv;  dst = g_WkvT;  off = i - SEG3; }
    else               { src = wout; dst = g_WoutT; off = i - SEG4; }
    float4 v = *(const float4*)&src[off];
    uint4 u = make_uint4(f2tf(v.x), f2tf(v.y), f2tf(v.z), f2tf(v.w));
    *(uint4*)&dst[off] = u;
}

// ---------------------------------------------------------------------------
// Mask dtype detect (int32 vs byte)
// ---------------------------------------------------------------------------
__global__ void mask_detect_kernel(const unsigned char* __restrict__ m)
{
    __shared__ int found;
    if (threadIdx.x == 0) { found = 0; g_allTrue = 1; }
    __syncthreads();
    for (int i = threadIdx.x; i < 16384; i += blockDim.x)
        if ((i & 3) && m[i]) found = 1;
    __syncthreads();
    if (threadIdx.x == 0) g_isByte = found;
}

__global__ void mask_convert_kernel(const unsigned char* __restrict__ m, int n)
{
    int i = blockIdx.x * blockDim.x + threadIdx.x;
    int v = 1;
    if (i < n) {
        v = g_isByte ? (m[i] ? 1 : 0) : (((const unsigned*)m)[i] ? 1 : 0);
        g_mask8[i] = (unsigned char)v;
    }
    int all = __syncthreads_and(v);
    if (!all && threadIdx.x == 0) g_allTrue = 0;
}

// ---------------------------------------------------------------------------
// GEMM core: BM=BN=128, BK=32, 128 threads = 4 warps (2M x 2N), warp 64x64.
// SMEM stride 36 words (conflict-free frags: bank = 4*g + t).
// 2-buffer cp.async pipeline, ONE __syncthreads per iteration.
// ---------------------------------------------------------------------------
#define LDS_T 36
#define BUFW (128 * LDS_T)
#define GEMM_SMEM (4 * BUFW * 4)    // A0,B0,A1,B1 = 73728 B

__device__ __forceinline__ void issueTile(uint32_t Sb, const float* __restrict__ P,
                                          int ld, int kk, int tid) {
#pragma unroll
    for (int i = 0; i < 8; i++) {
        int f = tid + i * 128;
        int row = f >> 3, kq = (f & 7) * 4;
        cpasync16(Sb + (uint32_t)(row * LDS_T + kq) * 4, P + (size_t)row * ld + kk + kq);
    }
}

// raw transposed-B staging (src pre-rounded; B[n][k] = W[k][n]) — W2 blocks
__device__ __forceinline__ void stageBT_raw(unsigned* Bs, const float* __restrict__ W,
                                            int n0, int kk, int ldn, int tid) {
#pragma unroll
    for (int i = 0; i < 8; i++) {
        int f = tid + i * 128;
        int kr = f >> 5, nq = (f & 31) * 4;
        uint4 v = *(const uint4*)&W[(size_t)(kk + kr) * ldn + n0 + nq];
        Bs[(nq + 0) * LDS_T + kr] = v.x;
        Bs[(nq + 1) * LDS_T + kr] = v.y;
        Bs[(nq + 2) * LDS_T + kr] = v.z;
        Bs[(nq + 3) * LDS_T + kr] = v.w;
    }
}

__device__ __forceinline__ void compute_tile(const unsigned* __restrict__ As,
                                             const unsigned* __restrict__ Bs,
                                             float c[4][8][4], int wm, int wn, int g, int t) {
#pragma unroll
    for (int ks = 0; ks < 4; ks++) {
        const int k8 = ks * 8;
        unsigned a[4][4];
#pragma unroll
        for (int mt = 0; mt < 4; mt++) {
            int r = wm * 64 + mt * 16;
            a[mt][0] = As[(r + g) * LDS_T + k8 + t];
            a[mt][1] = As[(r + 8 + g) * LDS_T + k8 + t];
            a[mt][2] = As[(r + g) * LDS_T + k8 + 4 + t];
            a[mt][3] = As[(r + 8 + g) * LDS_T + k8 + 4 + t];
        }
#pragma unroll
        for (int nt = 0; nt < 8; nt++) {
            int cx = wn * 64 + nt * 8;
            unsigned bf[2];
            bf[0] = Bs[(cx + g) * LDS_T + k8 + t];
            bf[1] = Bs[(cx + g) * LDS_T + k8 + 4 + t];
#pragma unroll
            for (int mt = 0; mt < 4; mt++)
                mma_tf32(c[mt][nt], a[mt], bf);
        }
    }
}

__device__ __forceinline__ void pipe_loop(uint32_t shb, const float* __restrict__ Ap,
                                          const float* __restrict__ Wp, int K,
                                          unsigned* sh, float c[4][8][4],
                                          int wm, int wn, int g, int t, int tid)
{
    const uint32_t Ab[2] = { shb, shb + 2 * BUFW * 4 };
    const uint32_t Bb[2] = { shb + BUFW * 4, shb + 3 * BUFW * 4 };
    unsigned* Abp[2] = { sh, sh + 2 * BUFW };
    unsigned* Bbp[2] = { sh + BUFW, sh + 3 * BUFW };
    const int NIT = K / 32;

    issueTile(Ab[0], Ap, K, 0, tid);
    issueTile(Bb[0], Wp, K, 0, tid);
    CP_COMMIT();
    for (int kt = 0; kt < NIT; kt++) {
        CP_WAIT0();
        __syncthreads();
        int cur = kt & 1;
        if (kt + 1 < NIT) {
            int nb = cur ^ 1;
            issueTile(Ab[nb], Ap, K, (kt + 1) * 32, tid);
            issueTile(Bb[nb], Wp, K, (kt + 1) * 32, tid);
            CP_COMMIT();
        }
        compute_tile(Abp[cur], Bbp[cur], c, wm, wn, g, t);
    }
}

// ---------------------------------------------------------------------------
// Final GEMM: C = A @ W^T (A=g_vals, W=g_W2, both pre-rounded)
// ---------------------------------------------------------------------------
__global__ __launch_bounds__(128, 2)
void final_gemm(const float* __restrict__ A, const float* __restrict__ W,
                float* __restrict__ C, int M, int N, int K)
{
    extern __shared__ unsigned sh[];
    uint32_t shb = (uint32_t)__cvta_generic_to_shared(sh);
    const int tid = threadIdx.x;
    const int m0 = blockIdx.y * 128, n0 = blockIdx.x * 128;
    const int warp = tid >> 5, lane = tid & 31;
    const int wm = warp & 1, wn = warp >> 1;
    const int g = lane >> 2, t = lane & 3;

    float c[4][8][4];
#pragma unroll
    for (int mt = 0; mt < 4; mt++)
#pragma unroll
        for (int nt = 0; nt < 8; nt++)
#pragma unroll
            for (int i = 0; i < 4; i++) c[mt][nt][i] = 0.f;

    pipe_loop(shb, A + (size_t)m0 * K, W + (size_t)n0 * K, K, sh, c, wm, wn, g, t, tid);

#pragma unroll
    for (int mt = 0; mt < 4; mt++) {
        int r0 = m0 + wm * 64 + mt * 16 + g;
        int r1 = r0 + 8;
#pragma unroll
        for (int nt = 0; nt < 8; nt++) {
            int col = n0 + wn * 64 + nt * 8 + 2 * t;
            *(float2*)&C[(size_t)r0 * N + col] = make_float2(c[mt][nt][0], c[mt][nt][1]);
            *(float2*)&C[(size_t)r1 * N + col] = make_float2(c[mt][nt][2], c[mt][nt][3]);
        }
    }
}

// ---------------------------------------------------------------------------
// Merged projections + W2 in ONE launch (W2 has no upstream dependency on
// proj; riding in the same wave removes its ~90us serial cost).
//  bid < 768 : proj tile (x = bid%24: 0..7 Q, 8..23 KV; y = bid/24)
//  bid >= 768: W2 tile (w = bid-768 -> 8x8), A cp.async + raw transposed B,
//              sources pre-rounded (operand bits identical to f2tf staging).
// ---------------------------------------------------------------------------
__global__ __launch_bounds__(128, 2)
void proj_w2_gemm()
{
    extern __shared__ unsigned sh[];
    uint32_t shb = (uint32_t)__cvta_generic_to_shared(sh);
    const int tid = threadIdx.x;
    const int bid = blockIdx.x;
    const int warp = tid >> 5, lane = tid & 31;
    const int wm = warp & 1, wn = warp >> 1;
    const int g = lane >> 2, t = lane & 3;
    const int K = DIMN;

    float c[4][8][4];
#pragma unroll
    for (int mt = 0; mt < 4; mt++)
#pragma unroll
        for (int nt = 0; nt < 8; nt++)
#pragma unroll
            for (int i = 0; i < 4; i++) c[mt][nt][i] = 0.f;

    if (bid >= 768) {
        // ---- W2 = Wout @ Wout ----
        const int w = bid - 768;
        const int m0 = (w >> 3) * 128, n0 = (w & 7) * 128;
        unsigned* As = sh;
        unsigned* Bs = sh + BUFW;
        for (int kk = 0; kk < K; kk += 32) {
            issueTile(shb, g_WoutT + (size_t)m0 * K, K, kk, tid);
            CP_COMMIT();
            stageBT_raw(Bs, g_WoutT, n0, kk, DIMN, tid);
            CP_WAIT0();
            __syncthreads();
            compute_tile(As, Bs, c, wm, wn, g, t);
            __syncthreads();
        }
#pragma unroll
        for (int mt = 0; mt < 4; mt++) {
            int r0 = m0 + wm * 64 + mt * 16 + g;
            int r1 = r0 + 8;
#pragma unroll
            for (int nt = 0; nt < 8; nt++) {
                int col = n0 + wn * 64 + nt * 8 + 2 * t;
                uint2 v0 = make_uint2(f2tf(c[mt][nt][0]), f2tf(c[mt][nt][1]));
                uint2 v1 = make_uint2(f2tf(c[mt][nt][2]), f2tf(c[mt][nt][3]));
                *(uint2*)&g_W2[(size_t)r0 * DIMN + col] = v0;
                *(uint2*)&g_W2[(size_t)r1 * DIMN + col] = v1;
            }
        }
        return;
    }

    // ---- projections ----
    const int bx = bid % 24, by = bid / 24;
    const bool isQ = bx < 8;
    const float* A = isQ ? g_decT : g_encT;
    const float* W = isQ ? g_WqT : g_WkvT;
    const int n0 = (isQ ? bx : (bx - 8)) * 128;
    const int m0 = by * 128;

    pipe_loop(shb, A + (size_t)m0 * K, W + (size_t)n0 * K, K, sh, c, wm, wn, g, t, tid);

#pragma unroll
    for (int mt = 0; mt < 4; mt++) {
        int r0 = wm * 64 + mt * 16 + g;
        int r1 = r0 + 8;
#pragma unroll
        for (int nt = 0; nt < 8; nt++) {
            int col = n0 + wn * 64 + nt * 8 + 2 * t;
#pragma unroll
            for (int e = 0; e < 4; e++) {
                int m = m0 + ((e < 2) ? r0 : r1);
                int n = col + (e & 1);
                float v = c[mt][nt][e];
                int b = m >> 10, q = m & 1023;
                if (isQ) {
                    int h = n & 15, d = n >> 4;
                    g_Qh[(((size_t)(b * NH + h) * QL + q) * DK) + d] =
                        __uint_as_float(f2tf(v * 0.125f));
                } else if (n < DIMN) {
                    int h = n & 15, d = n >> 4;
                    g_Kh[(((size_t)(b * NH + h) * KL + q) * DK) + d] =
                        __uint_as_float(f2tf(v));
                } else {
                    int nn = n - DIMN;
                    int h = nn & 15, d = nn >> 4;
                    g_Vh[(((size_t)(b * NH + h) * KL + q) * DK) + d] =
                        __uint_as_float(f2tf(v));
                }
            }
        }
    }
}

// ---------------------------------------------------------------------------
// Fused attention, cp.async edition (unchanged from R10 passing run).
// ---------------------------------------------------------------------------
#define ATT_LD 68
#define VLD 72
#define AQOFF 0
#define AKOFF(buf) (4352 + (buf) * 4352)
#define AVOFF(buf) (13056 + (buf) * 4608)
#define APSOFF 22272
#define ATT_SMEM (26624 * 4)

__device__ __forceinline__ void att_issue68(uint32_t shb, int woff,
                                            const float* __restrict__ src, int tid) {
#pragma unroll
    for (int i = 0; i < 8; i++) {
        int cch = tid + i * 128;
        int row = cch >> 4, c16 = cch & 15;
        cpasync16(shb + (uint32_t)(woff + row * ATT_LD + c16 * 4) * 4,
                  src + (size_t)row * DK + c16 * 4);
    }
}
__device__ __forceinline__ void att_issue72(uint32_t shb, int woff,
                                            const float* __restrict__ src, int tid) {
#pragma unroll
    for (int i = 0; i < 8; i++) {
        int cch = tid + i * 128;
        int row = cch >> 4, c16 = cch & 15;
        cpasync16(shb + (uint32_t)(woff + row * VLD + c16 * 4) * 4,
                  src + (size_t)row * DK + c16 * 4);
    }
}

__global__ __launch_bounds__(128, 2)
void attn_kernel()
{
    extern __shared__ unsigned smU[];
    uint32_t shb = (uint32_t)__cvta_generic_to_shared(smU);
    unsigned* Qs = smU + AQOFF;
    unsigned* Ps = smU + APSOFF;

    const int head = blockIdx.y;
    const int b = head >> 4, h = head & 15;
    const int q0 = blockIdx.x * 64;
    const int tid = threadIdx.x;
    const int w = tid >> 5, lane = tid & 31;
    const int g = lane >> 2, t = lane & 3;
    const int wq0 = w * 16;
    const int allTrue = g_allTrue;

    const float* Qp = g_Qh + (size_t)head * QL * DK;
    const float* Kp = g_Kh + (size_t)head * KL * DK;
    const float* Vp = g_Vh + (size_t)head * KL * DK;

    att_issue68(shb, AQOFF, Qp + (size_t)q0 * DK, tid);
    att_issue68(shb, AKOFF(0), Kp, tid);
    att_issue72(shb, AVOFF(0), Vp, tid);
    CP_COMMIT();

    float o[8][4];
#pragma unroll
    for (int nt = 0; nt < 8; nt++)
#pragma unroll
        for (int i = 0; i < 4; i++) o[nt][i] = 0.f;
    float l0 = 0.f, l1 = 0.f;

    const int NKT = KL / 64;  // 16
    for (int kt = 0; kt < NKT; kt++) {
        CP_WAIT0();
        __syncthreads();
        const int cur = kt & 1;
        if (kt + 1 < NKT) {
            att_issue68(shb, AKOFF(cur ^ 1), Kp + (size_t)(kt + 1) * 64 * DK, tid);
            att_issue72(shb, AVOFF(cur ^ 1), Vp + (size_t)(kt + 1) * 64 * DK, tid);
            CP_COMMIT();
        }
        const unsigned* Kc = smU + AKOFF(cur);
        const unsigned* Vc = smU + AVOFF(cur);

        float s[8][4];
#pragma unroll
        for (int nt = 0; nt < 8; nt++)
#pragma unroll
            for (int i = 0; i < 4; i++) s[nt][i] = 0.f;

#pragma unroll
        for (int ks = 0; ks < 8; ks++) {
            const int k8 = ks * 8;
            unsigned a[4];
            a[0] = Qs[(wq0 + g) * ATT_LD + k8 + t];
            a[1] = Qs[(wq0 + 8 + g) * ATT_LD + k8 + t];
            a[2] = Qs[(wq0 + g) * ATT_LD + k8 + 4 + t];
            a[3] = Qs[(wq0 + 8 + g) * ATT_LD + k8 + 4 + t];
#pragma unroll
            for (int nt = 0; nt < 8; nt++) {
                unsigned bf[2];
                bf[0] = Kc[(nt * 8 + g) * ATT_LD + k8 + t];
                bf[1] = Kc[(nt * 8 + g) * ATT_LD + k8 + 4 + t];
                mma_tf32(s[nt], a, bf);
            }
        }

        int qr0 = wq0 + g, qr1 = wq0 + 8 + g;
        const unsigned char* m0p = g_mask8 + ((size_t)(b * QL + q0 + qr0)) * KL + kt * 64;
        const unsigned char* m1p = g_mask8 + ((size_t)(b * QL + q0 + qr1)) * KL + kt * 64;
        float rs0 = 0.f, rs1 = 0.f;
#pragma unroll
        for (int nt = 0; nt < 8; nt++) {
            int kc = nt * 8 + 2 * t;
            float p00, p01, p10, p11;
            if (allTrue) {
                p00 = __expf(s[nt][0]); p01 = __expf(s[nt][1]);
                p10 = __expf(s[nt][2]); p11 = __expf(s[nt][3]);
            } else {
                p00 = m0p[kc]     ? __expf(s[nt][0]) : 0.f;
                p01 = m0p[kc + 1] ? __expf(s[nt][1]) : 0.f;
                p10 = m1p[kc]     ? __expf(s[nt][2]) : 0.f;
                p11 = m1p[kc + 1] ? __expf(s[nt][3]) : 0.f;
            }
            rs0 += p00 + p01;
            rs1 += p10 + p11;
            *(uint2*)&Ps[qr0 * ATT_LD + kc] = make_uint2(f2tf(p00), f2tf(p01));
            *(uint2*)&Ps[qr1 * ATT_LD + kc] = make_uint2(f2tf(p10), f2tf(p11));
        }
        rs0 += __shfl_xor_sync(0xffffffffu, rs0, 1);
        rs0 += __shfl_xor_sync(0xffffffffu, rs0, 2);
        rs1 += __shfl_xor_sync(0xffffffffu, rs1, 1);
        rs1 += __shfl_xor_sync(0xffffffffu, rs1, 2);
        l0 += rs0;
        l1 += rs1;
        __syncwarp();

#pragma unroll
        for (int ks = 0; ks < 8; ks++) {
            const int k8 = ks * 8;
            unsigned a[4];
            a[0] = Ps[(wq0 + g) * ATT_LD + k8 + t];
            a[1] = Ps[(wq0 + 8 + g) * ATT_LD + k8 + t];
            a[2] = Ps[(wq0 + g) * ATT_LD + k8 + 4 + t];
            a[3] = Ps[(wq0 + 8 + g) * ATT_LD + k8 + 4 + t];
#pragma unroll
            for (int nt = 0; nt < 8; nt++) {
                unsigned bf[2];
                bf[0] = Vc[(k8 + t) * VLD + nt * 8 + g];
                bf[1] = Vc[(k8 + 4 + t) * VLD + nt * 8 + g];
                mma_tf32(o[nt], a, bf);
            }
        }
    }

    float inv0 = 1.f / l0, inv1 = 1.f / l1;
    int qa = q0 + wq0 + g, qb = qa + 8;
#pragma unroll
    for (int nt = 0; nt < 8; nt++) {
        int d = nt * 8 + 2 * t;
        float* base0 = &g_vals[((size_t)(b * QL + qa)) * DIMN + d * NH + h];
        float* base1 = &g_vals[((size_t)(b * QL + qb)) * DIMN + d * NH + h];
        base0[0]  = __uint_as_float(f2tf(o[nt][0] * inv0));
        base0[NH] = __uint_as_float(f2tf(o[nt][1] * inv0));
        base1[0]  = __uint_as_float(f2tf(o[nt][2] * inv1));
        base1[NH] = __uint_as_float(f2tf(o[nt][3] * inv1));
    }
}

// ---------------------------------------------------------------------------
extern "C" void kernel_launch(void* const* d_in, const int* in_sizes, int n_in,
                              void* d_out, int out_size)
{
    const float* dec  = (const float*)d_in[0];
    const float* enc  = (const float*)d_in[1];
    const unsigned char* mask = (const unsigned char*)d_in[2];
    const float* Wq   = (const float*)d_in[3];
    const float* Wkv  = (const float*)d_in[4];
    const float* Wout = (const float*)d_in[5];
    float* out = (float*)d_out;

    float *vals_p, *w2_p;
    cudaGetSymbolAddress((void**)&vals_p, g_vals);
    cudaGetSymbolAddress((void**)&w2_p, g_W2);

    cudaFuncSetAttribute(final_gemm,   cudaFuncAttributeMaxDynamicSharedMemorySize, GEMM_SMEM);
    cudaFuncSetAttribute(proj_w2_gemm, cudaFuncAttributeMaxDynamicSharedMemorySize, GEMM_SMEM);
    cudaFuncSetAttribute(attn_kernel,  cudaFuncAttributeMaxDynamicSharedMemorySize, ATT_SMEM);

    const int M = BATCH * QL; // 4096
    const int NMASK = BATCH * QL * KL;
    dim3 blk(128);

    mask_detect_kernel<<<1, 256>>>(mask);
    mask_convert_kernel<<<(NMASK + 255) / 256, 256>>>(mask, NMASK);

    // fused tf32 pre-round of all GEMM inputs (incl. Wout)
    cvt_all_kernel<<<(int)((SEG5 / 4 + 255) / 256), 256>>>(dec, enc, Wq, Wkv, Wout);

    // merged Q + KV projections + W2 (runs concurrently in one wave)
    proj_w2_gemm<<<dim3(832), blk, GEMM_SMEM>>>();
    // fused attention -> g_vals (pre-rounded)
    attn_kernel<<<dim3(QL / 64, BATCH * NH), dim3(128), ATT_SMEM>>>();
    // out = vals @ W2^T
    final_gemm<<<dim3(8, M / 128), blk, GEMM_SMEM>>>(vals_p, w2_p, out, M, DIMN, DIMN);
}

// round 12
// speedup vs baseline: 1.3988x; 1.0070x over previous
#include <cuda_runtime.h>
#include <cstddef>
#include <cstdint>

#define DIMN 1024
#define NH   16
#define DK   64
#define BATCH 4
#define QL   1024
#define KL   1024

// Scratch (device globals: allocation-free rule)
__device__ float g_Qh[BATCH*NH*QL*DK];   // tf32-rounded, pre-scaled by 1/8
__device__ float g_Kh[BATCH*NH*KL*DK];   // tf32-rounded
__device__ float g_Vh[BATCH*NH*KL*DK];   // tf32-rounded
__device__ float g_vals[BATCH*QL*DIMN];  // attention out, tf32-rounded
__device__ float g_W2[DIMN*DIMN];        // Wout @ Wout, tf32-rounded
__device__ float g_decT[BATCH*QL*DIMN];
__device__ float g_encT[BATCH*KL*DIMN];
__device__ float g_WqT[DIMN*DIMN];
__device__ float g_WkvT[2*DIMN*DIMN];
__device__ float g_WoutT[DIMN*DIMN];
__device__ unsigned char g_mask8[BATCH*QL*KL];
__device__ int g_isByte;
__device__ int g_allTrue;

// ---------------------------------------------------------------------------
__device__ __forceinline__ unsigned f2tf(float x) {
    unsigned r;
    asm("cvt.rna.tf32.f32 %0, %1;" : "=r"(r) : "f"(x));
    return r;
}

__device__ __forceinline__ void mma_tf32(float c[4], const unsigned a[4], const unsigned b[2]) {
    asm("mma.sync.aligned.m16n8k8.row.col.f32.tf32.tf32.f32 "
        "{%0,%1,%2,%3}, {%4,%5,%6,%7}, {%8,%9}, {%0,%1,%2,%3};"
        : "+f"(c[0]), "+f"(c[1]), "+f"(c[2]), "+f"(c[3])
        : "r"(a[0]), "r"(a[1]), "r"(a[2]), "r"(a[3]), "r"(b[0]), "r"(b[1]));
}

__device__ __forceinline__ void cpasync16(uint32_t dst, const void* src) {
    asm volatile("cp.async.cg.shared.global [%0], [%1], 16;" :: "r"(dst), "l"(src));
}
#define CP_COMMIT()  asm volatile("cp.async.commit_group;" ::: "memory")
#define CP_WAIT0()   asm volatile("cp.async.wait_all;" ::: "memory")
#define CP_WAIT1()   asm volatile("cp.async.wait_group 1;" ::: "memory")

// ---------------------------------------------------------------------------
// Fused tf32 pre-round prep: dec | enc | Wq | Wkv | Wout in one launch
// ---------------------------------------------------------------------------
#define SEG1 4194304L    // dec floats
#define SEG2 8388608L    // + enc
#define SEG3 9437184L    // + Wq
#define SEG4 11534336L   // + Wkv
#define SEG5 12582912L   // + Wout

__global__ void cvt_all_kernel(const float* __restrict__ dec, const float* __restrict__ enc,
                               const float* __restrict__ wq, const float* __restrict__ wkv,
                               const float* __restrict__ wout)
{
    long i = ((long)blockIdx.x * blockDim.x + threadIdx.x) * 4;
    if (i >= SEG5) return;
    const float* src; float* dst; long off;
    if (i < SEG1)      { src = dec;  dst = g_decT;  off = i; }
    else if (i < SEG2) { src = enc;  dst = g_encT;  off = i - SEG1; }
    else if (i < SEG3) { src = wq;   dst = g_WqT;   off = i - SEG2; }
    else if (i < SEG4) { src = wkv;  dst = g_WkvT;  off = i - SEG3; }
    else               { src = wout; dst = g_WoutT; off = i - SEG4; }
    float4 v = *(const float4*)&src[off];
    uint4 u = make_uint4(f2tf(v.x), f2tf(v.y), f2tf(v.z), f2tf(v.w));
    *(uint4*)&dst[off] = u;
}

// ---------------------------------------------------------------------------
// Mask dtype detect (int32 vs byte)
// ---------------------------------------------------------------------------
__global__ void mask_detect_kernel(const unsigned char* __restrict__ m)
{
    __shared__ int found;
    if (threadIdx.x == 0) { found = 0; g_allTrue = 1; }
    __syncthreads();
    for (int i = threadIdx.x; i < 16384; i += blockDim.x)
        if ((i & 3) && m[i]) found = 1;
    __syncthreads();
    if (threadIdx.x == 0) g_isByte = found;
}

__global__ void mask_convert_kernel(const unsigned char* __restrict__ m, int n)
{
    int i = blockIdx.x * blockDim.x + threadIdx.x;
    int v = 1;
    if (i < n) {
        v = g_isByte ? (m[i] ? 1 : 0) : (((const unsigned*)m)[i] ? 1 : 0);
        g_mask8[i] = (unsigned char)v;
    }
    int all = __syncthreads_and(v);
    if (!all && threadIdx.x == 0) g_allTrue = 0;
}

// ---------------------------------------------------------------------------
// GEMM core: BM=BN=128, BK=32, 128 threads = 4 warps (2M x 2N), warp 64x64.
// SMEM stride 36 words (conflict-free frags: bank = 4*g + t).
// 3-stage cp.async pipeline, wait_group 1 (prefetch distance 2), one
// __syncthreads per iteration. Buffer s: A @ s*2*BUFW, B @ s*2*BUFW+BUFW.
// ---------------------------------------------------------------------------
#define LDS_T 36
#define BUFW (128 * LDS_T)
#define GEMM_SMEM (6 * BUFW * 4)    // 3 x (A+B) = 110592 B -> 2 CTAs/SM

__device__ __forceinline__ void issueTile(uint32_t Sb, const float* __restrict__ P,
                                          int ld, int kk, int tid) {
#pragma unroll
    for (int i = 0; i < 8; i++) {
        int f = tid + i * 128;
        int row = f >> 3, kq = (f & 7) * 4;
        cpasync16(Sb + (uint32_t)(row * LDS_T + kq) * 4, P + (size_t)row * ld + kk + kq);
    }
}

// raw transposed-B staging (src pre-rounded; B[n][k] = W[k][n]) — W2 blocks
__device__ __forceinline__ void stageBT_raw(unsigned* Bs, const float* __restrict__ W,
                                            int n0, int kk, int ldn, int tid) {
#pragma unroll
    for (int i = 0; i < 8; i++) {
        int f = tid + i * 128;
        int kr = f >> 5, nq = (f & 31) * 4;
        uint4 v = *(const uint4*)&W[(size_t)(kk + kr) * ldn + n0 + nq];
        Bs[(nq + 0) * LDS_T + kr] = v.x;
        Bs[(nq + 1) * LDS_T + kr] = v.y;
        Bs[(nq + 2) * LDS_T + kr] = v.z;
        Bs[(nq + 3) * LDS_T + kr] = v.w;
    }
}

__device__ __forceinline__ void compute_tile(const unsigned* __restrict__ As,
                                             const unsigned* __restrict__ Bs,
                                             float c[4][8][4], int wm, int wn, int g, int t) {
#pragma unroll
    for (int ks = 0; ks < 4; ks++) {
        const int k8 = ks * 8;
        unsigned a[4][4];
#pragma unroll
        for (int mt = 0; mt < 4; mt++) {
            int r = wm * 64 + mt * 16;
            a[mt][0] = As[(r + g) * LDS_T + k8 + t];
            a[mt][1] = As[(r + 8 + g) * LDS_T + k8 + t];
            a[mt][2] = As[(r + g) * LDS_T + k8 + 4 + t];
            a[mt][3] = As[(r + 8 + g) * LDS_T + k8 + 4 + t];
        }
#pragma unroll
        for (int nt = 0; nt < 8; nt++) {
            int cx = wn * 64 + nt * 8;
            unsigned bf[2];
            bf[0] = Bs[(cx + g) * LDS_T + k8 + t];
            bf[1] = Bs[(cx + g) * LDS_T + k8 + 4 + t];
#pragma unroll
            for (int mt = 0; mt < 4; mt++)
                mma_tf32(c[mt][nt], a[mt], bf);
        }
    }
}

// 3-stage pipeline. At top of iter kt: wait_group 1 leaves only the newest
// group (tile kt+1) pending -> tile kt complete; last iter uses wait_all.
// The barrier proves compute(kt-1) done before reusing buffer (kt+2)%3.
__device__ __forceinline__ void pipe_loop(uint32_t shb, const float* __restrict__ Ap,
                                          const float* __restrict__ Wp, int K,
                                          unsigned* sh, float c[4][8][4],
                                          int wm, int wn, int g, int t, int tid)
{
    const int NIT = K / 32;
    issueTile(shb,                Ap, K, 0, tid);
    issueTile(shb + BUFW * 4,     Wp, K, 0, tid);
    CP_COMMIT();
    issueTile(shb + 2 * BUFW * 4, Ap, K, 32, tid);
    issueTile(shb + 3 * BUFW * 4, Wp, K, 32, tid);
    CP_COMMIT();

    int cur = 0;
    for (int kt = 0; kt < NIT; kt++) {
        if (kt + 1 < NIT) { CP_WAIT1(); } else { CP_WAIT0(); }
        __syncthreads();
        if (kt + 2 < NIT) {
            int nb = cur + 2; if (nb >= 3) nb -= 3;
            uint32_t base = shb + (uint32_t)(nb * 2 * BUFW) * 4;
            issueTile(base,            Ap, K, (kt + 2) * 32, tid);
            issueTile(base + BUFW * 4, Wp, K, (kt + 2) * 32, tid);
            CP_COMMIT();
        }
        compute_tile(sh + cur * 2 * BUFW, sh + cur * 2 * BUFW + BUFW, c, wm, wn, g, t);
        cur = (cur == 2) ? 0 : cur + 1;
    }
}

// ---------------------------------------------------------------------------
// Final GEMM: C = A @ W^T (A=g_vals, W=g_W2, both pre-rounded)
// ---------------------------------------------------------------------------
__global__ __launch_bounds__(128, 2)
void final_gemm(const float* __restrict__ A, const float* __restrict__ W,
                float* __restrict__ C, int M, int N, int K)
{
    extern __shared__ unsigned sh[];
    uint32_t shb = (uint32_t)__cvta_generic_to_shared(sh);
    const int tid = threadIdx.x;
    const int m0 = blockIdx.y * 128, n0 = blockIdx.x * 128;
    const int warp = tid >> 5, lane = tid & 31;
    const int wm = warp & 1, wn = warp >> 1;
    const int g = lane >> 2, t = lane & 3;

    float c[4][8][4];
#pragma unroll
    for (int mt = 0; mt < 4; mt++)
#pragma unroll
        for (int nt = 0; nt < 8; nt++)
#pragma unroll
            for (int i = 0; i < 4; i++) c[mt][nt][i] = 0.f;

    pipe_loop(shb, A + (size_t)m0 * K, W + (size_t)n0 * K, K, sh, c, wm, wn, g, t, tid);

#pragma unroll
    for (int mt = 0; mt < 4; mt++) {
        int r0 = m0 + wm * 64 + mt * 16 + g;
        int r1 = r0 + 8;
#pragma unroll
        for (int nt = 0; nt < 8; nt++) {
            int col = n0 + wn * 64 + nt * 8 + 2 * t;
            *(float2*)&C[(size_t)r0 * N + col] = make_float2(c[mt][nt][0], c[mt][nt][1]);
            *(float2*)&C[(size_t)r1 * N + col] = make_float2(c[mt][nt][2], c[mt][nt][3]);
        }
    }
}

// ---------------------------------------------------------------------------
// Merged projections + W2 in ONE launch.
//  bid < 768 : proj tile (x = bid%24: 0..7 Q, 8..23 KV; y = bid/24)
//  bid >= 768: W2 tile (8x8); A cp.async + raw transposed B (pre-rounded)
// ---------------------------------------------------------------------------
__global__ __launch_bounds__(128, 2)
void proj_w2_gemm()
{
    extern __shared__ unsigned sh[];
    uint32_t shb = (uint32_t)__cvta_generic_to_shared(sh);
    const int tid = threadIdx.x;
    const int bid = blockIdx.x;
    const int warp = tid >> 5, lane = tid & 31;
    const int wm = warp & 1, wn = warp >> 1;
    const int g = lane >> 2, t = lane & 3;
    const int K = DIMN;

    float c[4][8][4];
#pragma unroll
    for (int mt = 0; mt < 4; mt++)
#pragma unroll
        for (int nt = 0; nt < 8; nt++)
#pragma unroll
            for (int i = 0; i < 4; i++) c[mt][nt][i] = 0.f;

    if (bid >= 768) {
        // ---- W2 = Wout @ Wout ----
        const int w = bid - 768;
        const int m0 = (w >> 3) * 128, n0 = (w & 7) * 128;
        unsigned* As = sh;
        unsigned* Bs = sh + BUFW;
        for (int kk = 0; kk < K; kk += 32) {
            issueTile(shb, g_WoutT + (size_t)m0 * K, K, kk, tid);
            CP_COMMIT();
            stageBT_raw(Bs, g_WoutT, n0, kk, DIMN, tid);
            CP_WAIT0();
            __syncthreads();
            compute_tile(As, Bs, c, wm, wn, g, t);
            __syncthreads();
        }
#pragma unroll
        for (int mt = 0; mt < 4; mt++) {
            int r0 = m0 + wm * 64 + mt * 16 + g;
            int r1 = r0 + 8;
#pragma unroll
            for (int nt = 0; nt < 8; nt++) {
                int col = n0 + wn * 64 + nt * 8 + 2 * t;
                uint2 v0 = make_uint2(f2tf(c[mt][nt][0]), f2tf(c[mt][nt][1]));
                uint2 v1 = make_uint2(f2tf(c[mt][nt][2]), f2tf(c[mt][nt][3]));
                *(uint2*)&g_W2[(size_t)r0 * DIMN + col] = v0;
                *(uint2*)&g_W2[(size_t)r1 * DIMN + col] = v1;
            }
        }
        return;
    }

    // ---- projections ----
    const int bx = bid % 24, by = bid / 24;
    const bool isQ = bx < 8;
    const float* A = isQ ? g_decT : g_encT;
    const float* W = isQ ? g_WqT : g_WkvT;
    const int n0 = (isQ ? bx : (bx - 8)) * 128;
    const int m0 = by * 128;

    pipe_loop(shb, A + (size_t)m0 * K, W + (size_t)n0 * K, K, sh, c, wm, wn, g, t, tid);

#pragma unroll
    for (int mt = 0; mt < 4; mt++) {
        int r0 = wm * 64 + mt * 16 + g;
        int r1 = r0 + 8;
#pragma unroll
        for (int nt = 0; nt < 8; nt++) {
            int col = n0 + wn * 64 + nt * 8 + 2 * t;
#pragma unroll
            for (int e = 0; e < 4; e++) {
                int m = m0 + ((e < 2) ? r0 : r1);
                int n = col + (e & 1);
                float v = c[mt][nt][e];
                int b = m >> 10, q = m & 1023;
                if (isQ) {
                    int h = n & 15, d = n >> 4;
                    g_Qh[(((size_t)(b * NH + h) * QL + q) * DK) + d] =
                        __uint_as_float(f2tf(v * 0.125f));
                } else if (n < DIMN) {
                    int h = n & 15, d = n >> 4;
                    g_Kh[(((size_t)(b * NH + h) * KL + q) * DK) + d] =
                        __uint_as_float(f2tf(v));
                } else {
                    int nn = n - DIMN;
                    int h = nn & 15, d = nn >> 4;
                    g_Vh[(((size_t)(b * NH + h) * KL + q) * DK) + d] =
                        __uint_as_float(f2tf(v));
                }
            }
        }
    }
}

// ---------------------------------------------------------------------------
// Fused attention, cp.async edition (unchanged from R10/R11 passing runs).
// ---------------------------------------------------------------------------
#define ATT_LD 68
#define VLD 72
#define AQOFF 0
#define AKOFF(buf) (4352 + (buf) * 4352)
#define AVOFF(buf) (13056 + (buf) * 4608)
#define APSOFF 22272
#define ATT_SMEM (26624 * 4)

__device__ __forceinline__ void att_issue68(uint32_t shb, int woff,
                                            const float* __restrict__ src, int tid) {
#pragma unroll
    for (int i = 0; i < 8; i++) {
        int cch = tid + i * 128;
        int row = cch >> 4, c16 = cch & 15;
        cpasync16(shb + (uint32_t)(woff + row * ATT_LD + c16 * 4) * 4,
                  src + (size_t)row * DK + c16 * 4);
    }
}
__device__ __forceinline__ void att_issue72(uint32_t shb, int woff,
                                            const float* __restrict__ src, int tid) {
#pragma unroll
    for (int i = 0; i < 8; i++) {
        int cch = tid + i * 128;
        int row = cch >> 4, c16 = cch & 15;
        cpasync16(shb + (uint32_t)(woff + row * VLD + c16 * 4) * 4,
                  src + (size_t)row * DK + c16 * 4);
    }
}

__global__ __launch_bounds__(128, 2)
void attn_kernel()
{
    extern __shared__ unsigned smU[];
    uint32_t shb = (uint32_t)__cvta_generic_to_shared(smU);
    unsigned* Qs = smU + AQOFF;
    unsigned* Ps = smU + APSOFF;

    const int head = blockIdx.y;
    const int b = head >> 4, h = head & 15;
    const int q0 = blockIdx.x * 64;
    const int tid = threadIdx.x;
    const int w = tid >> 5, lane = tid & 31;
    const int g = lane >> 2, t = lane & 3;
    const int wq0 = w * 16;
    const int allTrue = g_allTrue;

    const float* Qp = g_Qh + (size_t)head * QL * DK;
    const float* Kp = g_Kh + (size_t)head * KL * DK;
    const float* Vp = g_Vh + (size_t)head * KL * DK;

    att_issue68(shb, AQOFF, Qp + (size_t)q0 * DK, tid);
    att_issue68(shb, AKOFF(0), Kp, tid);
    att_issue72(shb, AVOFF(0), Vp, tid);
    CP_COMMIT();

    float o[8][4];
#pragma unroll
    for (int nt = 0; nt < 8; nt++)
#pragma unroll
        for (int i = 0; i < 4; i++) o[nt][i] = 0.f;
    float l0 = 0.f, l1 = 0.f;

    const int NKT = KL / 64;  // 16
    for (int kt = 0; kt < NKT; kt++) {
        CP_WAIT0();
        __syncthreads();
        const int cur = kt & 1;
        if (kt + 1 < NKT) {
            att_issue68(shb, AKOFF(cur ^ 1), Kp + (size_t)(kt + 1) * 64 * DK, tid);
            att_issue72(shb, AVOFF(cur ^ 1), Vp + (size_t)(kt + 1) * 64 * DK, tid);
            CP_COMMIT();
        }
        const unsigned* Kc = smU + AKOFF(cur);
        const unsigned* Vc = smU + AVOFF(cur);

        float s[8][4];
#pragma unroll
        for (int nt = 0; nt < 8; nt++)
#pragma unroll
            for (int i = 0; i < 4; i++) s[nt][i] = 0.f;

#pragma unroll
        for (int ks = 0; ks < 8; ks++) {
            const int k8 = ks * 8;
            unsigned a[4];
            a[0] = Qs[(wq0 + g) * ATT_LD + k8 + t];
            a[1] = Qs[(wq0 + 8 + g) * ATT_LD + k8 + t];
            a[2] = Qs[(wq0 + g) * ATT_LD + k8 + 4 + t];
            a[3] = Qs[(wq0 + 8 + g) * ATT_LD + k8 + 4 + t];
#pragma unroll
            for (int nt = 0; nt < 8; nt++) {
                unsigned bf[2];
                bf[0] = Kc[(nt * 8 + g) * ATT_LD + k8 + t];
                bf[1] = Kc[(nt * 8 + g) * ATT_LD + k8 + 4 + t];
                mma_tf32(s[nt], a, bf);
            }
        }

        int qr0 = wq0 + g, qr1 = wq0 + 8 + g;
        const unsigned char* m0p = g_mask8 + ((size_t)(b * QL + q0 + qr0)) * KL + kt * 64;
        const unsigned char* m1p = g_mask8 + ((size_t)(b * QL + q0 + qr1)) * KL + kt * 64;
        float rs0 = 0.f, rs1 = 0.f;
#pragma unroll
        for (int nt = 0; nt < 8; nt++) {
            int kc = nt * 8 + 2 * t;
            float p00, p01, p10, p11;
            if (allTrue) {
                p00 = __expf(s[nt][0]); p01 = __expf(s[nt][1]);
                p10 = __expf(s[nt][2]); p11 = __expf(s[nt][3]);
            } else {
                p00 = m0p[kc]     ? __expf(s[nt][0]) : 0.f;
                p01 = m0p[kc + 1] ? __expf(s[nt][1]) : 0.f;
                p10 = m1p[kc]     ? __expf(s[nt][2]) : 0.f;
                p11 = m1p[kc + 1] ? __expf(s[nt][3]) : 0.f;
            }
            rs0 += p00 + p01;
            rs1 += p10 + p11;
            *(uint2*)&Ps[qr0 * ATT_LD + kc] = make_uint2(f2tf(p00), f2tf(p01));
            *(uint2*)&Ps[qr1 * ATT_LD + kc] = make_uint2(f2tf(p10), f2tf(p11));
        }
        rs0 += __shfl_xor_sync(0xffffffffu, rs0, 1);
        rs0 += __shfl_xor_sync(0xffffffffu, rs0, 2);
        rs1 += __shfl_xor_sync(0xffffffffu, rs1, 1);
        rs1 += __shfl_xor_sync(0xffffffffu, rs1, 2);
        l0 += rs0;
        l1 += rs1;
        __syncwarp();

#pragma unroll
        for (int ks = 0; ks < 8; ks++) {
            const int k8 = ks * 8;
            unsigned a[4];
            a[0] = Ps[(wq0 + g) * ATT_LD + k8 + t];
            a[1] = Ps[(wq0 + 8 + g) * ATT_LD + k8 + t];
            a[2] = Ps[(wq0 + g) * ATT_LD + k8 + 4 + t];
            a[3] = Ps[(wq0 + 8 + g) * ATT_LD + k8 + 4 + t];
#pragma unroll
            for (int nt = 0; nt < 8; nt++) {
                unsigned bf[2];
                bf[0] = Vc[(k8 + t) * VLD + nt * 8 + g];
                bf[1] = Vc[(k8 + 4 + t) * VLD + nt * 8 + g];
                mma_tf32(o[nt], a, bf);
            }
        }
    }

    float inv0 = 1.f / l0, inv1 = 1.f / l1;
    int qa = q0 + wq0 + g, qb = qa + 8;
#pragma unroll
    for (int nt = 0; nt < 8; nt++) {
        int d = nt * 8 + 2 * t;
        float* base0 = &g_vals[((size_t)(b * QL + qa)) * DIMN + d * NH + h];
        float* base1 = &g_vals[((size_t)(b * QL + qb)) * DIMN + d * NH + h];
        base0[0]  = __uint_as_float(f2tf(o[nt][0] * inv0));
        base0[NH] = __uint_as_float(f2tf(o[nt][1] * inv0));
        base1[0]  = __uint_as_float(f2tf(o[nt][2] * inv1));
        base1[NH] = __uint_as_float(f2tf(o[nt][3] * inv1));
    }
}

// ---------------------------------------------------------------------------
extern "C" void kernel_launch(void* const* d_in, const int* in_sizes, int n_in,
                              void* d_out, int out_size)
{
    const float* dec  = (const float*)d_in[0];
    const float* enc  = (const float*)d_in[1];
    const unsigned char* mask = (const unsigned char*)d_in[2];
    const float* Wq   = (const float*)d_in[3];
    const float* Wkv  = (const float*)d_in[4];
    const float* Wout = (const float*)d_in[5];
    float* out = (float*)d_out;

    float *vals_p, *w2_p;
    cudaGetSymbolAddress((void**)&vals_p, g_vals);
    cudaGetSymbolAddress((void**)&w2_p, g_W2);

    cudaFuncSetAttribute(final_gemm,   cudaFuncAttributeMaxDynamicSharedMemorySize, GEMM_SMEM);
    cudaFuncSetAttribute(proj_w2_gemm, cudaFuncAttributeMaxDynamicSharedMemorySize, GEMM_SMEM);
    cudaFuncSetAttribute(attn_kernel,  cudaFuncAttributeMaxDynamicSharedMemorySize, ATT_SMEM);

    const int M = BATCH * QL; // 4096
    const int NMASK = BATCH * QL * KL;
    dim3 blk(128);

    mask_detect_kernel<<<1, 256>>>(mask);
    mask_convert_kernel<<<(NMASK + 255) / 256, 256>>>(mask, NMASK);

    // fused tf32 pre-round of all GEMM inputs (incl. Wout)
    cvt_all_kernel<<<(int)((SEG5 / 4 + 255) / 256), 256>>>(dec, enc, Wq, Wkv, Wout);

    // merged Q + KV projections + W2 (one wave)
    proj_w2_gemm<<<dim3(832), blk, GEMM_SMEM>>>();
    // fused attention -> g_vals (pre-rounded)
    attn_kernel<<<dim3(QL / 64, BATCH * NH), dim3(128), ATT_SMEM>>>();
    // out = vals @ W2^T
    final_gemm<<<dim3(8, M / 128), blk, GEMM_SMEM>>>(vals_p, w2_p, out, M, DIMN, DIMN);
}

// round 13
// speedup vs baseline: 1.4815x; 1.0591x over previous
#include <cuda_runtime.h>
#include <cstddef>
#include <cstdint>

#define DIMN 1024
#define NH   16
#define DK   64
#define BATCH 4
#define QL   1024
#define KL   1024

// Scratch (device globals: allocation-free rule)
__device__ float g_Qh[BATCH*NH*QL*DK];   // tf32-rounded, pre-scaled by 1/8
__device__ float g_Kh[BATCH*NH*KL*DK];   // tf32-rounded
__device__ float g_Vh[BATCH*NH*KL*DK];   // tf32-rounded
__device__ float g_vals[BATCH*QL*DIMN];  // attention out, tf32-rounded
__device__ float g_W2[DIMN*DIMN];        // Wout @ Wout, tf32-rounded
__device__ float g_decA[BATCH*QL*DIMN];  // dec, A-fragment-major tf32
__device__ float g_encA[BATCH*KL*DIMN];  // enc, A-fragment-major tf32
__device__ float g_WqB[DIMN*DIMN];       // Wq, B-fragment-major tf32
__device__ float g_WkvB[2*DIMN*DIMN];    // Wkv, B-fragment-major tf32
__device__ float g_WoutT[DIMN*DIMN];     // Wout, row-major tf32 (W2 legacy)
__device__ unsigned char g_mask8[BATCH*QL*KL];
__device__ int g_isByte;
__device__ int g_allTrue;

// ---------------------------------------------------------------------------
__device__ __forceinline__ unsigned f2tf(float x) {
    unsigned r;
    asm("cvt.rna.tf32.f32 %0, %1;" : "=r"(r) : "f"(x));
    return r;
}

__device__ __forceinline__ void mma_tf32(float c[4], const unsigned a[4], const unsigned b[2]) {
    asm("mma.sync.aligned.m16n8k8.row.col.f32.tf32.tf32.f32 "
        "{%0,%1,%2,%3}, {%4,%5,%6,%7}, {%8,%9}, {%0,%1,%2,%3};"
        : "+f"(c[0]), "+f"(c[1]), "+f"(c[2]), "+f"(c[3])
        : "r"(a[0]), "r"(a[1]), "r"(a[2]), "r"(a[3]), "r"(b[0]), "r"(b[1]));
}

__device__ __forceinline__ void cpasync16(uint32_t dst, const void* src) {
    asm volatile("cp.async.cg.shared.global [%0], [%1], 16;" :: "r"(dst), "l"(src));
}
#define CP_COMMIT()  asm volatile("cp.async.commit_group;" ::: "memory")
#define CP_WAIT0()   asm volatile("cp.async.wait_all;" ::: "memory")
#define CP_WAIT1()   asm volatile("cp.async.wait_group 1;" ::: "memory")

// ---------------------------------------------------------------------------
// cvt: tf32 pre-round + layout transform, one 128x32 tile per block.
//  A-fragment-major: tile = 32 atoms(am*4+ak) x 128 words; lane l's frag at
//    l*4 + j, with l=(r&7)*4+(c&3), j=(r>>3)+2*(c>>2)  [r=m&15, c=k&7]
//  B-fragment-major: tile = 64 atoms(bn*4+bk) x 64 words; word = l*2 + h,
//    l=(n&7)*4+(c&3), h=c>>2
//  blocks: 0..1023 dec(A) | 1024..2047 enc(A) | 2048..2303 Wq(B)
//          | 2304..2815 Wkv(B) | 2816..3071 Wout row-major copy
// ---------------------------------------------------------------------------
#define CVT_BLOCKS 3072

__global__ __launch_bounds__(256)
void cvt_frag_kernel(const float* __restrict__ dec, const float* __restrict__ enc,
                     const float* __restrict__ wq, const float* __restrict__ wkv,
                     const float* __restrict__ wout)
{
    __shared__ float tile[128 * 33];
    const int bid = blockIdx.x;
    const int tid = threadIdx.x;

    if (bid >= 2816) {
        // Wout: plain tf32-rounded copy (row-major) for the legacy W2 path
        long off = (long)(bid - 2816) * 4096 + tid * 4;
#pragma unroll
        for (int ii = 0; ii < 4; ii++) {
            float4 v = *(const float4*)&wout[off + ii * 1024];
            uint4 u = make_uint4(f2tf(v.x), f2tf(v.y), f2tf(v.z), f2tf(v.w));
            *(uint4*)&g_WoutT[off + ii * 1024] = u;
        }
        return;
    }

    const float* src;
    float* dst;
    int mt, kt;
    bool isA;
    if (bid < 1024)      { src = dec; dst = g_decA; mt = bid >> 5; kt = bid & 31; isA = true; }
    else if (bid < 2048) { src = enc; dst = g_encA; mt = (bid - 1024) >> 5; kt = bid & 31; isA = true; }
    else if (bid < 2304) { src = wq;  dst = g_WqB;  mt = (bid - 2048) >> 5; kt = bid & 31; isA = false; }
    else                 { src = wkv; dst = g_WkvB; mt = (bid - 2304) >> 5; kt = bid & 31; isA = false; }

    // stage 128x32 tile (rounded) into smem, coalesced
#pragma unroll
    for (int ii = 0; ii < 4; ii++) {
        int fidx = tid + ii * 256;
        int m = fidx >> 3, kq = (fidx & 7) * 4;
        float4 v = *(const float4*)&src[(size_t)(mt * 128 + m) * DIMN + kt * 32 + kq];
        float* d = &tile[m * 33 + kq];
        d[0] = __uint_as_float(f2tf(v.x));
        d[1] = __uint_as_float(f2tf(v.y));
        d[2] = __uint_as_float(f2tf(v.z));
        d[3] = __uint_as_float(f2tf(v.w));
    }
    __syncthreads();

    float* out = dst + (size_t)(mt * 32 + kt) * 4096;
    if (isA) {
#pragma unroll
        for (int ii = 0; ii < 4; ii++) {
            int cidx = tid + ii * 256;
            int l = cidx & 31, aidx = cidx >> 5;
            int am = aidx >> 2, ak = aidx & 3;
            int g = l >> 2, tt = l & 3;
            uint4 o;
            o.x = __float_as_uint(tile[(am * 16 + 0 + g) * 33 + ak * 8 + 0 + tt]);
            o.y = __float_as_uint(tile[(am * 16 + 8 + g) * 33 + ak * 8 + 0 + tt]);
            o.z = __float_as_uint(tile[(am * 16 + 0 + g) * 33 + ak * 8 + 4 + tt]);
            o.w = __float_as_uint(tile[(am * 16 + 8 + g) * 33 + ak * 8 + 4 + tt]);
            *(uint4*)&out[cidx * 4] = o;
        }
    } else {
#pragma unroll
        for (int ii = 0; ii < 4; ii++) {
            int cidx = tid + ii * 256;
            int aidx = cidx >> 4;               // 64 atoms
            int bn = aidx >> 2, bk = aidx & 3;
            int l0 = (cidx & 15) * 2;
            uint4 o;
#pragma unroll
            for (int e = 0; e < 4; e++) {
                int l = l0 + (e >> 1), h = e & 1;
                int n_loc = bn * 8 + (l >> 2);
                int k_loc = bk * 8 + h * 4 + (l & 3);
                ((unsigned*)&o)[e] = __float_as_uint(tile[n_loc * 33 + k_loc]);
            }
            *(uint4*)&out[cidx * 4] = o;
        }
    }
}

// ---------------------------------------------------------------------------
// Mask dtype detect (int32 vs byte)
// ---------------------------------------------------------------------------
__global__ void mask_detect_kernel(const unsigned char* __restrict__ m)
{
    __shared__ int found;
    if (threadIdx.x == 0) { found = 0; g_allTrue = 1; }
    __syncthreads();
    for (int i = threadIdx.x; i < 16384; i += blockDim.x)
        if ((i & 3) && m[i]) found = 1;
    __syncthreads();
    if (threadIdx.x == 0) g_isByte = found;
}

__global__ void mask_convert_kernel(const unsigned char* __restrict__ m, int n)
{
    int i = blockIdx.x * blockDim.x + threadIdx.x;
    int v = 1;
    if (i < n) {
        v = g_isByte ? (m[i] ? 1 : 0) : (((const unsigned*)m)[i] ? 1 : 0);
        g_mask8[i] = (unsigned char)v;
    }
    int all = __syncthreads_and(v);
    if (!all && threadIdx.x == 0) g_allTrue = 0;
}

// ---------------------------------------------------------------------------
// Legacy GEMM pieces (stride-36 layout) — used by W2 branch and final_gemm.
// ---------------------------------------------------------------------------
#define LDS_T 36
#define BUFW (128 * LDS_T)
#define GEMM_SMEM (6 * BUFW * 4)

__device__ __forceinline__ void issueTile(uint32_t Sb, const float* __restrict__ P,
                                          int ld, int kk, int tid) {
#pragma unroll
    for (int i = 0; i < 8; i++) {
        int f = tid + i * 128;
        int row = f >> 3, kq = (f & 7) * 4;
        cpasync16(Sb + (uint32_t)(row * LDS_T + kq) * 4, P + (size_t)row * ld + kk + kq);
    }
}

__device__ __forceinline__ void stageBT_raw(unsigned* Bs, const float* __restrict__ W,
                                            int n0, int kk, int ldn, int tid) {
#pragma unroll
    for (int i = 0; i < 8; i++) {
        int f = tid + i * 128;
        int kr = f >> 5, nq = (f & 31) * 4;
        uint4 v = *(const uint4*)&W[(size_t)(kk + kr) * ldn + n0 + nq];
        Bs[(nq + 0) * LDS_T + kr] = v.x;
        Bs[(nq + 1) * LDS_T + kr] = v.y;
        Bs[(nq + 2) * LDS_T + kr] = v.z;
        Bs[(nq + 3) * LDS_T + kr] = v.w;
    }
}

__device__ __forceinline__ void compute_tile(const unsigned* __restrict__ As,
                                             const unsigned* __restrict__ Bs,
                                             float c[4][8][4], int wm, int wn, int g, int t) {
#pragma unroll
    for (int ks = 0; ks < 4; ks++) {
        const int k8 = ks * 8;
        unsigned a[4][4];
#pragma unroll
        for (int mt = 0; mt < 4; mt++) {
            int r = wm * 64 + mt * 16;
            a[mt][0] = As[(r + g) * LDS_T + k8 + t];
            a[mt][1] = As[(r + 8 + g) * LDS_T + k8 + t];
            a[mt][2] = As[(r + g) * LDS_T + k8 + 4 + t];
            a[mt][3] = As[(r + 8 + g) * LDS_T + k8 + 4 + t];
        }
#pragma unroll
        for (int nt = 0; nt < 8; nt++) {
            int cx = wn * 64 + nt * 8;
            unsigned bf[2];
            bf[0] = Bs[(cx + g) * LDS_T + k8 + t];
            bf[1] = Bs[(cx + g) * LDS_T + k8 + 4 + t];
#pragma unroll
            for (int mt = 0; mt < 4; mt++)
                mma_tf32(c[mt][nt], a[mt], bf);
        }
    }
}

__device__ __forceinline__ void pipe_loop(uint32_t shb, const float* __restrict__ Ap,
                                          const float* __restrict__ Wp, int K,
                                          unsigned* sh, float c[4][8][4],
                                          int wm, int wn, int g, int t, int tid)
{
    const int NIT = K / 32;
    issueTile(shb,                Ap, K, 0, tid);
    issueTile(shb + BUFW * 4,     Wp, K, 0, tid);
    CP_COMMIT();
    issueTile(shb + 2 * BUFW * 4, Ap, K, 32, tid);
    issueTile(shb + 3 * BUFW * 4, Wp, K, 32, tid);
    CP_COMMIT();

    int cur = 0;
    for (int kt = 0; kt < NIT; kt++) {
        if (kt + 1 < NIT) { CP_WAIT1(); } else { CP_WAIT0(); }
        __syncthreads();
        if (kt + 2 < NIT) {
            int nb = cur + 2; if (nb >= 3) nb -= 3;
            uint32_t base = shb + (uint32_t)(nb * 2 * BUFW) * 4;
            issueTile(base,            Ap, K, (kt + 2) * 32, tid);
            issueTile(base + BUFW * 4, Wp, K, (kt + 2) * 32, tid);
            CP_COMMIT();
        }
        compute_tile(sh + cur * 2 * BUFW, sh + cur * 2 * BUFW + BUFW, c, wm, wn, g, t);
        cur = (cur == 2) ? 0 : cur + 1;
    }
}

// ---------------------------------------------------------------------------
// Fragment-major GEMM core (proj): linear cp.async staging (4096+4096 words
// per stage), LDS.128 A-frags + LDS.64 B-frags (both conflict-free).
// ---------------------------------------------------------------------------
#define FBUF 8192                 // words per stage (A 4096 + B 4096)
#define PROJ_SMEM (3 * FBUF * 4)  // 98304 B -> 2 CTAs/SM

__device__ __forceinline__ void issueFrag(uint32_t Sb, const float* __restrict__ P, int tid) {
#pragma unroll
    for (int i = 0; i < 8; i++) {
        int cch = tid + i * 128;
        cpasync16(Sb + (uint32_t)cch * 16, P + cch * 4);
    }
}

__device__ __forceinline__ void compute_tile_frag(const unsigned* __restrict__ As,
                                                  const unsigned* __restrict__ Bs,
                                                  float c[4][8][4], int wm, int wn, int lane) {
#pragma unroll
    for (int ks = 0; ks < 4; ks++) {
        unsigned a[4][4];
#pragma unroll
        for (int mt = 0; mt < 4; mt++) {
            uint4 av = *(const uint4*)&As[(((wm * 4 + mt) * 4 + ks) << 7) + lane * 4];
            a[mt][0] = av.x; a[mt][1] = av.y; a[mt][2] = av.z; a[mt][3] = av.w;
        }
#pragma unroll
        for (int nt = 0; nt < 8; nt++) {
            uint2 bv = *(const uint2*)&Bs[(((wn * 8 + nt) * 4 + ks) << 6) + lane * 2];
            unsigned bf[2] = { bv.x, bv.y };
#pragma unroll
            for (int mt = 0; mt < 4; mt++)
                mma_tf32(c[mt][nt], a[mt], bf);
        }
    }
}

// ---------------------------------------------------------------------------
// Final GEMM: legacy path (A=g_vals, W=g_W2, both row-major pre-rounded)
// ---------------------------------------------------------------------------
__global__ __launch_bounds__(128, 2)
void final_gemm(const float* __restrict__ A, const float* __restrict__ W,
                float* __restrict__ C, int M, int N, int K)
{
    extern __shared__ unsigned sh[];
    uint32_t shb = (uint32_t)__cvta_generic_to_shared(sh);
    const int tid = threadIdx.x;
    const int m0 = blockIdx.y * 128, n0 = blockIdx.x * 128;
    const int warp = tid >> 5, lane = tid & 31;
    const int wm = warp & 1, wn = warp >> 1;
    const int g = lane >> 2, t = lane & 3;

    float c[4][8][4];
#pragma unroll
    for (int mt = 0; mt < 4; mt++)
#pragma unroll
        for (int nt = 0; nt < 8; nt++)
#pragma unroll
            for (int i = 0; i < 4; i++) c[mt][nt][i] = 0.f;

    pipe_loop(shb, A + (size_t)m0 * K, W + (size_t)n0 * K, K, sh, c, wm, wn, g, t, tid);

#pragma unroll
    for (int mt = 0; mt < 4; mt++) {
        int r0 = m0 + wm * 64 + mt * 16 + g;
        int r1 = r0 + 8;
#pragma unroll
        for (int nt = 0; nt < 8; nt++) {
            int col = n0 + wn * 64 + nt * 8 + 2 * t;
            *(float2*)&C[(size_t)r0 * N + col] = make_float2(c[mt][nt][0], c[mt][nt][1]);
            *(float2*)&C[(size_t)r1 * N + col] = make_float2(c[mt][nt][2], c[mt][nt][3]);
        }
    }
}

// ---------------------------------------------------------------------------
// Merged projections (fragment-major fast path) + W2 (legacy path).
//  bid < 768 : proj tile (bx = bid%24: 0..7 Q, 8..23 KV; by = bid/24)
//  bid >= 768: W2 tile (8x8), legacy stride-36 staging from g_WoutT
// ---------------------------------------------------------------------------
__global__ __launch_bounds__(128, 2)
void proj_w2_gemm()
{
    extern __shared__ unsigned sh[];
    uint32_t shb = (uint32_t)__cvta_generic_to_shared(sh);
    const int tid = threadIdx.x;
    const int bid = blockIdx.x;
    const int warp = tid >> 5, lane = tid & 31;
    const int wm = warp & 1, wn = warp >> 1;
    const int g = lane >> 2, t = lane & 3;
    const int K = DIMN;

    float c[4][8][4];
#pragma unroll
    for (int mt = 0; mt < 4; mt++)
#pragma unroll
        for (int nt = 0; nt < 8; nt++)
#pragma unroll
            for (int i = 0; i < 4; i++) c[mt][nt][i] = 0.f;

    if (bid >= 768) {
        // ---- W2 = Wout @ Wout (legacy) ----
        const int w = bid - 768;
        const int m0 = (w >> 3) * 128, n0 = (w & 7) * 128;
        unsigned* As = sh;
        unsigned* Bs = sh + BUFW;
        for (int kk = 0; kk < K; kk += 32) {
            issueTile(shb, g_WoutT + (size_t)m0 * K, K, kk, tid);
            CP_COMMIT();
            stageBT_raw(Bs, g_WoutT, n0, kk, DIMN, tid);
            CP_WAIT0();
            __syncthreads();
            compute_tile(As, Bs, c, wm, wn, g, t);
            __syncthreads();
        }
#pragma unroll
        for (int mt = 0; mt < 4; mt++) {
            int r0 = m0 + wm * 64 + mt * 16 + g;
            int r1 = r0 + 8;
#pragma unroll
            for (int nt = 0; nt < 8; nt++) {
                int col = n0 + wn * 64 + nt * 8 + 2 * t;
                uint2 v0 = make_uint2(f2tf(c[mt][nt][0]), f2tf(c[mt][nt][1]));
                uint2 v1 = make_uint2(f2tf(c[mt][nt][2]), f2tf(c[mt][nt][3]));
                *(uint2*)&g_W2[(size_t)r0 * DIMN + col] = v0;
                *(uint2*)&g_W2[(size_t)r1 * DIMN + col] = v1;
            }
        }
        return;
    }

    // ---- projections: fragment-major pipeline ----
    const int bx = bid % 24, by = bid / 24;
    const bool isQ = bx < 8;
    const float* Abase = (isQ ? g_decA : g_encA) + (size_t)by * 32 * 4096;
    const float* Bbase = (isQ ? g_WqB : g_WkvB) + (size_t)(isQ ? bx : (bx - 8)) * 32 * 4096;
    const int n0 = (isQ ? bx : (bx - 8)) * 128;
    const int m0 = by * 128;
    const int NIT = 32;

    issueFrag(shb,                 Abase, tid);
    issueFrag(shb + 4096 * 4,      Bbase, tid);
    CP_COMMIT();
    issueFrag(shb + FBUF * 4,            Abase + 4096, tid);
    issueFrag(shb + FBUF * 4 + 4096 * 4, Bbase + 4096, tid);
    CP_COMMIT();

    int cur = 0;
    for (int kt = 0; kt < NIT; kt++) {
        if (kt + 1 < NIT) { CP_WAIT1(); } else { CP_WAIT0(); }
        __syncthreads();
        if (kt + 2 < NIT) {
            int nb = cur + 2; if (nb >= 3) nb -= 3;
            uint32_t base = shb + (uint32_t)(nb * FBUF) * 4;
            issueFrag(base,            Abase + (size_t)(kt + 2) * 4096, tid);
            issueFrag(base + 4096 * 4, Bbase + (size_t)(kt + 2) * 4096, tid);
            CP_COMMIT();
        }
        compute_tile_frag(sh + cur * FBUF, sh + cur * FBUF + 4096, c, wm, wn, lane);
        cur = (cur == 2) ? 0 : cur + 1;
    }

    // scatter epilogue (unchanged)
#pragma unroll
    for (int mt = 0; mt < 4; mt++) {
        int r0 = wm * 64 + mt * 16 + g;
        int r1 = r0 + 8;
#pragma unroll
        for (int nt = 0; nt < 8; nt++) {
            int col = n0 + wn * 64 + nt * 8 + 2 * t;
#pragma unroll
            for (int e = 0; e < 4; e++) {
                int m = m0 + ((e < 2) ? r0 : r1);
                int n = col + (e & 1);
                float v = c[mt][nt][e];
                int b = m >> 10, q = m & 1023;
                if (isQ) {
                    int h = n & 15, d = n >> 4;
                    g_Qh[(((size_t)(b * NH + h) * QL + q) * DK) + d] =
                        __uint_as_float(f2tf(v * 0.125f));
                } else if (n < DIMN) {
                    int h = n & 15, d = n >> 4;
                    g_Kh[(((size_t)(b * NH + h) * KL + q) * DK) + d] =
                        __uint_as_float(f2tf(v));
                } else {
                    int nn = n - DIMN;
                    int h = nn & 15, d = nn >> 4;
                    g_Vh[(((size_t)(b * NH + h) * KL + q) * DK) + d] =
                        __uint_as_float(f2tf(v));
                }
            }
        }
    }
}

// ---------------------------------------------------------------------------
// Fused attention, cp.async edition (unchanged from R10-R12 passing runs).
// ---------------------------------------------------------------------------
#define ATT_LD 68
#define VLD 72
#define AQOFF 0
#define AKOFF(buf) (4352 + (buf) * 4352)
#define AVOFF(buf) (13056 + (buf) * 4608)
#define APSOFF 22272
#define ATT_SMEM (26624 * 4)

__device__ __forceinline__ void att_issue68(uint32_t shb, int woff,
                                            const float* __restrict__ src, int tid) {
#pragma unroll
    for (int i = 0; i < 8; i++) {
        int cch = tid + i * 128;
        int row = cch >> 4, c16 = cch & 15;
        cpasync16(shb + (uint32_t)(woff + row * ATT_LD + c16 * 4) * 4,
                  src + (size_t)row * DK + c16 * 4);
    }
}
__device__ __forceinline__ void att_issue72(uint32_t shb, int woff,
                                            const float* __restrict__ src, int tid) {
#pragma unroll
    for (int i = 0; i < 8; i++) {
        int cch = tid + i * 128;
        int row = cch >> 4, c16 = cch & 15;
        cpasync16(shb + (uint32_t)(woff + row * VLD + c16 * 4) * 4,
                  src + (size_t)row * DK + c16 * 4);
    }
}

__global__ __launch_bounds__(128, 2)
void attn_kernel()
{
    extern __shared__ unsigned smU[];
    uint32_t shb = (uint32_t)__cvta_generic_to_shared(smU);
    unsigned* Qs = smU + AQOFF;
    unsigned* Ps = smU + APSOFF;

    const int head = blockIdx.y;
    const int b = head >> 4, h = head & 15;
    const int q0 = blockIdx.x * 64;
    const int tid = threadIdx.x;
    const int w = tid >> 5, lane = tid & 31;
    const int g = lane >> 2, t = lane & 3;
    const int wq0 = w * 16;
    const int allTrue = g_allTrue;

    const float* Qp = g_Qh + (size_t)head * QL * DK;
    const float* Kp = g_Kh + (size_t)head * KL * DK;
    const float* Vp = g_Vh + (size_t)head * KL * DK;

    att_issue68(shb, AQOFF, Qp + (size_t)q0 * DK, tid);
    att_issue68(shb, AKOFF(0), Kp, tid);
    att_issue72(shb, AVOFF(0), Vp, tid);
    CP_COMMIT();

    float o[8][4];
#pragma unroll
    for (int nt = 0; nt < 8; nt++)
#pragma unroll
        for (int i = 0; i < 4; i++) o[nt][i] = 0.f;
    float l0 = 0.f, l1 = 0.f;

    const int NKT = KL / 64;  // 16
    for (int kt = 0; kt < NKT; kt++) {
        CP_WAIT0();
        __syncthreads();
        const int cur = kt & 1;
        if (kt + 1 < NKT) {
            att_issue68(shb, AKOFF(cur ^ 1), Kp + (size_t)(kt + 1) * 64 * DK, tid);
            att_issue72(shb, AVOFF(cur ^ 1), Vp + (size_t)(kt + 1) * 64 * DK, tid);
            CP_COMMIT();
        }
        const unsigned* Kc = smU + AKOFF(cur);
        const unsigned* Vc = smU + AVOFF(cur);

        float s[8][4];
#pragma unroll
        for (int nt = 0; nt < 8; nt++)
#pragma unroll
            for (int i = 0; i < 4; i++) s[nt][i] = 0.f;

#pragma unroll
        for (int ks = 0; ks < 8; ks++) {
            const int k8 = ks * 8;
            unsigned a[4];
            a[0] = Qs[(wq0 + g) * ATT_LD + k8 + t];
            a[1] = Qs[(wq0 + 8 + g) * ATT_LD + k8 + t];
            a[2] = Qs[(wq0 + g) * ATT_LD + k8 + 4 + t];
            a[3] = Qs[(wq0 + 8 + g) * ATT_LD + k8 + 4 + t];
#pragma unroll
            for (int nt = 0; nt < 8; nt++) {
                unsigned bf[2];
                bf[0] = Kc[(nt * 8 + g) * ATT_LD + k8 + t];
                bf[1] = Kc[(nt * 8 + g) * ATT_LD + k8 + 4 + t];
                mma_tf32(s[nt], a, bf);
            }
        }

        int qr0 = wq0 + g, qr1 = wq0 + 8 + g;
        const unsigned char* m0p = g_mask8 + ((size_t)(b * QL + q0 + qr0)) * KL + kt * 64;
        const unsigned char* m1p = g_mask8 + ((size_t)(b * QL + q0 + qr1)) * KL + kt * 64;
        float rs0 = 0.f, rs1 = 0.f;
#pragma unroll
        for (int nt = 0; nt < 8; nt++) {
            int kc = nt * 8 + 2 * t;
            float p00, p01, p10, p11;
            if (allTrue) {
                p00 = __expf(s[nt][0]); p01 = __expf(s[nt][1]);
                p10 = __expf(s[nt][2]); p11 = __expf(s[nt][3]);
            } else {
                p00 = m0p[kc]     ? __expf(s[nt][0]) : 0.f;
                p01 = m0p[kc + 1] ? __expf(s[nt][1]) : 0.f;
                p10 = m1p[kc]     ? __expf(s[nt][2]) : 0.f;
                p11 = m1p[kc + 1] ? __expf(s[nt][3]) : 0.f;
            }
            rs0 += p00 + p01;
            rs1 += p10 + p11;
            *(uint2*)&Ps[qr0 * ATT_LD + kc] = make_uint2(f2tf(p00), f2tf(p01));
            *(uint2*)&Ps[qr1 * ATT_LD + kc] = make_uint2(f2tf(p10), f2tf(p11));
        }
        rs0 += __shfl_xor_sync(0xffffffffu, rs0, 1);
        rs0 += __shfl_xor_sync(0xffffffffu, rs0, 2);
        rs1 += __shfl_xor_sync(0xffffffffu, rs1, 1);
        rs1 += __shfl_xor_sync(0xffffffffu, rs1, 2);
        l0 += rs0;
        l1 += rs1;
        __syncwarp();

#pragma unroll
        for (int ks = 0; ks < 8; ks++) {
            const int k8 = ks * 8;
            unsigned a[4];
            a[0] = Ps[(wq0 + g) * ATT_LD + k8 + t];
            a[1] = Ps[(wq0 + 8 + g) * ATT_LD + k8 + t];
            a[2] = Ps[(wq0 + g) * ATT_LD + k8 + 4 + t];
            a[3] = Ps[(wq0 + 8 + g) * ATT_LD + k8 + 4 + t];
#pragma unroll
            for (int nt = 0; nt < 8; nt++) {
                unsigned bf[2];
                bf[0] = Vc[(k8 + t) * VLD + nt * 8 + g];
                bf[1] = Vc[(k8 + 4 + t) * VLD + nt * 8 + g];
                mma_tf32(o[nt], a, bf);
            }
        }
    }

    float inv0 = 1.f / l0, inv1 = 1.f / l1;
    int qa = q0 + wq0 + g, qb = qa + 8;
#pragma unroll
    for (int nt = 0; nt < 8; nt++) {
        int d = nt * 8 + 2 * t;
        float* base0 = &g_vals[((size_t)(b * QL + qa)) * DIMN + d * NH + h];
        float* base1 = &g_vals[((size_t)(b * QL + qb)) * DIMN + d * NH + h];
        base0[0]  = __uint_as_float(f2tf(o[nt][0] * inv0));
        base0[NH] = __uint_as_float(f2tf(o[nt][1] * inv0));
        base1[0]  = __uint_as_float(f2tf(o[nt][2] * inv1));
        base1[NH] = __uint_as_float(f2tf(o[nt][3] * inv1));
    }
}

// ---------------------------------------------------------------------------
extern "C" void kernel_launch(void* const* d_in, const int* in_sizes, int n_in,
                              void* d_out, int out_size)
{
    const float* dec  = (const float*)d_in[0];
    const float* enc  = (const float*)d_in[1];
    const unsigned char* mask = (const unsigned char*)d_in[2];
    const float* Wq   = (const float*)d_in[3];
    const float* Wkv  = (const float*)d_in[4];
    const float* Wout = (const float*)d_in[5];
    float* out = (float*)d_out;

    float *vals_p, *w2_p;
    cudaGetSymbolAddress((void**)&vals_p, g_vals);
    cudaGetSymbolAddress((void**)&w2_p, g_W2);

    cudaFuncSetAttribute(final_gemm,   cudaFuncAttributeMaxDynamicSharedMemorySize, GEMM_SMEM);
    cudaFuncSetAttribute(proj_w2_gemm, cudaFuncAttributeMaxDynamicSharedMemorySize, PROJ_SMEM);
    cudaFuncSetAttribute(attn_kernel,  cudaFuncAttributeMaxDynamicSharedMemorySize, ATT_SMEM);

    const int M = BATCH * QL; // 4096
    const int NMASK = BATCH * QL * KL;
    dim3 blk(128);

    mask_detect_kernel<<<1, 256>>>(mask);
    mask_convert_kernel<<<(NMASK + 255) / 256, 256>>>(mask, NMASK);

    // tf32 pre-round + fragment-major layout transform
    cvt_frag_kernel<<<CVT_BLOCKS, 256>>>(dec, enc, Wq, Wkv, Wout);

    // merged Q + KV projections (frag-major) + W2 (legacy) in one wave
    proj_w2_gemm<<<dim3(832), blk, PROJ_SMEM>>>();
    // fused attention -> g_vals (pre-rounded)
    attn_kernel<<<dim3(QL / 64, BATCH * NH), dim3(128), ATT_SMEM>>>();
    // out = vals @ W2^T (legacy)
    final_gemm<<<dim3(8, M / 128), blk, GEMM_SMEM>>>(vals_p, w2_p, out, M, DIMN, DIMN);
}

// round 14
// speedup vs baseline: 1.7051x; 1.1510x over previous
#include <cuda_runtime.h>
#include <cstddef>
#include <cstdint>

#define DIMN 1024
#define NH   16
#define DK   64
#define BATCH 4
#define QL   1024
#define KL   1024

// Scratch (device globals). All operand tensors live in FRAGMENT-MAJOR tf32
// layouts so GEMM/attention staging is a linear cp.async and frag loads are
// LDS.128/LDS.64.
__device__ float g_Qh[BATCH*NH*QL*DK];   // per head: qtile64 A-frag tiles
__device__ float g_Kh[BATCH*NH*KL*DK];   // per head: ktile64 B-frag (n=key,k=d)
__device__ float g_Vh[BATCH*NH*KL*DK];   // per head: ktile64 B-frag (n=d,k=key)
__device__ float g_valsA[BATCH*QL*DIMN]; // attn out, A-frag of [4096,1024]
__device__ float g_W2B[DIMN*DIMN];       // Wout@Wout, B-frag
__device__ float g_decA[BATCH*QL*DIMN];  // dec, A-frag
__device__ float g_encA[BATCH*KL*DIMN];  // enc, A-frag
__device__ float g_WqB[DIMN*DIMN];       // Wq, B-frag
__device__ float g_WkvB[2*DIMN*DIMN];    // Wkv, B-frag
__device__ float g_WoutA[DIMN*DIMN];     // Wout, A-frag      (W2 A operand)
__device__ float g_WoutB[DIMN*DIMN];     // Wout^T, B-frag    (W2 B operand)
__device__ unsigned char g_mask8[BATCH*QL*KL];
__device__ int g_isByte;
__device__ int g_allTrue;

// ---------------------------------------------------------------------------
__device__ __forceinline__ unsigned f2tf(float x) {
    unsigned r;
    asm("cvt.rna.tf32.f32 %0, %1;" : "=r"(r) : "f"(x));
    return r;
}

__device__ __forceinline__ void mma_tf32(float c[4], const unsigned a[4], const unsigned b[2]) {
    asm("mma.sync.aligned.m16n8k8.row.col.f32.tf32.tf32.f32 "
        "{%0,%1,%2,%3}, {%4,%5,%6,%7}, {%8,%9}, {%0,%1,%2,%3};"
        : "+f"(c[0]), "+f"(c[1]), "+f"(c[2]), "+f"(c[3])
        : "r"(a[0]), "r"(a[1]), "r"(a[2]), "r"(a[3]), "r"(b[0]), "r"(b[1]));
}

__device__ __forceinline__ void cpasync16(uint32_t dst, const void* src) {
    asm volatile("cp.async.cg.shared.global [%0], [%1], 16;" :: "r"(dst), "l"(src));
}
#define CP_COMMIT()  asm volatile("cp.async.commit_group;" ::: "memory")
#define CP_WAIT0()   asm volatile("cp.async.wait_all;" ::: "memory")
#define CP_WAIT1()   asm volatile("cp.async.wait_group 1;" ::: "memory")

// ---------------------------------------------------------------------------
// cvt: tf32 pre-round + fragment-major transforms, one 128x32 (or 32x128)
// tile per block.
//  A-frag (GEMM): atoms(am*4+ak)x128 words; l=(r&7)*4+(c&3), j=(r>>3)+2*(c>>2)
//  B-frag (GEMM): atoms(bn*4+bk)x64 words; l=(n&7)*4+(k&3), h=(k>>2)&1
// blocks: 0..1023 dec(A) | 1024..2047 enc(A) | 2048..2303 Wq(B)
//         | 2304..2815 Wkv(B) | 2816..3071 WoutA(A) | 3072..3327 WoutB(B^T)
// ---------------------------------------------------------------------------
#define CVT_BLOCKS 3328

__global__ __launch_bounds__(256)
void cvt_frag_kernel(const float* __restrict__ dec, const float* __restrict__ enc,
                     const float* __restrict__ wq, const float* __restrict__ wkv,
                     const float* __restrict__ wout)
{
    __shared__ float tile[128 * 33];  // also used as [32][132]
    const int bid = blockIdx.x;
    const int tid = threadIdx.x;

    if (bid >= 3072) {
        // WoutB: B-frag of Wout^T. B[n][k] = Wout[k][n].
        int idx = bid - 3072;
        int mt = idx >> 5, kt = idx & 31;
#pragma unroll
        for (int ii = 0; ii < 4; ii++) {
            int fidx = tid + ii * 256;
            int kr = fidx >> 5, nq = (fidx & 31) * 4;
            float4 v = *(const float4*)&wout[(size_t)(kt * 32 + kr) * DIMN + mt * 128 + nq];
            float* d = &tile[kr * 132 + nq];
            d[0] = __uint_as_float(f2tf(v.x));
            d[1] = __uint_as_float(f2tf(v.y));
            d[2] = __uint_as_float(f2tf(v.z));
            d[3] = __uint_as_float(f2tf(v.w));
        }
        __syncthreads();
        float* outp = g_WoutB + (size_t)(mt * 32 + kt) * 4096;
#pragma unroll
        for (int ii = 0; ii < 4; ii++) {
            int cidx = tid + ii * 256;
            int aidx = cidx >> 4;
            int bn = aidx >> 2, bk = aidx & 3;
            int l0 = (cidx & 15) * 2;
            uint4 o;
#pragma unroll
            for (int e = 0; e < 4; e++) {
                int l = l0 + (e >> 1), h = e & 1;
                int n_loc = bn * 8 + (l >> 2);
                int k_loc = bk * 8 + h * 4 + (l & 3);
                ((unsigned*)&o)[e] = __float_as_uint(tile[k_loc * 132 + n_loc]);
            }
            *(uint4*)&outp[cidx * 4] = o;
        }
        return;
    }

    const float* src;
    float* dst;
    int mt, kt;
    bool isA;
    if (bid < 1024)      { src = dec;  dst = g_decA;  mt = bid >> 5;          kt = bid & 31; isA = true; }
    else if (bid < 2048) { src = enc;  dst = g_encA;  mt = (bid - 1024) >> 5; kt = bid & 31; isA = true; }
    else if (bid < 2304) { src = wq;   dst = g_WqB;   mt = (bid - 2048) >> 5; kt = bid & 31; isA = false; }
    else if (bid < 2816) { src = wkv;  dst = g_WkvB;  mt = (bid - 2304) >> 5; kt = bid & 31; isA = false; }
    else                 { src = wout; dst = g_WoutA; mt = (bid - 2816) >> 5; kt = bid & 31; isA = true; }

#pragma unroll
    for (int ii = 0; ii < 4; ii++) {
        int fidx = tid + ii * 256;
        int m = fidx >> 3, kq = (fidx & 7) * 4;
        float4 v = *(const float4*)&src[(size_t)(mt * 128 + m) * DIMN + kt * 32 + kq];
        float* d = &tile[m * 33 + kq];
        d[0] = __uint_as_float(f2tf(v.x));
        d[1] = __uint_as_float(f2tf(v.y));
        d[2] = __uint_as_float(f2tf(v.z));
        d[3] = __uint_as_float(f2tf(v.w));
    }
    __syncthreads();

    float* out = dst + (size_t)(mt * 32 + kt) * 4096;
    if (isA) {
#pragma unroll
        for (int ii = 0; ii < 4; ii++) {
            int cidx = tid + ii * 256;
            int l = cidx & 31, aidx = cidx >> 5;
            int am = aidx >> 2, ak = aidx & 3;
            int g = l >> 2, tt = l & 3;
            uint4 o;
            o.x = __float_as_uint(tile[(am * 16 + 0 + g) * 33 + ak * 8 + 0 + tt]);
            o.y = __float_as_uint(tile[(am * 16 + 8 + g) * 33 + ak * 8 + 0 + tt]);
            o.z = __float_as_uint(tile[(am * 16 + 0 + g) * 33 + ak * 8 + 4 + tt]);
            o.w = __float_as_uint(tile[(am * 16 + 8 + g) * 33 + ak * 8 + 4 + tt]);
            *(uint4*)&out[cidx * 4] = o;
        }
    } else {
#pragma unroll
        for (int ii = 0; ii < 4; ii++) {
            int cidx = tid + ii * 256;
            int aidx = cidx >> 4;
            int bn = aidx >> 2, bk = aidx & 3;
            int l0 = (cidx & 15) * 2;
            uint4 o;
#pragma unroll
            for (int e = 0; e < 4; e++) {
                int l = l0 + (e >> 1), h = e & 1;
                int n_loc = bn * 8 + (l >> 2);
                int k_loc = bk * 8 + h * 4 + (l & 3);
                ((unsigned*)&o)[e] = __float_as_uint(tile[n_loc * 33 + k_loc]);
            }
            *(uint4*)&out[cidx * 4] = o;
        }
    }
}

// ---------------------------------------------------------------------------
// Mask dtype detect (int32 vs byte)
// ---------------------------------------------------------------------------
__global__ void mask_detect_kernel(const unsigned char* __restrict__ m)
{
    __shared__ int found;
    if (threadIdx.x == 0) { found = 0; g_allTrue = 1; }
    __syncthreads();
    for (int i = threadIdx.x; i < 16384; i += blockDim.x)
        if ((i & 3) && m[i]) found = 1;
    __syncthreads();
    if (threadIdx.x == 0) g_isByte = found;
}

__global__ void mask_convert_kernel(const unsigned char* __restrict__ m, int n)
{
    int i = blockIdx.x * blockDim.x + threadIdx.x;
    int v = 1;
    if (i < n) {
        v = g_isByte ? (m[i] ? 1 : 0) : (((const unsigned*)m)[i] ? 1 : 0);
        g_mask8[i] = (unsigned char)v;
    }
    int all = __syncthreads_and(v);
    if (!all && threadIdx.x == 0) g_allTrue = 0;
}

// ---------------------------------------------------------------------------
// Fragment-major GEMM core: BM=BN=128, BK=32, 128 threads = 4 warps (2Mx2N),
// warp 64x64. Linear cp.async staging, LDS.128 A + LDS.64 B frags.
// 3-stage pipeline, wait_group 1, one __syncthreads per iteration.
// ---------------------------------------------------------------------------
#define FBUF 8192                 // words per stage (A 4096 + B 4096)
#define FRAG_SMEM (3 * FBUF * 4)  // 98304 B -> 2 CTAs/SM

__device__ __forceinline__ void issueFrag(uint32_t Sb, const float* __restrict__ P, int tid) {
#pragma unroll
    for (int i = 0; i < 8; i++) {
        int cch = tid + i * 128;
        cpasync16(Sb + (uint32_t)cch * 16, P + cch * 4);
    }
}

__device__ __forceinline__ void compute_tile_frag(const unsigned* __restrict__ As,
                                                  const unsigned* __restrict__ Bs,
                                                  float c[4][8][4], int wm, int wn, int lane) {
#pragma unroll
    for (int ks = 0; ks < 4; ks++) {
        unsigned a[4][4];
#pragma unroll
        for (int mt = 0; mt < 4; mt++) {
            uint4 av = *(const uint4*)&As[(((wm * 4 + mt) * 4 + ks) << 7) + lane * 4];
            a[mt][0] = av.x; a[mt][1] = av.y; a[mt][2] = av.z; a[mt][3] = av.w;
        }
#pragma unroll
        for (int nt = 0; nt < 8; nt++) {
            uint2 bv = *(const uint2*)&Bs[(((wn * 8 + nt) * 4 + ks) << 6) + lane * 2];
            unsigned bf[2] = { bv.x, bv.y };
#pragma unroll
            for (int mt = 0; mt < 4; mt++)
                mma_tf32(c[mt][nt], a[mt], bf);
        }
    }
}

__device__ __forceinline__ void pipe_frag(uint32_t shb, unsigned* sh,
                                          const float* __restrict__ Abase,
                                          const float* __restrict__ Bbase,
                                          float c[4][8][4], int wm, int wn,
                                          int lane, int tid)
{
    const int NIT = 32;
    issueFrag(shb,            Abase, tid);
    issueFrag(shb + 4096 * 4, Bbase, tid);
    CP_COMMIT();
    issueFrag(shb + FBUF * 4,            Abase + 4096, tid);
    issueFrag(shb + FBUF * 4 + 4096 * 4, Bbase + 4096, tid);
    CP_COMMIT();

    int cur = 0;
    for (int kt = 0; kt < NIT; kt++) {
        if (kt + 1 < NIT) { CP_WAIT1(); } else { CP_WAIT0(); }
        __syncthreads();
        if (kt + 2 < NIT) {
            int nb = cur + 2; if (nb >= 3) nb -= 3;
            uint32_t base = shb + (uint32_t)(nb * FBUF) * 4;
            issueFrag(base,            Abase + (size_t)(kt + 2) * 4096, tid);
            issueFrag(base + 4096 * 4, Bbase + (size_t)(kt + 2) * 4096, tid);
            CP_COMMIT();
        }
        compute_tile_frag(sh + cur * FBUF, sh + cur * FBUF + 4096, c, wm, wn, lane);
        cur = (cur == 2) ? 0 : cur + 1;
    }
}

// ---------------------------------------------------------------------------
// Final GEMM: out = vals @ W2^T  (A = g_valsA frag, B = g_W2B frag)
// ---------------------------------------------------------------------------
__global__ __launch_bounds__(128, 2)
void final_gemm(float* __restrict__ C)
{
    extern __shared__ unsigned sh[];
    uint32_t shb = (uint32_t)__cvta_generic_to_shared(sh);
    const int tid = threadIdx.x;
    const int m0 = blockIdx.y * 128, n0 = blockIdx.x * 128;
    const int warp = tid >> 5, lane = tid & 31;
    const int wm = warp & 1, wn = warp >> 1;
    const int g = lane >> 2, t = lane & 3;

    float c[4][8][4];
#pragma unroll
    for (int mt = 0; mt < 4; mt++)
#pragma unroll
        for (int nt = 0; nt < 8; nt++)
#pragma unroll
            for (int i = 0; i < 4; i++) c[mt][nt][i] = 0.f;

    pipe_frag(shb, sh, g_valsA + (size_t)blockIdx.y * 32 * 4096,
              g_W2B + (size_t)blockIdx.x * 32 * 4096, c, wm, wn, lane, tid);

#pragma unroll
    for (int mt = 0; mt < 4; mt++) {
        int r0 = m0 + wm * 64 + mt * 16 + g;
        int r1 = r0 + 8;
#pragma unroll
        for (int nt = 0; nt < 8; nt++) {
            int col = n0 + wn * 64 + nt * 8 + 2 * t;
            *(float2*)&C[(size_t)r0 * DIMN + col] = make_float2(c[mt][nt][0], c[mt][nt][1]);
            *(float2*)&C[(size_t)r1 * DIMN + col] = make_float2(c[mt][nt][2], c[mt][nt][3]);
        }
    }
}

// ---------------------------------------------------------------------------
// Merged projections + W2, all on the frag pipeline.
//  bid < 768 : proj tile (bx = bid%24: 0..7 Q, 8..23 KV; by = bid/24)
//              epilogue scatters into ATTENTION frag layouts (Qh/Kh/Vh)
//  bid >= 768: W2 tile (8x8); A=g_WoutA, B=g_WoutB; epilogue -> g_W2B
// ---------------------------------------------------------------------------
__global__ __launch_bounds__(128, 2)
void proj_w2_gemm()
{
    extern __shared__ unsigned sh[];
    uint32_t shb = (uint32_t)__cvta_generic_to_shared(sh);
    const int tid = threadIdx.x;
    const int bid = blockIdx.x;
    const int warp = tid >> 5, lane = tid & 31;
    const int wm = warp & 1, wn = warp >> 1;
    const int g = lane >> 2, t = lane & 3;

    float c[4][8][4];
#pragma unroll
    for (int mt = 0; mt < 4; mt++)
#pragma unroll
        for (int nt = 0; nt < 8; nt++)
#pragma unroll
            for (int i = 0; i < 4; i++) c[mt][nt][i] = 0.f;

    if (bid >= 768) {
        // ---- W2 = Wout @ Wout ----
        const int w = bid - 768;
        const int m0 = (w >> 3) * 128, n0 = (w & 7) * 128;
        pipe_frag(shb, sh, g_WoutA + (size_t)(w >> 3) * 32 * 4096,
                  g_WoutB + (size_t)(w & 7) * 32 * 4096, c, wm, wn, lane, tid);
        unsigned* W2u = (unsigned*)g_W2B;
#pragma unroll
        for (int mt = 0; mt < 4; mt++) {
            int r0 = m0 + wm * 64 + mt * 16 + g;
#pragma unroll
            for (int nt = 0; nt < 8; nt++) {
                int col = n0 + wn * 64 + nt * 8 + 2 * t;
#pragma unroll
                for (int e = 0; e < 4; e++) {
                    int r = (e < 2) ? r0 : (r0 + 8);
                    int cc = col + (e & 1);
                    int nt2 = r >> 7, kt2 = cc >> 5;
                    int bn = (r >> 3) & 15, bk = (cc >> 3) & 3;
                    int l = (r & 7) * 4 + (cc & 3);
                    int hb = (cc >> 2) & 1;
                    W2u[(size_t)(nt2 * 32 + kt2) * 4096 + (bn * 4 + bk) * 64 + l * 2 + hb] =
                        f2tf(c[mt][nt][e]);
                }
            }
        }
        return;
    }

    // ---- projections ----
    const int bx = bid % 24, by = bid / 24;
    const bool isQ = bx < 8;
    const float* Abase = (isQ ? g_decA : g_encA) + (size_t)by * 32 * 4096;
    const float* Bbase = (isQ ? g_WqB : g_WkvB) + (size_t)(isQ ? bx : (bx - 8)) * 32 * 4096;
    const int n0 = (isQ ? bx : (bx - 8)) * 128;
    const int m0 = by * 128;

    pipe_frag(shb, sh, Abase, Bbase, c, wm, wn, lane, tid);

    unsigned* Qu = (unsigned*)g_Qh;
    unsigned* Ku = (unsigned*)g_Kh;
    unsigned* Vu = (unsigned*)g_Vh;
#pragma unroll
    for (int mt = 0; mt < 4; mt++) {
        int r0 = wm * 64 + mt * 16 + g;
#pragma unroll
        for (int nt = 0; nt < 8; nt++) {
            int col = n0 + wn * 64 + nt * 8 + 2 * t;
#pragma unroll
            for (int e = 0; e < 4; e++) {
                int m = m0 + ((e < 2) ? r0 : (r0 + 8));
                int n = col + (e & 1);
                float v = c[mt][nt][e];
                int b = m >> 10, q = m & 1023;
                if (isQ) {
                    int hh = n & 15, d = n >> 4;
                    size_t base = (size_t)(b * NH + hh) * (QL * DK);
                    int qt = q >> 6;
                    int am = (q >> 4) & 3;
                    int l = (q & 7) * 4 + (d & 3);
                    int j = ((q >> 3) & 1) + 2 * ((d >> 2) & 1);
                    Qu[base + qt * 4096 + (am * 8 + (d >> 3)) * 128 + l * 4 + j] =
                        f2tf(v * 0.125f);
                } else if (n < DIMN) {
                    int hh = n & 15, d = n >> 4;
                    size_t base = (size_t)(b * NH + hh) * (KL * DK);
                    int kt = q >> 6;
                    int bn = (q >> 3) & 7, bk = d >> 3;
                    int l = (q & 7) * 4 + (d & 3);
                    int hb = (d >> 2) & 1;
                    Ku[base + kt * 4096 + (bn * 8 + bk) * 64 + l * 2 + hb] = f2tf(v);
                } else {
                    int nn = n - DIMN;
                    int hh = nn & 15, d = nn >> 4;
                    size_t base = (size_t)(b * NH + hh) * (KL * DK);
                    int kt = q >> 6;
                    int bn = d >> 3, bk = (q >> 3) & 7;
                    int l = (d & 7) * 4 + (q & 3);
                    int hb = (q >> 2) & 1;
                    Vu[base + kt * 4096 + (bn * 8 + bk) * 64 + l * 2 + hb] = f2tf(v);
                }
            }
        }
    }
}

// ---------------------------------------------------------------------------
// Fused attention, all-fragment edition.
// Smem words: Q A-frag @0 (4096), K B-frag x2 @4096/@8192,
//             V B-frag x2 @12288/@16384, P A-frag per warp @20480 + w*1024.
// ---------------------------------------------------------------------------
#define AQOFF 0
#define AKOFF(buf) (4096 + (buf) * 4096)
#define AVOFF(buf) (12288 + (buf) * 4096)
#define APSOFF 20480
#define ATT_SMEM (24576 * 4)

__device__ __forceinline__ void att_issue(uint32_t shb, int woff,
                                          const float* __restrict__ src, int tid) {
#pragma unroll
    for (int i = 0; i < 8; i++) {
        int cch = tid + i * 128;
        cpasync16(shb + (uint32_t)(woff + cch * 4) * 4, src + cch * 4);
    }
}

__global__ __launch_bounds__(128, 2)
void attn_kernel()
{
    extern __shared__ unsigned smU[];
    uint32_t shb = (uint32_t)__cvta_generic_to_shared(smU);
    unsigned* Qs = smU + AQOFF;

    const int head = blockIdx.y;
    const int b = head >> 4, h = head & 15;
    const int q0 = blockIdx.x * 64;
    const int tid = threadIdx.x;
    const int w = tid >> 5, lane = tid & 31;
    const int g = lane >> 2, t = lane & 3;
    const int allTrue = g_allTrue;

    const float* Qp = g_Qh + (size_t)head * QL * DK + (size_t)blockIdx.x * 4096;
    const float* Kp = g_Kh + (size_t)head * KL * DK;
    const float* Vp = g_Vh + (size_t)head * KL * DK;
    unsigned* Pw = smU + APSOFF + w * 1024;

    att_issue(shb, AQOFF, Qp, tid);
    att_issue(shb, AKOFF(0), Kp, tid);
    att_issue(shb, AVOFF(0), Vp, tid);
    CP_COMMIT();

    float o[8][4];
#pragma unroll
    for (int nt = 0; nt < 8; nt++)
#pragma unroll
        for (int i = 0; i < 4; i++) o[nt][i] = 0.f;
    float l0 = 0.f, l1 = 0.f;

    const int NKT = KL / 64;  // 16
    for (int kt = 0; kt < NKT; kt++) {
        CP_WAIT0();
        __syncthreads();
        const int cur = kt & 1;
        if (kt + 1 < NKT) {
            att_issue(shb, AKOFF(cur ^ 1), Kp + (size_t)(kt + 1) * 4096, tid);
            att_issue(shb, AVOFF(cur ^ 1), Vp + (size_t)(kt + 1) * 4096, tid);
            CP_COMMIT();
        }
        const unsigned* Kc = smU + AKOFF(cur);
        const unsigned* Vc = smU + AVOFF(cur);

        // S = Q @ K^T : A-frags LDS.128, B-frags LDS.64
        float s[8][4];
#pragma unroll
        for (int nt = 0; nt < 8; nt++)
#pragma unroll
            for (int i = 0; i < 4; i++) s[nt][i] = 0.f;

#pragma unroll
        for (int ks = 0; ks < 8; ks++) {
            uint4 av = *(const uint4*)&Qs[((w * 8 + ks) << 7) + lane * 4];
            unsigned a[4] = { av.x, av.y, av.z, av.w };
#pragma unroll
            for (int nt = 0; nt < 8; nt++) {
                uint2 bv = *(const uint2*)&Kc[((nt * 8 + ks) << 6) + lane * 2];
                unsigned bf[2] = { bv.x, bv.y };
                mma_tf32(s[nt], a, bf);
            }
        }

        // mask + exp + rowsum; P -> per-warp A-frag region (scalar STS)
        int qr0 = w * 16 + g, qr1 = qr0 + 8;
        const unsigned char* m0p = g_mask8 + ((size_t)(b * QL + q0 + qr0)) * KL + kt * 64;
        const unsigned char* m1p = g_mask8 + ((size_t)(b * QL + q0 + qr1)) * KL + kt * 64;
        float rs0 = 0.f, rs1 = 0.f;
#pragma unroll
        for (int nt = 0; nt < 8; nt++) {
            int kc = 2 * t;
            float p00, p01, p10, p11;
            if (allTrue) {
                p00 = __expf(s[nt][0]); p01 = __expf(s[nt][1]);
                p10 = __expf(s[nt][2]); p11 = __expf(s[nt][3]);
            } else {
                int kg = nt * 8 + kc;
                p00 = m0p[kg]     ? __expf(s[nt][0]) : 0.f;
                p01 = m0p[kg + 1] ? __expf(s[nt][1]) : 0.f;
                p10 = m1p[kg]     ? __expf(s[nt][2]) : 0.f;
                p11 = m1p[kg + 1] ? __expf(s[nt][3]) : 0.f;
            }
            rs0 += p00 + p01;
            rs1 += p10 + p11;
            // A-frag addr: atom nt, l=(g*4 + (c&3)), j=rowbit + 2*(c>>2)
            int l00 = g * 4 + (kc & 3);
            int l01 = g * 4 + ((kc + 1) & 3);
            int j0 = 2 * (kc >> 2);
            Pw[nt * 128 + l00 * 4 + j0]     = f2tf(p00);
            Pw[nt * 128 + l00 * 4 + j0 + 1] = f2tf(p10);
            Pw[nt * 128 + l01 * 4 + j0]     = f2tf(p01);
            Pw[nt * 128 + l01 * 4 + j0 + 1] = f2tf(p11);
        }
        rs0 += __shfl_xor_sync(0xffffffffu, rs0, 1);
        rs0 += __shfl_xor_sync(0xffffffffu, rs0, 2);
        rs1 += __shfl_xor_sync(0xffffffffu, rs1, 1);
        rs1 += __shfl_xor_sync(0xffffffffu, rs1, 2);
        l0 += rs0;
        l1 += rs1;
        __syncwarp();   // P produced & consumed within this warp

        // O += P @ V : P A-frags LDS.128, V B-frags LDS.64
#pragma unroll
        for (int ks = 0; ks < 8; ks++) {
            uint4 pav = *(const uint4*)&Pw[(ks << 7) + lane * 4];
            unsigned a[4] = { pav.x, pav.y, pav.z, pav.w };
#pragma unroll
            for (int nt = 0; nt < 8; nt++) {
                uint2 bv = *(const uint2*)&Vc[((nt * 8 + ks) << 6) + lane * 2];
                unsigned bf[2] = { bv.x, bv.y };
                mma_tf32(o[nt], a, bf);
            }
        }
        __syncwarp();   // protect Pw before next tile overwrites
    }

    // normalize + scatter into g_valsA (A-frag of [4096, 1024])
    float inv0 = 1.f / l0, inv1 = 1.f / l1;
    int ma = b * QL + q0 + w * 16 + g;
    int mb = ma + 8;
    unsigned* Vo = (unsigned*)g_valsA;
#pragma unroll
    for (int nt = 0; nt < 8; nt++) {
        int d = nt * 8 + 2 * t;
#pragma unroll
        for (int e = 0; e < 4; e++) {
            int m = (e == 1 || e == 3) ? mb : ma;                 // rows: o2,o3 -> mb
            // mapping: o[0]->(ma,d), o[1]->(ma,d+1), o[2]->(mb,d), o[3]->(mb,d+1)
            int dd, mm;
            float val;
            if (e == 0)      { mm = ma; dd = d;     val = o[nt][0] * inv0; }
            else if (e == 1) { mm = ma; dd = d + 1; val = o[nt][1] * inv0; }
            else if (e == 2) { mm = mb; dd = d;     val = o[nt][2] * inv1; }
            else             { mm = mb; dd = d + 1; val = o[nt][3] * inv1; }
            int ncol = dd * NH + h;
            int mt2 = mm >> 7, kt2 = ncol >> 5;
            int am = (mm >> 4) & 7, ak = (ncol >> 3) & 3;
            int l = (mm & 7) * 4 + (ncol & 3);
            int j = ((mm >> 3) & 1) + 2 * ((ncol >> 2) & 1);
            Vo[(size_t)(mt2 * 32 + kt2) * 4096 + (am * 4 + ak) * 128 + l * 4 + j] = f2tf(val);
            (void)m;
        }
    }
}

// ---------------------------------------------------------------------------
extern "C" void kernel_launch(void* const* d_in, const int* in_sizes, int n_in,
                              void* d_out, int out_size)
{
    const float* dec  = (const float*)d_in[0];
    const float* enc  = (const float*)d_in[1];
    const unsigned char* mask = (const unsigned char*)d_in[2];
    const float* Wq   = (const float*)d_in[3];
    const float* Wkv  = (const float*)d_in[4];
    const float* Wout = (const float*)d_in[5];
    float* out = (float*)d_out;

    cudaFuncSetAttribute(final_gemm,   cudaFuncAttributeMaxDynamicSharedMemorySize, FRAG_SMEM);
    cudaFuncSetAttribute(proj_w2_gemm, cudaFuncAttributeMaxDynamicSharedMemorySize, FRAG_SMEM);
    cudaFuncSetAttribute(attn_kernel,  cudaFuncAttributeMaxDynamicSharedMemorySize, ATT_SMEM);

    const int M = BATCH * QL; // 4096
    const int NMASK = BATCH * QL * KL;
    dim3 blk(128);

    mask_detect_kernel<<<1, 256>>>(mask);
    mask_convert_kernel<<<(NMASK + 255) / 256, 256>>>(mask, NMASK);

    // tf32 pre-round + fragment-major layout transforms
    cvt_frag_kernel<<<CVT_BLOCKS, 256>>>(dec, enc, Wq, Wkv, Wout);

    // merged Q + KV projections + W2, all frag pipeline, one wave
    proj_w2_gemm<<<dim3(832), blk, FRAG_SMEM>>>();
    // fused attention (all-frag) -> g_valsA
    attn_kernel<<<dim3(QL / 64, BATCH * NH), dim3(128), ATT_SMEM>>>();
    // out = vals @ W2^T (frag pipeline)
    final_gemm<<<dim3(8, M / 128), blk, FRAG_SMEM>>>(out);
}

// round 15
// speedup vs baseline: 1.7609x; 1.0327x over previous
#include <cuda_runtime.h>
#include <cstddef>
#include <cstdint>

#define DIMN 1024
#define NH   16
#define DK   64
#define BATCH 4
#define QL   1024
#define KL   1024

// Scratch (device globals). All operand tensors in FRAGMENT-MAJOR tf32.
// B layouts use ks-PAIRED atoms: word = pair*128 + lane*4 + (ks&1)*2 + h.
__device__ float g_Qh[BATCH*NH*QL*DK];   // per head: qtile64 A-frag tiles
__device__ float g_Kh[BATCH*NH*KL*DK];   // per head: ktile64 B-frag paired (n=key,k=d)
__device__ float g_Vh[BATCH*NH*KL*DK];   // per head: ktile64 B-frag paired (n=d,k=key)
__device__ float g_valsA[BATCH*QL*DIMN]; // attn out, A-frag of [4096,1024]
__device__ float g_W2B[DIMN*DIMN];       // Wout@Wout, B-frag paired
__device__ float g_decA[BATCH*QL*DIMN];  // dec, A-frag
__device__ float g_encA[BATCH*KL*DIMN];  // enc, A-frag
__device__ float g_WqB[DIMN*DIMN];       // Wq, B-frag paired
__device__ float g_WkvB[2*DIMN*DIMN];    // Wkv, B-frag paired
__device__ float g_WoutA[DIMN*DIMN];     // Wout, A-frag
__device__ float g_WoutB[DIMN*DIMN];     // Wout^T, B-frag paired
__device__ unsigned char g_mask8[BATCH*QL*KL];
__device__ int g_isByte;
__device__ int g_allTrue;

// ---------------------------------------------------------------------------
__device__ __forceinline__ unsigned f2tf(float x) {
    unsigned r;
    asm("cvt.rna.tf32.f32 %0, %1;" : "=r"(r) : "f"(x));
    return r;
}

__device__ __forceinline__ void mma_tf32(float c[4], const unsigned a[4], const unsigned b[2]) {
    asm("mma.sync.aligned.m16n8k8.row.col.f32.tf32.tf32.f32 "
        "{%0,%1,%2,%3}, {%4,%5,%6,%7}, {%8,%9}, {%0,%1,%2,%3};"
        : "+f"(c[0]), "+f"(c[1]), "+f"(c[2]), "+f"(c[3])
        : "r"(a[0]), "r"(a[1]), "r"(a[2]), "r"(a[3]), "r"(b[0]), "r"(b[1]));
}

__device__ __forceinline__ void cpasync16(uint32_t dst, const void* src) {
    asm volatile("cp.async.cg.shared.global [%0], [%1], 16;" :: "r"(dst), "l"(src));
}
#define CP_COMMIT()  asm volatile("cp.async.commit_group;" ::: "memory")
#define CP_WAIT0()   asm volatile("cp.async.wait_all;" ::: "memory")
#define CP_WAIT1()   asm volatile("cp.async.wait_group 1;" ::: "memory")

// ---------------------------------------------------------------------------
// cvt: tf32 pre-round + fragment-major transforms.
//  A-frag: atoms(am*4+ak)x128; l=(r&7)*4+(c&3), j=(r>>3)+2*(c>>2)
//  B-frag PAIRED (GEMM, k-tile 32): pair = bn*2 + (bk>>1), 32 pairs x 128;
//    word = pair*128 + l*4 + (bk&1)*2 + h;  l=(n&7)*4+(k&3), h=(k>>2)&1
// blocks: 0..1023 dec(A) | 1024..2047 enc(A) | 2048..2303 Wq(B)
//         | 2304..2815 Wkv(B) | 2816..3071 WoutA(A) | 3072..3327 WoutB(B^T)
// ---------------------------------------------------------------------------
#define CVT_BLOCKS 3328

__global__ __launch_bounds__(256)
void cvt_frag_kernel(const float* __restrict__ dec, const float* __restrict__ enc,
                     const float* __restrict__ wq, const float* __restrict__ wkv,
                     const float* __restrict__ wout)
{
    __shared__ float tile[128 * 33];  // also used as [32][132]
    const int bid = blockIdx.x;
    const int tid = threadIdx.x;

    if (bid >= 3072) {
        // WoutB: paired B-frag of Wout^T. B[n][k] = Wout[k][n].
        int idx = bid - 3072;
        int mt = idx >> 5, kt = idx & 31;
#pragma unroll
        for (int ii = 0; ii < 4; ii++) {
            int fidx = tid + ii * 256;
            int kr = fidx >> 5, nq = (fidx & 31) * 4;
            float4 v = *(const float4*)&wout[(size_t)(kt * 32 + kr) * DIMN + mt * 128 + nq];
            float* d = &tile[kr * 132 + nq];
            d[0] = __uint_as_float(f2tf(v.x));
            d[1] = __uint_as_float(f2tf(v.y));
            d[2] = __uint_as_float(f2tf(v.z));
            d[3] = __uint_as_float(f2tf(v.w));
        }
        __syncthreads();
        float* outp = g_WoutB + (size_t)(mt * 32 + kt) * 4096;
#pragma unroll
        for (int ii = 0; ii < 4; ii++) {
            int cidx = tid + ii * 256;
            int pair = cidx >> 5;
            int bn = pair >> 1, bkp = pair & 1;
            int l = cidx & 31;
            uint4 o;
#pragma unroll
            for (int e = 0; e < 4; e++) {
                int bk = bkp * 2 + (e >> 1), h = e & 1;
                int n_loc = bn * 8 + (l >> 2);
                int k_loc = bk * 8 + h * 4 + (l & 3);
                ((unsigned*)&o)[e] = __float_as_uint(tile[k_loc * 132 + n_loc]);
            }
            *(uint4*)&outp[cidx * 4] = o;
        }
        return;
    }

    const float* src;
    float* dst;
    int mt, kt;
    bool isA;
    if (bid < 1024)      { src = dec;  dst = g_decA;  mt = bid >> 5;          kt = bid & 31; isA = true; }
    else if (bid < 2048) { src = enc;  dst = g_encA;  mt = (bid - 1024) >> 5; kt = bid & 31; isA = true; }
    else if (bid < 2304) { src = wq;   dst = g_WqB;   mt = (bid - 2048) >> 5; kt = bid & 31; isA = false; }
    else if (bid < 2816) { src = wkv;  dst = g_WkvB;  mt = (bid - 2304) >> 5; kt = bid & 31; isA = false; }
    else                 { src = wout; dst = g_WoutA; mt = (bid - 2816) >> 5; kt = bid & 31; isA = true; }

#pragma unroll
    for (int ii = 0; ii < 4; ii++) {
        int fidx = tid + ii * 256;
        int m = fidx >> 3, kq = (fidx & 7) * 4;
        float4 v = *(const float4*)&src[(size_t)(mt * 128 + m) * DIMN + kt * 32 + kq];
        float* d = &tile[m * 33 + kq];
        d[0] = __uint_as_float(f2tf(v.x));
        d[1] = __uint_as_float(f2tf(v.y));
        d[2] = __uint_as_float(f2tf(v.z));
        d[3] = __uint_as_float(f2tf(v.w));
    }
    __syncthreads();

    float* out = dst + (size_t)(mt * 32 + kt) * 4096;
    if (isA) {
#pragma unroll
        for (int ii = 0; ii < 4; ii++) {
            int cidx = tid + ii * 256;
            int l = cidx & 31, aidx = cidx >> 5;
            int am = aidx >> 2, ak = aidx & 3;
            int g = l >> 2, tt = l & 3;
            uint4 o;
            o.x = __float_as_uint(tile[(am * 16 + 0 + g) * 33 + ak * 8 + 0 + tt]);
            o.y = __float_as_uint(tile[(am * 16 + 8 + g) * 33 + ak * 8 + 0 + tt]);
            o.z = __float_as_uint(tile[(am * 16 + 0 + g) * 33 + ak * 8 + 4 + tt]);
            o.w = __float_as_uint(tile[(am * 16 + 8 + g) * 33 + ak * 8 + 4 + tt]);
            *(uint4*)&out[cidx * 4] = o;
        }
    } else {
#pragma unroll
        for (int ii = 0; ii < 4; ii++) {
            int cidx = tid + ii * 256;
            int pair = cidx >> 5;
            int bn = pair >> 1, bkp = pair & 1;
            int l = cidx & 31;
            uint4 o;
#pragma unroll
            for (int e = 0; e < 4; e++) {
                int bk = bkp * 2 + (e >> 1), h = e & 1;
                int n_loc = bn * 8 + (l >> 2);
                int k_loc = bk * 8 + h * 4 + (l & 3);
                ((unsigned*)&o)[e] = __float_as_uint(tile[n_loc * 33 + k_loc]);
            }
            *(uint4*)&out[cidx * 4] = o;
        }
    }
}

// ---------------------------------------------------------------------------
// Mask dtype detect (int32 vs byte)
// ---------------------------------------------------------------------------
__global__ void mask_detect_kernel(const unsigned char* __restrict__ m)
{
    __shared__ int found;
    if (threadIdx.x == 0) { found = 0; g_allTrue = 1; }
    __syncthreads();
    for (int i = threadIdx.x; i < 16384; i += blockDim.x)
        if ((i & 3) && m[i]) found = 1;
    __syncthreads();
    if (threadIdx.x == 0) g_isByte = found;
}

__global__ void mask_convert_kernel(const unsigned char* __restrict__ m, int n)
{
    int i = blockIdx.x * blockDim.x + threadIdx.x;
    int v = 1;
    if (i < n) {
        v = g_isByte ? (m[i] ? 1 : 0) : (((const unsigned*)m)[i] ? 1 : 0);
        g_mask8[i] = (unsigned char)v;
    }
    int all = __syncthreads_and(v);
    if (!all && threadIdx.x == 0) g_allTrue = 0;
}

// ---------------------------------------------------------------------------
// Fragment-major GEMM core (paired B): warp 64x64, LDS.128 for A and B.
// ---------------------------------------------------------------------------
#define FBUF 8192
#define FRAG_SMEM (3 * FBUF * 4)

__device__ __forceinline__ void issueFrag(uint32_t Sb, const float* __restrict__ P, int tid) {
#pragma unroll
    for (int i = 0; i < 8; i++) {
        int cch = tid + i * 128;
        cpasync16(Sb + (uint32_t)cch * 16, P + cch * 4);
    }
}

__device__ __forceinline__ void compute_tile_frag(const unsigned* __restrict__ As,
                                                  const unsigned* __restrict__ Bs,
                                                  float c[4][8][4], int wm, int wn, int lane) {
#pragma unroll
    for (int ksp = 0; ksp < 2; ksp++) {
        unsigned a0[4][4], a1[4][4];
#pragma unroll
        for (int mt = 0; mt < 4; mt++) {
            uint4 av0 = *(const uint4*)&As[(((wm * 4 + mt) * 4 + 2 * ksp) << 7) + lane * 4];
            uint4 av1 = *(const uint4*)&As[(((wm * 4 + mt) * 4 + 2 * ksp + 1) << 7) + lane * 4];
            a0[mt][0] = av0.x; a0[mt][1] = av0.y; a0[mt][2] = av0.z; a0[mt][3] = av0.w;
            a1[mt][0] = av1.x; a1[mt][1] = av1.y; a1[mt][2] = av1.z; a1[mt][3] = av1.w;
        }
#pragma unroll
        for (int nt = 0; nt < 8; nt++) {
            uint4 bv = *(const uint4*)&Bs[(((wn * 8 + nt) * 2 + ksp) << 7) + lane * 4];
            unsigned bf0[2] = { bv.x, bv.y };
            unsigned bf1[2] = { bv.z, bv.w };
#pragma unroll
            for (int mt = 0; mt < 4; mt++) {
                mma_tf32(c[mt][nt], a0[mt], bf0);
                mma_tf32(c[mt][nt], a1[mt], bf1);
            }
        }
    }
}

__device__ __forceinline__ void pipe_frag(uint32_t shb, unsigned* sh,
                                          const float* __restrict__ Abase,
                                          const float* __restrict__ Bbase,
                                          float c[4][8][4], int wm, int wn,
                                          int lane, int tid)
{
    const int NIT = 32;
    issueFrag(shb,            Abase, tid);
    issueFrag(shb + 4096 * 4, Bbase, tid);
    CP_COMMIT();
    issueFrag(shb + FBUF * 4,            Abase + 4096, tid);
    issueFrag(shb + FBUF * 4 + 4096 * 4, Bbase + 4096, tid);
    CP_COMMIT();

    int cur = 0;
    for (int kt = 0; kt < NIT; kt++) {
        if (kt + 1 < NIT) { CP_WAIT1(); } else { CP_WAIT0(); }
        __syncthreads();
        if (kt + 2 < NIT) {
            int nb = cur + 2; if (nb >= 3) nb -= 3;
            uint32_t base = shb + (uint32_t)(nb * FBUF) * 4;
            issueFrag(base,            Abase + (size_t)(kt + 2) * 4096, tid);
            issueFrag(base + 4096 * 4, Bbase + (size_t)(kt + 2) * 4096, tid);
            CP_COMMIT();
        }
        compute_tile_frag(sh + cur * FBUF, sh + cur * FBUF + 4096, c, wm, wn, lane);
        cur = (cur == 2) ? 0 : cur + 1;
    }
}

// ---------------------------------------------------------------------------
// Final GEMM: out = vals @ W2^T
// ---------------------------------------------------------------------------
__global__ __launch_bounds__(128, 2)
void final_gemm(float* __restrict__ C)
{
    extern __shared__ unsigned sh[];
    uint32_t shb = (uint32_t)__cvta_generic_to_shared(sh);
    const int tid = threadIdx.x;
    const int m0 = blockIdx.y * 128, n0 = blockIdx.x * 128;
    const int warp = tid >> 5, lane = tid & 31;
    const int wm = warp & 1, wn = warp >> 1;
    const int g = lane >> 2, t = lane & 3;

    float c[4][8][4];
#pragma unroll
    for (int mt = 0; mt < 4; mt++)
#pragma unroll
        for (int nt = 0; nt < 8; nt++)
#pragma unroll
            for (int i = 0; i < 4; i++) c[mt][nt][i] = 0.f;

    pipe_frag(shb, sh, g_valsA + (size_t)blockIdx.y * 32 * 4096,
              g_W2B + (size_t)blockIdx.x * 32 * 4096, c, wm, wn, lane, tid);

#pragma unroll
    for (int mt = 0; mt < 4; mt++) {
        int r0 = m0 + wm * 64 + mt * 16 + g;
        int r1 = r0 + 8;
#pragma unroll
        for (int nt = 0; nt < 8; nt++) {
            int col = n0 + wn * 64 + nt * 8 + 2 * t;
            *(float2*)&C[(size_t)r0 * DIMN + col] = make_float2(c[mt][nt][0], c[mt][nt][1]);
            *(float2*)&C[(size_t)r1 * DIMN + col] = make_float2(c[mt][nt][2], c[mt][nt][3]);
        }
    }
}

// ---------------------------------------------------------------------------
// Merged projections + W2, frag pipeline.
// ---------------------------------------------------------------------------
__global__ __launch_bounds__(128, 2)
void proj_w2_gemm()
{
    extern __shared__ unsigned sh[];
    uint32_t shb = (uint32_t)__cvta_generic_to_shared(sh);
    const int tid = threadIdx.x;
    const int bid = blockIdx.x;
    const int warp = tid >> 5, lane = tid & 31;
    const int wm = warp & 1, wn = warp >> 1;
    const int g = lane >> 2, t = lane & 3;

    float c[4][8][4];
#pragma unroll
    for (int mt = 0; mt < 4; mt++)
#pragma unroll
        for (int nt = 0; nt < 8; nt++)
#pragma unroll
            for (int i = 0; i < 4; i++) c[mt][nt][i] = 0.f;

    if (bid >= 768) {
        // ---- W2 = Wout @ Wout ----
        const int w = bid - 768;
        const int m0 = (w >> 3) * 128, n0 = (w & 7) * 128;
        pipe_frag(shb, sh, g_WoutA + (size_t)(w >> 3) * 32 * 4096,
                  g_WoutB + (size_t)(w & 7) * 32 * 4096, c, wm, wn, lane, tid);
        unsigned* W2u = (unsigned*)g_W2B;
#pragma unroll
        for (int mt = 0; mt < 4; mt++) {
            int r0 = m0 + wm * 64 + mt * 16 + g;
#pragma unroll
            for (int nt = 0; nt < 8; nt++) {
                int col = n0 + wn * 64 + nt * 8 + 2 * t;
#pragma unroll
                for (int e = 0; e < 4; e++) {
                    int r = (e < 2) ? r0 : (r0 + 8);
                    int cc = col + (e & 1);
                    int nt2 = r >> 7, kt2 = cc >> 5;
                    int pair = ((r >> 3) & 15) * 2 + ((cc >> 4) & 1);
                    int l = (r & 7) * 4 + (cc & 3);
                    int w4 = ((cc >> 3) & 1) * 2 + ((cc >> 2) & 1);
                    W2u[(size_t)(nt2 * 32 + kt2) * 4096 + pair * 128 + l * 4 + w4] =
                        f2tf(c[mt][nt][e]);
                }
            }
        }
        return;
    }

    // ---- projections ----
    const int bx = bid % 24, by = bid / 24;
    const bool isQ = bx < 8;
    const float* Abase = (isQ ? g_decA : g_encA) + (size_t)by * 32 * 4096;
    const float* Bbase = (isQ ? g_WqB : g_WkvB) + (size_t)(isQ ? bx : (bx - 8)) * 32 * 4096;
    const int n0 = (isQ ? bx : (bx - 8)) * 128;
    const int m0 = by * 128;

    pipe_frag(shb, sh, Abase, Bbase, c, wm, wn, lane, tid);

    unsigned* Qu = (unsigned*)g_Qh;
    unsigned* Ku = (unsigned*)g_Kh;
    unsigned* Vu = (unsigned*)g_Vh;
#pragma unroll
    for (int mt = 0; mt < 4; mt++) {
        int r0 = wm * 64 + mt * 16 + g;
#pragma unroll
        for (int nt = 0; nt < 8; nt++) {
            int col = n0 + wn * 64 + nt * 8 + 2 * t;
#pragma unroll
            for (int e = 0; e < 4; e++) {
                int m = m0 + ((e < 2) ? r0 : (r0 + 8));
                int n = col + (e & 1);
                float v = c[mt][nt][e];
                int b = m >> 10, q = m & 1023;
                if (isQ) {
                    int hh = n & 15, d = n >> 4;
                    size_t base = (size_t)(b * NH + hh) * (QL * DK);
                    int qt = q >> 6;
                    int am = (q >> 4) & 3;
                    int l = (q & 7) * 4 + (d & 3);
                    int j = ((q >> 3) & 1) + 2 * ((d >> 2) & 1);
                    Qu[base + qt * 4096 + (am * 8 + (d >> 3)) * 128 + l * 4 + j] =
                        f2tf(v * 0.125f);
                } else if (n < DIMN) {
                    // K: paired B-frag, n=key(q), k=d
                    int hh = n & 15, d = n >> 4;
                    size_t base = (size_t)(b * NH + hh) * (KL * DK);
                    int kt = q >> 6;
                    int pair = ((q >> 3) & 7) * 4 + (d >> 4);
                    int l = (q & 7) * 4 + (d & 3);
                    int w4 = ((d >> 3) & 1) * 2 + ((d >> 2) & 1);
                    Ku[base + kt * 4096 + pair * 128 + l * 4 + w4] = f2tf(v);
                } else {
                    // V: paired B-frag, n=d, k=key(q)
                    int nn = n - DIMN;
                    int hh = nn & 15, d = nn >> 4;
                    size_t base = (size_t)(b * NH + hh) * (KL * DK);
                    int kt = q >> 6;
                    int pair = (d >> 3) * 4 + ((q >> 4) & 3);
                    int l = (d & 7) * 4 + (q & 3);
                    int w4 = ((q >> 3) & 1) * 2 + ((q >> 2) & 1);
                    Vu[base + kt * 4096 + pair * 128 + l * 4 + w4] = f2tf(v);
                }
            }
        }
    }
}

// ---------------------------------------------------------------------------
// Fused attention, all-fragment + paired K/V + Q hoisted to registers.
// ---------------------------------------------------------------------------
#define AQOFF 0
#define AKOFF(buf) (4096 + (buf) * 4096)
#define AVOFF(buf) (12288 + (buf) * 4096)
#define APSOFF 20480
#define ATT_SMEM (24576 * 4)

__device__ __forceinline__ void att_issue(uint32_t shb, int woff,
                                          const float* __restrict__ src, int tid) {
#pragma unroll
    for (int i = 0; i < 8; i++) {
        int cch = tid + i * 128;
        cpasync16(shb + (uint32_t)(woff + cch * 4) * 4, src + cch * 4);
    }
}

__global__ __launch_bounds__(128, 2)
void attn_kernel()
{
    extern __shared__ unsigned smU[];
    uint32_t shb = (uint32_t)__cvta_generic_to_shared(smU);
    unsigned* Qs = smU + AQOFF;

    const int head = blockIdx.y;
    const int b = head >> 4, h = head & 15;
    const int q0 = blockIdx.x * 64;
    const int tid = threadIdx.x;
    const int w = tid >> 5, lane = tid & 31;
    const int g = lane >> 2, t = lane & 3;
    const int allTrue = g_allTrue;

    const float* Qp = g_Qh + (size_t)head * QL * DK + (size_t)blockIdx.x * 4096;
    const float* Kp = g_Kh + (size_t)head * KL * DK;
    const float* Vp = g_Vh + (size_t)head * KL * DK;
    unsigned* Pw = smU + APSOFF + w * 1024;

    att_issue(shb, AQOFF, Qp, tid);
    att_issue(shb, AKOFF(0), Kp, tid);
    att_issue(shb, AVOFF(0), Vp, tid);
    CP_COMMIT();

    float o[8][4];
#pragma unroll
    for (int nt = 0; nt < 8; nt++)
#pragma unroll
        for (int i = 0; i < 4; i++) o[nt][i] = 0.f;
    float l0 = 0.f, l1 = 0.f;

    uint4 qa[8];  // hoisted Q fragments (loaded at kt==0)

    const int NKT = KL / 64;  // 16
    for (int kt = 0; kt < NKT; kt++) {
        CP_WAIT0();
        __syncthreads();
        const int cur = kt & 1;
        if (kt == 0) {
#pragma unroll
            for (int ks = 0; ks < 8; ks++)
                qa[ks] = *(const uint4*)&Qs[((w * 8 + ks) << 7) + lane * 4];
        }
        if (kt + 1 < NKT) {
            att_issue(shb, AKOFF(cur ^ 1), Kp + (size_t)(kt + 1) * 4096, tid);
            att_issue(shb, AVOFF(cur ^ 1), Vp + (size_t)(kt + 1) * 4096, tid);
            CP_COMMIT();
        }
        const unsigned* Kc = smU + AKOFF(cur);
        const unsigned* Vc = smU + AVOFF(cur);

        // S = Q @ K^T : Q regs, K paired LDS.128
        float s[8][4];
#pragma unroll
        for (int nt = 0; nt < 8; nt++)
#pragma unroll
            for (int i = 0; i < 4; i++) s[nt][i] = 0.f;

#pragma unroll
        for (int ksp = 0; ksp < 4; ksp++) {
            unsigned a0[4] = { qa[2*ksp].x, qa[2*ksp].y, qa[2*ksp].z, qa[2*ksp].w };
            unsigned a1[4] = { qa[2*ksp+1].x, qa[2*ksp+1].y, qa[2*ksp+1].z, qa[2*ksp+1].w };
#pragma unroll
            for (int nt = 0; nt < 8; nt++) {
                uint4 bv = *(const uint4*)&Kc[((nt * 4 + ksp) << 7) + lane * 4];
                unsigned bf0[2] = { bv.x, bv.y };
                unsigned bf1[2] = { bv.z, bv.w };
                mma_tf32(s[nt], a0, bf0);
                mma_tf32(s[nt], a1, bf1);
            }
        }

        // mask + exp + rowsum; P -> per-warp A-frag region (scalar STS)
        int qr0 = w * 16 + g, qr1 = qr0 + 8;
        const unsigned char* m0p = g_mask8 + ((size_t)(b * QL + q0 + qr0)) * KL + kt * 64;
        const unsigned char* m1p = g_mask8 + ((size_t)(b * QL + q0 + qr1)) * KL + kt * 64;
        float rs0 = 0.f, rs1 = 0.f;
#pragma unroll
        for (int nt = 0; nt < 8; nt++) {
            int kc = 2 * t;
            float p00, p01, p10, p11;
            if (allTrue) {
                p00 = __expf(s[nt][0]); p01 = __expf(s[nt][1]);
                p10 = __expf(s[nt][2]); p11 = __expf(s[nt][3]);
            } else {
                int kg = nt * 8 + kc;
                p00 = m0p[kg]     ? __expf(s[nt][0]) : 0.f;
                p01 = m0p[kg + 1] ? __expf(s[nt][1]) : 0.f;
                p10 = m1p[kg]     ? __expf(s[nt][2]) : 0.f;
                p11 = m1p[kg + 1] ? __expf(s[nt][3]) : 0.f;
            }
            rs0 += p00 + p01;
            rs1 += p10 + p11;
            int l00 = g * 4 + (kc & 3);
            int l01 = g * 4 + ((kc + 1) & 3);
            int j0 = 2 * (kc >> 2);
            Pw[nt * 128 + l00 * 4 + j0]     = f2tf(p00);
            Pw[nt * 128 + l00 * 4 + j0 + 1] = f2tf(p10);
            Pw[nt * 128 + l01 * 4 + j0]     = f2tf(p01);
            Pw[nt * 128 + l01 * 4 + j0 + 1] = f2tf(p11);
        }
        rs0 += __shfl_xor_sync(0xffffffffu, rs0, 1);
        rs0 += __shfl_xor_sync(0xffffffffu, rs0, 2);
        rs1 += __shfl_xor_sync(0xffffffffu, rs1, 1);
        rs1 += __shfl_xor_sync(0xffffffffu, rs1, 2);
        l0 += rs0;
        l1 += rs1;
        __syncwarp();

        // O += P @ V : P A-frags LDS.128, V paired LDS.128
#pragma unroll
        for (int ksp = 0; ksp < 4; ksp++) {
            uint4 pav0 = *(const uint4*)&Pw[((2 * ksp) << 7) + lane * 4];
            uint4 pav1 = *(const uint4*)&Pw[((2 * ksp + 1) << 7) + lane * 4];
            unsigned a0[4] = { pav0.x, pav0.y, pav0.z, pav0.w };
            unsigned a1[4] = { pav1.x, pav1.y, pav1.z, pav1.w };
#pragma unroll
            for (int nt = 0; nt < 8; nt++) {
                uint4 bv = *(const uint4*)&Vc[((nt * 4 + ksp) << 7) + lane * 4];
                unsigned bf0[2] = { bv.x, bv.y };
                unsigned bf1[2] = { bv.z, bv.w };
                mma_tf32(o[nt], a0, bf0);
                mma_tf32(o[nt], a1, bf1);
            }
        }
        __syncwarp();
    }

    // normalize + scatter into g_valsA (A-frag of [4096, 1024])
    float inv0 = 1.f / l0, inv1 = 1.f / l1;
    int ma = b * QL + q0 + w * 16 + g;
    int mb = ma + 8;
    unsigned* Vo = (unsigned*)g_valsA;
#pragma unroll
    for (int nt = 0; nt < 8; nt++) {
        int d = nt * 8 + 2 * t;
#pragma unroll
        for (int e = 0; e < 4; e++) {
            int dd, mm;
            float val;
            if (e == 0)      { mm = ma; dd = d;     val = o[nt][0] * inv0; }
            else if (e == 1) { mm = ma; dd = d + 1; val = o[nt][1] * inv0; }
            else if (e == 2) { mm = mb; dd = d;     val = o[nt][2] * inv1; }
            else             { mm = mb; dd = d + 1; val = o[nt][3] * inv1; }
            int ncol = dd * NH + h;
            int mt2 = mm >> 7, kt2 = ncol >> 5;
            int am = (mm >> 4) & 7, ak = (ncol >> 3) & 3;
            int l = (mm & 7) * 4 + (ncol & 3);
            int j = ((mm >> 3) & 1) + 2 * ((ncol >> 2) & 1);
            Vo[(size_t)(mt2 * 32 + kt2) * 4096 + (am * 4 + ak) * 128 + l * 4 + j] = f2tf(val);
        }
    }
}

// ---------------------------------------------------------------------------
extern "C" void kernel_launch(void* const* d_in, const int* in_sizes, int n_in,
                              void* d_out, int out_size)
{
    const float* dec  = (const float*)d_in[0];
    const float* enc  = (const float*)d_in[1];
    const unsigned char* mask = (const unsigned char*)d_in[2];
    const float* Wq   = (const float*)d_in[3];
    const float* Wkv  = (const float*)d_in[4];
    const float* Wout = (const float*)d_in[5];
    float* out = (float*)d_out;

    cudaFuncSetAttribute(final_gemm,   cudaFuncAttributeMaxDynamicSharedMemorySize, FRAG_SMEM);
    cudaFuncSetAttribute(proj_w2_gemm, cudaFuncAttributeMaxDynamicSharedMemorySize, FRAG_SMEM);
    cudaFuncSetAttribute(attn_kernel,  cudaFuncAttributeMaxDynamicSharedMemorySize, ATT_SMEM);

    const int M = BATCH * QL; // 4096
    const int NMASK = BATCH * QL * KL;
    dim3 blk(128);

    mask_detect_kernel<<<1, 256>>>(mask);
    mask_convert_kernel<<<(NMASK + 255) / 256, 256>>>(mask, NMASK);

    // tf32 pre-round + fragment-major layout transforms (paired B)
    cvt_frag_kernel<<<CVT_BLOCKS, 256>>>(dec, enc, Wq, Wkv, Wout);

    // merged Q + KV projections + W2, one wave
    proj_w2_gemm<<<dim3(832), blk, FRAG_SMEM>>>();
    // fused attention (all-frag, paired K/V) -> g_valsA
    attn_kernel<<<dim3(QL / 64, BATCH * NH), dim3(128), ATT_SMEM>>>();
    // out = vals @ W2^T
    final_gemm<<<dim3(8, M / 128), blk, FRAG_SMEM>>>(out);
}

// round 16
// speedup vs baseline: 1.8083x; 1.0270x over previous
#include <cuda_runtime.h>
#include <cstddef>
#include <cstdint>

#define DIMN 1024
#define NH   16
#define DK   64
#define BATCH 4
#define QL   1024
#define KL   1024

// Scratch (device globals). All operand tensors in FRAGMENT-MAJOR tf32.
// B layouts use ks-PAIRED atoms: word = pair*128 + lane*4 + (ks&1)*2 + h.
__device__ float g_Qh[BATCH*NH*QL*DK];   // per head: qtile64 A-frag tiles
__device__ float g_Kh[BATCH*NH*KL*DK];   // per head: ktile64 B-frag paired (n=key,k=d)
__device__ float g_Vh[BATCH*NH*KL*DK];   // per head: ktile64 B-frag paired (n=d,k=key)
__device__ float g_valsA[BATCH*QL*DIMN]; // attn out, A-frag of [4096,1024]
__device__ float g_W2B[DIMN*DIMN];       // Wout@Wout, B-frag paired
__device__ float g_decA[BATCH*QL*DIMN];  // dec, A-frag
__device__ float g_encA[BATCH*KL*DIMN];  // enc, A-frag
__device__ float g_WqB[DIMN*DIMN];       // Wq, B-frag paired
__device__ float g_WkvB[2*DIMN*DIMN];    // Wkv, B-frag paired
__device__ float g_WoutA[DIMN*DIMN];     // Wout, A-frag
__device__ float g_WoutB[DIMN*DIMN];     // Wout^T, B-frag paired
__device__ unsigned char g_mask8[BATCH*QL*KL];
__device__ int g_isByte;
__device__ int g_allTrue;

// ---------------------------------------------------------------------------
__device__ __forceinline__ unsigned f2tf(float x) {
    unsigned r;
    asm("cvt.rna.tf32.f32 %0, %1;" : "=r"(r) : "f"(x));
    return r;
}

__device__ __forceinline__ void mma_tf32(float c[4], const unsigned a[4], const unsigned b[2]) {
    asm("mma.sync.aligned.m16n8k8.row.col.f32.tf32.tf32.f32 "
        "{%0,%1,%2,%3}, {%4,%5,%6,%7}, {%8,%9}, {%0,%1,%2,%3};"
        : "+f"(c[0]), "+f"(c[1]), "+f"(c[2]), "+f"(c[3])
        : "r"(a[0]), "r"(a[1]), "r"(a[2]), "r"(a[3]), "r"(b[0]), "r"(b[1]));
}

// mbarrier + bulk-copy primitives (sm_90 PTX; NOT sm_100a-gated)
#define MBAR_INIT(a, c) \
    asm volatile("mbarrier.init.shared.b64 [%0], %1;" :: "r"(a), "r"(c) : "memory")
#define MBAR_EXPTX(a, bytes) \
    asm volatile("mbarrier.arrive.expect_tx.shared.b64 _, [%0], %1;" :: "r"(a), "r"(bytes) : "memory")
#define MBAR_WAIT(addr, ph) do { \
    asm volatile( \
        "{\n\t.reg .pred P1;\n\t" \
        "WL%=:\n\t" \
        "mbarrier.try_wait.parity.acquire.cta.shared::cta.b64 P1, [%0], %1, 0x989680;\n\t" \
        "@P1 bra.uni WD%=;\n\t" \
        "bra.uni WL%=;\n\t" \
        "WD%=:\n\t}" \
        :: "r"(addr), "r"(ph) : "memory"); \
} while (0)
#define BULK_G2S(dst, src, bytes, mbar) \
    asm volatile("cp.async.bulk.shared::cluster.global.mbarrier::complete_tx::bytes " \
                 "[%0], [%1], %2, [%3];" \
                 :: "r"(dst), "l"(src), "r"(bytes), "r"(mbar) : "memory")

// ---------------------------------------------------------------------------
// cvt: tf32 pre-round + fragment-major transforms (unchanged from R15).
// ---------------------------------------------------------------------------
#define CVT_BLOCKS 3328

__global__ __launch_bounds__(256)
void cvt_frag_kernel(const float* __restrict__ dec, const float* __restrict__ enc,
                     const float* __restrict__ wq, const float* __restrict__ wkv,
                     const float* __restrict__ wout)
{
    __shared__ float tile[128 * 33];
    const int bid = blockIdx.x;
    const int tid = threadIdx.x;

    if (bid >= 3072) {
        int idx = bid - 3072;
        int mt = idx >> 5, kt = idx & 31;
#pragma unroll
        for (int ii = 0; ii < 4; ii++) {
            int fidx = tid + ii * 256;
            int kr = fidx >> 5, nq = (fidx & 31) * 4;
            float4 v = *(const float4*)&wout[(size_t)(kt * 32 + kr) * DIMN + mt * 128 + nq];
            float* d = &tile[kr * 132 + nq];
            d[0] = __uint_as_float(f2tf(v.x));
            d[1] = __uint_as_float(f2tf(v.y));
            d[2] = __uint_as_float(f2tf(v.z));
            d[3] = __uint_as_float(f2tf(v.w));
        }
        __syncthreads();
        float* outp = g_WoutB + (size_t)(mt * 32 + kt) * 4096;
#pragma unroll
        for (int ii = 0; ii < 4; ii++) {
            int cidx = tid + ii * 256;
            int pair = cidx >> 5;
            int bn = pair >> 1, bkp = pair & 1;
            int l = cidx & 31;
            uint4 o;
#pragma unroll
            for (int e = 0; e < 4; e++) {
                int bk = bkp * 2 + (e >> 1), h = e & 1;
                int n_loc = bn * 8 + (l >> 2);
                int k_loc = bk * 8 + h * 4 + (l & 3);
                ((unsigned*)&o)[e] = __float_as_uint(tile[k_loc * 132 + n_loc]);
            }
            *(uint4*)&outp[cidx * 4] = o;
        }
        return;
    }

    const float* src;
    float* dst;
    int mt, kt;
    bool isA;
    if (bid < 1024)      { src = dec;  dst = g_decA;  mt = bid >> 5;          kt = bid & 31; isA = true; }
    else if (bid < 2048) { src = enc;  dst = g_encA;  mt = (bid - 1024) >> 5; kt = bid & 31; isA = true; }
    else if (bid < 2304) { src = wq;   dst = g_WqB;   mt = (bid - 2048) >> 5; kt = bid & 31; isA = false; }
    else if (bid < 2816) { src = wkv;  dst = g_WkvB;  mt = (bid - 2304) >> 5; kt = bid & 31; isA = false; }
    else                 { src = wout; dst = g_WoutA; mt = (bid - 2816) >> 5; kt = bid & 31; isA = true; }

#pragma unroll
    for (int ii = 0; ii < 4; ii++) {
        int fidx = tid + ii * 256;
        int m = fidx >> 3, kq = (fidx & 7) * 4;
        float4 v = *(const float4*)&src[(size_t)(mt * 128 + m) * DIMN + kt * 32 + kq];
        float* d = &tile[m * 33 + kq];
        d[0] = __uint_as_float(f2tf(v.x));
        d[1] = __uint_as_float(f2tf(v.y));
        d[2] = __uint_as_float(f2tf(v.z));
        d[3] = __uint_as_float(f2tf(v.w));
    }
    __syncthreads();

    float* out = dst + (size_t)(mt * 32 + kt) * 4096;
    if (isA) {
#pragma unroll
        for (int ii = 0; ii < 4; ii++) {
            int cidx = tid + ii * 256;
            int l = cidx & 31, aidx = cidx >> 5;
            int am = aidx >> 2, ak = aidx & 3;
            int g = l >> 2, tt = l & 3;
            uint4 o;
            o.x = __float_as_uint(tile[(am * 16 + 0 + g) * 33 + ak * 8 + 0 + tt]);
            o.y = __float_as_uint(tile[(am * 16 + 8 + g) * 33 + ak * 8 + 0 + tt]);
            o.z = __float_as_uint(tile[(am * 16 + 0 + g) * 33 + ak * 8 + 4 + tt]);
            o.w = __float_as_uint(tile[(am * 16 + 8 + g) * 33 + ak * 8 + 4 + tt]);
            *(uint4*)&out[cidx * 4] = o;
        }
    } else {
#pragma unroll
        for (int ii = 0; ii < 4; ii++) {
            int cidx = tid + ii * 256;
            int pair = cidx >> 5;
            int bn = pair >> 1, bkp = pair & 1;
            int l = cidx & 31;
            uint4 o;
#pragma unroll
            for (int e = 0; e < 4; e++) {
                int bk = bkp * 2 + (e >> 1), h = e & 1;
                int n_loc = bn * 8 + (l >> 2);
                int k_loc = bk * 8 + h * 4 + (l & 3);
                ((unsigned*)&o)[e] = __float_as_uint(tile[n_loc * 33 + k_loc]);
            }
            *(uint4*)&out[cidx * 4] = o;
        }
    }
}

// ---------------------------------------------------------------------------
// Mask: detect dtype (16KB), scan all-true (no writes), convert (early-out)
// ---------------------------------------------------------------------------
__global__ void mask_detect_kernel(const unsigned char* __restrict__ m)
{
    __shared__ int found;
    if (threadIdx.x == 0) { found = 0; g_allTrue = 1; }
    __syncthreads();
    for (int i = threadIdx.x; i < 16384; i += blockDim.x)
        if ((i & 3) && m[i]) found = 1;
    __syncthreads();
    if (threadIdx.x == 0) g_isByte = found;
}

__global__ void mask_scan_kernel(const unsigned char* __restrict__ m, int nelem)
{
    const int isB = g_isByte;
    const long limit = isB ? (long)nelem : (long)nelem * 4;   // bytes in buffer
    long i = ((long)blockIdx.x * blockDim.x + threadIdx.x) * 16;
    int ok = 1;
    if (i < limit) {
        uint4 v = *(const uint4*)(m + i);
        if (isB) {
            unsigned z = ((v.x - 0x01010101u) & ~v.x & 0x80808080u)
                       | ((v.y - 0x01010101u) & ~v.y & 0x80808080u)
                       | ((v.z - 0x01010101u) & ~v.z & 0x80808080u)
                       | ((v.w - 0x01010101u) & ~v.w & 0x80808080u);
            ok = (z == 0);
        } else {
            ok = (v.x != 0) && (v.y != 0) && (v.z != 0) && (v.w != 0);
        }
    }
    if (__syncthreads_and(ok) == 0 && threadIdx.x == 0) g_allTrue = 0;
}

__global__ void mask_convert_kernel(const unsigned char* __restrict__ m, int n)
{
    if (g_allTrue) return;
    int i = blockIdx.x * blockDim.x + threadIdx.x;
    if (i < n)
        g_mask8[i] = g_isByte ? (m[i] ? 1 : 0) : (((const unsigned*)m)[i] ? 1 : 0);
}

// ---------------------------------------------------------------------------
// Fragment-major GEMM core (paired B) with cp.async.bulk staging.
// ---------------------------------------------------------------------------
#define FBUF 8192
#define FRAG_SMEM (3 * FBUF * 4 + 64)

__device__ __forceinline__ void compute_tile_frag(const unsigned* __restrict__ As,
                                                  const unsigned* __restrict__ Bs,
                                                  float c[4][8][4], int wm, int wn, int lane) {
#pragma unroll
    for (int ksp = 0; ksp < 2; ksp++) {
        unsigned a0[4][4], a1[4][4];
#pragma unroll
        for (int mt = 0; mt < 4; mt++) {
            uint4 av0 = *(const uint4*)&As[(((wm * 4 + mt) * 4 + 2 * ksp) << 7) + lane * 4];
            uint4 av1 = *(const uint4*)&As[(((wm * 4 + mt) * 4 + 2 * ksp + 1) << 7) + lane * 4];
            a0[mt][0] = av0.x; a0[mt][1] = av0.y; a0[mt][2] = av0.z; a0[mt][3] = av0.w;
            a1[mt][0] = av1.x; a1[mt][1] = av1.y; a1[mt][2] = av1.z; a1[mt][3] = av1.w;
        }
#pragma unroll
        for (int nt = 0; nt < 8; nt++) {
            uint4 bv = *(const uint4*)&Bs[(((wn * 8 + nt) * 2 + ksp) << 7) + lane * 4];
            unsigned bf0[2] = { bv.x, bv.y };
            unsigned bf1[2] = { bv.z, bv.w };
#pragma unroll
            for (int mt = 0; mt < 4; mt++) {
                mma_tf32(c[mt][nt], a0[mt], bf0);
                mma_tf32(c[mt][nt], a1[mt], bf1);
            }
        }
    }
}

__device__ __forceinline__ void pipe_frag(uint32_t shb, unsigned* sh,
                                          const float* __restrict__ Abase,
                                          const float* __restrict__ Bbase,
                                          float c[4][8][4], int wm, int wn,
                                          int lane, int tid)
{
    const uint32_t mb = shb + 3 * FBUF * 4;   // mbarrier area (3 x 8B)
    if (tid == 0) {
        MBAR_INIT(mb + 0, 1);
        MBAR_INIT(mb + 8, 1);
        MBAR_INIT(mb + 16, 1);
    }
    __syncthreads();
    if (tid == 0) {
        MBAR_EXPTX(mb + 0, 32768);
        BULK_G2S(shb,          Abase,        16384, mb + 0);
        BULK_G2S(shb + 16384,  Bbase,        16384, mb + 0);
        MBAR_EXPTX(mb + 8, 32768);
        BULK_G2S(shb + 32768,  Abase + 4096, 16384, mb + 8);
        BULK_G2S(shb + 49152,  Bbase + 4096, 16384, mb + 8);
    }

    const int NIT = 32;
    for (int kt = 0; kt < NIT; kt++) {
        int b = kt % 3;
        int ph = (kt / 3) & 1;
        MBAR_WAIT(mb + b * 8, ph);
        __syncthreads();
        if (kt + 2 < NIT && tid == 0) {
            int nb = b + 2; if (nb >= 3) nb -= 3;
            MBAR_EXPTX(mb + nb * 8, 32768);
            BULK_G2S(shb + nb * 32768,         Abase + (size_t)(kt + 2) * 4096, 16384, mb + nb * 8);
            BULK_G2S(shb + nb * 32768 + 16384, Bbase + (size_t)(kt + 2) * 4096, 16384, mb + nb * 8);
        }
        compute_tile_frag(sh + b * FBUF, sh + b * FBUF + 4096, c, wm, wn, lane);
    }
}

// ---------------------------------------------------------------------------
// Final GEMM: out = vals @ W2^T
// ---------------------------------------------------------------------------
__global__ __launch_bounds__(128, 2)
void final_gemm(float* __restrict__ C)
{
    extern __shared__ unsigned sh[];
    uint32_t shb = (uint32_t)__cvta_generic_to_shared(sh);
    const int tid = threadIdx.x;
    const int m0 = blockIdx.y * 128, n0 = blockIdx.x * 128;
    const int warp = tid >> 5, lane = tid & 31;
    const int wm = warp & 1, wn = warp >> 1;
    const int g = lane >> 2, t = lane & 3;

    float c[4][8][4];
#pragma unroll
    for (int mt = 0; mt < 4; mt++)
#pragma unroll
        for (int nt = 0; nt < 8; nt++)
#pragma unroll
            for (int i = 0; i < 4; i++) c[mt][nt][i] = 0.f;

    pipe_frag(shb, sh, g_valsA + (size_t)blockIdx.y * 32 * 4096,
              g_W2B + (size_t)blockIdx.x * 32 * 4096, c, wm, wn, lane, tid);

#pragma unroll
    for (int mt = 0; mt < 4; mt++) {
        int r0 = m0 + wm * 64 + mt * 16 + g;
        int r1 = r0 + 8;
#pragma unroll
        for (int nt = 0; nt < 8; nt++) {
            int col = n0 + wn * 64 + nt * 8 + 2 * t;
            *(float2*)&C[(size_t)r0 * DIMN + col] = make_float2(c[mt][nt][0], c[mt][nt][1]);
            *(float2*)&C[(size_t)r1 * DIMN + col] = make_float2(c[mt][nt][2], c[mt][nt][3]);
        }
    }
}

// ---------------------------------------------------------------------------
// Merged projections + W2, frag pipeline (bulk staging).
// ---------------------------------------------------------------------------
__global__ __launch_bounds__(128, 2)
void proj_w2_gemm()
{
    extern __shared__ unsigned sh[];
    uint32_t shb = (uint32_t)__cvta_generic_to_shared(sh);
    const int tid = threadIdx.x;
    const int bid = blockIdx.x;
    const int warp = tid >> 5, lane = tid & 31;
    const int wm = warp & 1, wn = warp >> 1;
    const int g = lane >> 2, t = lane & 3;

    float c[4][8][4];
#pragma unroll
    for (int mt = 0; mt < 4; mt++)
#pragma unroll
        for (int nt = 0; nt < 8; nt++)
#pragma unroll
            for (int i = 0; i < 4; i++) c[mt][nt][i] = 0.f;

    if (bid >= 768) {
        const int w = bid - 768;
        const int m0 = (w >> 3) * 128, n0 = (w & 7) * 128;
        pipe_frag(shb, sh, g_WoutA + (size_t)(w >> 3) * 32 * 4096,
                  g_WoutB + (size_t)(w & 7) * 32 * 4096, c, wm, wn, lane, tid);
        unsigned* W2u = (unsigned*)g_W2B;
#pragma unroll
        for (int mt = 0; mt < 4; mt++) {
            int r0 = m0 + wm * 64 + mt * 16 + g;
#pragma unroll
            for (int nt = 0; nt < 8; nt++) {
                int col = n0 + wn * 64 + nt * 8 + 2 * t;
#pragma unroll
                for (int e = 0; e < 4; e++) {
                    int r = (e < 2) ? r0 : (r0 + 8);
                    int cc = col + (e & 1);
                    int nt2 = r >> 7, kt2 = cc >> 5;
                    int pair = ((r >> 3) & 15) * 2 + ((cc >> 4) & 1);
                    int l = (r & 7) * 4 + (cc & 3);
                    int w4 = ((cc >> 3) & 1) * 2 + ((cc >> 2) & 1);
                    W2u[(size_t)(nt2 * 32 + kt2) * 4096 + pair * 128 + l * 4 + w4] =
                        f2tf(c[mt][nt][e]);
                }
            }
        }
        return;
    }

    const int bx = bid % 24, by = bid / 24;
    const bool isQ = bx < 8;
    const float* Abase = (isQ ? g_decA : g_encA) + (size_t)by * 32 * 4096;
    const float* Bbase = (isQ ? g_WqB : g_WkvB) + (size_t)(isQ ? bx : (bx - 8)) * 32 * 4096;
    const int n0 = (isQ ? bx : (bx - 8)) * 128;
    const int m0 = by * 128;

    pipe_frag(shb, sh, Abase, Bbase, c, wm, wn, lane, tid);

    unsigned* Qu = (unsigned*)g_Qh;
    unsigned* Ku = (unsigned*)g_Kh;
    unsigned* Vu = (unsigned*)g_Vh;
#pragma unroll
    for (int mt = 0; mt < 4; mt++) {
        int r0 = wm * 64 + mt * 16 + g;
#pragma unroll
        for (int nt = 0; nt < 8; nt++) {
            int col = n0 + wn * 64 + nt * 8 + 2 * t;
#pragma unroll
            for (int e = 0; e < 4; e++) {
                int m = m0 + ((e < 2) ? r0 : (r0 + 8));
                int n = col + (e & 1);
                float v = c[mt][nt][e];
                int b = m >> 10, q = m & 1023;
                if (isQ) {
                    int hh = n & 15, d = n >> 4;
                    size_t base = (size_t)(b * NH + hh) * (QL * DK);
                    int qt = q >> 6;
                    int am = (q >> 4) & 3;
                    int l = (q & 7) * 4 + (d & 3);
                    int j = ((q >> 3) & 1) + 2 * ((d >> 2) & 1);
                    Qu[base + qt * 4096 + (am * 8 + (d >> 3)) * 128 + l * 4 + j] =
                        f2tf(v * 0.125f);
                } else if (n < DIMN) {
                    int hh = n & 15, d = n >> 4;
                    size_t base = (size_t)(b * NH + hh) * (KL * DK);
                    int kt = q >> 6;
                    int pair = ((q >> 3) & 7) * 4 + (d >> 4);
                    int l = (q & 7) * 4 + (d & 3);
                    int w4 = ((d >> 3) & 1) * 2 + ((d >> 2) & 1);
                    Ku[base + kt * 4096 + pair * 128 + l * 4 + w4] = f2tf(v);
                } else {
                    int nn = n - DIMN;
                    int hh = nn & 15, d = nn >> 4;
                    size_t base = (size_t)(b * NH + hh) * (KL * DK);
                    int kt = q >> 6;
                    int pair = (d >> 3) * 4 + ((q >> 4) & 3);
                    int l = (d & 7) * 4 + (q & 3);
                    int w4 = ((q >> 3) & 1) * 2 + ((q >> 2) & 1);
                    Vu[base + kt * 4096 + pair * 128 + l * 4 + w4] = f2tf(v);
                }
            }
        }
    }
}

// ---------------------------------------------------------------------------
// Fused attention: all-frag, paired K/V, Q hoisted, bulk staging.
// Smem words: Q @0 (4096), K x2 @4096/@8192, V x2 @12288/@16384,
//             P per warp @20480; mbarriers at byte offset 24576*4.
// ---------------------------------------------------------------------------
#define AQOFF 0
#define AKOFF(buf) (4096 + (buf) * 4096)
#define AVOFF(buf) (12288 + (buf) * 4096)
#define APSOFF 20480
#define ATT_SMEM (24576 * 4 + 64)

__global__ __launch_bounds__(128, 2)
void attn_kernel()
{
    extern __shared__ unsigned smU[];
    uint32_t shb = (uint32_t)__cvta_generic_to_shared(smU);
    unsigned* Qs = smU + AQOFF;
    const uint32_t mb = shb + 24576 * 4;

    const int head = blockIdx.y;
    const int b = head >> 4, h = head & 15;
    const int q0 = blockIdx.x * 64;
    const int tid = threadIdx.x;
    const int w = tid >> 5, lane = tid & 31;
    const int g = lane >> 2, t = lane & 3;
    const int allTrue = g_allTrue;

    const float* Qp = g_Qh + (size_t)head * QL * DK + (size_t)blockIdx.x * 4096;
    const float* Kp = g_Kh + (size_t)head * KL * DK;
    const float* Vp = g_Vh + (size_t)head * KL * DK;
    unsigned* Pw = smU + APSOFF + w * 1024;

    if (tid == 0) {
        MBAR_INIT(mb + 0, 1);
        MBAR_INIT(mb + 8, 1);
    }
    __syncthreads();
    if (tid == 0) {
        MBAR_EXPTX(mb + 0, 49152);
        BULK_G2S(shb + AQOFF * 4,    Qp, 16384, mb + 0);
        BULK_G2S(shb + AKOFF(0) * 4, Kp, 16384, mb + 0);
        BULK_G2S(shb + AVOFF(0) * 4, Vp, 16384, mb + 0);
    }

    float o[8][4];
#pragma unroll
    for (int nt = 0; nt < 8; nt++)
#pragma unroll
        for (int i = 0; i < 4; i++) o[nt][i] = 0.f;
    float l0 = 0.f, l1 = 0.f;

    uint4 qa[8];

    const int NKT = KL / 64;  // 16
    for (int kt = 0; kt < NKT; kt++) {
        const int cur = kt & 1;
        MBAR_WAIT(mb + cur * 8, (kt >> 1) & 1);
        __syncthreads();
        if (kt == 0) {
#pragma unroll
            for (int ks = 0; ks < 8; ks++)
                qa[ks] = *(const uint4*)&Qs[((w * 8 + ks) << 7) + lane * 4];
        }
        if (kt + 1 < NKT && tid == 0) {
            int nb = cur ^ 1;
            MBAR_EXPTX(mb + nb * 8, 32768);
            BULK_G2S(shb + AKOFF(nb) * 4, Kp + (size_t)(kt + 1) * 4096, 16384, mb + nb * 8);
            BULK_G2S(shb + AVOFF(nb) * 4, Vp + (size_t)(kt + 1) * 4096, 16384, mb + nb * 8);
        }
        const unsigned* Kc = smU + AKOFF(cur);
        const unsigned* Vc = smU + AVOFF(cur);

        float s[8][4];
#pragma unroll
        for (int nt = 0; nt < 8; nt++)
#pragma unroll
            for (int i = 0; i < 4; i++) s[nt][i] = 0.f;

#pragma unroll
        for (int ksp = 0; ksp < 4; ksp++) {
            unsigned a0[4] = { qa[2*ksp].x, qa[2*ksp].y, qa[2*ksp].z, qa[2*ksp].w };
            unsigned a1[4] = { qa[2*ksp+1].x, qa[2*ksp+1].y, qa[2*ksp+1].z, qa[2*ksp+1].w };
#pragma unroll
            for (int nt = 0; nt < 8; nt++) {
                uint4 bv = *(const uint4*)&Kc[((nt * 4 + ksp) << 7) + lane * 4];
                unsigned bf0[2] = { bv.x, bv.y };
                unsigned bf1[2] = { bv.z, bv.w };
                mma_tf32(s[nt], a0, bf0);
                mma_tf32(s[nt], a1, bf1);
            }
        }

        int qr0 = w * 16 + g, qr1 = qr0 + 8;
        const unsigned char* m0p = g_mask8 + ((size_t)(b * QL + q0 + qr0)) * KL + kt * 64;
        const unsigned char* m1p = g_mask8 + ((size_t)(b * QL + q0 + qr1)) * KL + kt * 64;
        float rs0 = 0.f, rs1 = 0.f;
#pragma unroll
        for (int nt = 0; nt < 8; nt++) {
            int kc = 2 * t;
            float p00, p01, p10, p11;
            if (allTrue) {
                p00 = __expf(s[nt][0]); p01 = __expf(s[nt][1]);
                p10 = __expf(s[nt][2]); p11 = __expf(s[nt][3]);
            } else {
                int kg = nt * 8 + kc;
                p00 = m0p[kg]     ? __expf(s[nt][0]) : 0.f;
                p01 = m0p[kg + 1] ? __expf(s[nt][1]) : 0.f;
                p10 = m1p[kg]     ? __expf(s[nt][2]) : 0.f;
                p11 = m1p[kg + 1] ? __expf(s[nt][3]) : 0.f;
            }
            rs0 += p00 + p01;
            rs1 += p10 + p11;
            int l00 = g * 4 + (kc & 3);
            int l01 = g * 4 + ((kc + 1) & 3);
            int j0 = 2 * (kc >> 2);
            Pw[nt * 128 + l00 * 4 + j0]     = f2tf(p00);
            Pw[nt * 128 + l00 * 4 + j0 + 1] = f2tf(p10);
            Pw[nt * 128 + l01 * 4 + j0]     = f2tf(p01);
            Pw[nt * 128 + l01 * 4 + j0 + 1] = f2tf(p11);
        }
        rs0 += __shfl_xor_sync(0xffffffffu, rs0, 1);
        rs0 += __shfl_xor_sync(0xffffffffu, rs0, 2);
        rs1 += __shfl_xor_sync(0xffffffffu, rs1, 1);
        rs1 += __shfl_xor_sync(0xffffffffu, rs1, 2);
        l0 += rs0;
        l1 += rs1;
        __syncwarp();

#pragma unroll
        for (int ksp = 0; ksp < 4; ksp++) {
            uint4 pav0 = *(const uint4*)&Pw[((2 * ksp) << 7) + lane * 4];
            uint4 pav1 = *(const uint4*)&Pw[((2 * ksp + 1) << 7) + lane * 4];
            unsigned a0[4] = { pav0.x, pav0.y, pav0.z, pav0.w };
            unsigned a1[4] = { pav1.x, pav1.y, pav1.z, pav1.w };
#pragma unroll
            for (int nt = 0; nt < 8; nt++) {
                uint4 bv = *(const uint4*)&Vc[((nt * 4 + ksp) << 7) + lane * 4];
                unsigned bf0[2] = { bv.x, bv.y };
                unsigned bf1[2] = { bv.z, bv.w };
                mma_tf32(o[nt], a0, bf0);
                mma_tf32(o[nt], a1, bf1);
            }
        }
        __syncwarp();
    }

    float inv0 = 1.f / l0, inv1 = 1.f / l1;
    int ma = b * QL + q0 + w * 16 + g;
    int mbq = ma + 8;
    unsigned* Vo = (unsigned*)g_valsA;
#pragma unroll
    for (int nt = 0; nt < 8; nt++) {
        int d = nt * 8 + 2 * t;
#pragma unroll
        for (int e = 0; e < 4; e++) {
            int dd, mm;
            float val;
            if (e == 0)      { mm = ma;  dd = d;     val = o[nt][0] * inv0; }
            else if (e == 1) { mm = ma;  dd = d + 1; val = o[nt][1] * inv0; }
            else if (e == 2) { mm = mbq; dd = d;     val = o[nt][2] * inv1; }
            else             { mm = mbq; dd = d + 1; val = o[nt][3] * inv1; }
            int ncol = dd * NH + h;
            int mt2 = mm >> 7, kt2 = ncol >> 5;
            int am = (mm >> 4) & 7, ak = (ncol >> 3) & 3;
            int l = (mm & 7) * 4 + (ncol & 3);
            int j = ((mm >> 3) & 1) + 2 * ((ncol >> 2) & 1);
            Vo[(size_t)(mt2 * 32 + kt2) * 4096 + (am * 4 + ak) * 128 + l * 4 + j] = f2tf(val);
        }
    }
}

// ---------------------------------------------------------------------------
extern "C" void kernel_launch(void* const* d_in, const int* in_sizes, int n_in,
                              void* d_out, int out_size)
{
    const float* dec  = (const float*)d_in[0];
    const float* enc  = (const float*)d_in[1];
    const unsigned char* mask = (const unsigned char*)d_in[2];
    const float* Wq   = (const float*)d_in[3];
    const float* Wkv  = (const float*)d_in[4];
    const float* Wout = (const float*)d_in[5];
    float* out = (float*)d_out;

    cudaFuncSetAttribute(final_gemm,   cudaFuncAttributeMaxDynamicSharedMemorySize, FRAG_SMEM);
    cudaFuncSetAttribute(proj_w2_gemm, cudaFuncAttributeMaxDynamicSharedMemorySize, FRAG_SMEM);
    cudaFuncSetAttribute(attn_kernel,  cudaFuncAttributeMaxDynamicSharedMemorySize, ATT_SMEM);

    const int M = BATCH * QL; // 4096
    const int NMASK = BATCH * QL * KL;
    dim3 blk(128);

    mask_detect_kernel<<<1, 256>>>(mask);
    mask_scan_kernel<<<(NMASK * 4 / 16 + 255) / 256, 256>>>(mask, NMASK);
    mask_convert_kernel<<<(NMASK + 255) / 256, 256>>>(mask, NMASK);

    // tf32 pre-round + fragment-major layout transforms (paired B)
    cvt_frag_kernel<<<CVT_BLOCKS, 256>>>(dec, enc, Wq, Wkv, Wout);

    // merged Q + KV projections + W2, one wave
    proj_w2_gemm<<<dim3(832), blk, FRAG_SMEM>>>();
    // fused attention (all-frag, paired K/V) -> g_valsA
    attn_kernel<<<dim3(QL / 64, BATCH * NH), dim3(128), ATT_SMEM>>>();
    // out = vals @ W2^T
    final_gemm<<<dim3(8, M / 128), blk, FRAG_SMEM>>>(out);
}

// round 17
// speedup vs baseline: 1.8114x; 1.0017x over previous
#include <cuda_runtime.h>
#include <cstddef>
#include <cstdint>

#define DIMN 1024
#define NH   16
#define DK   64
#define BATCH 4
#define QL   1024
#define KL   1024

// Scratch (device globals). All operand tensors in FRAGMENT-MAJOR tf32.
// B layouts use ks-PAIRED atoms: word = pair*128 + lane*4 + (ks&1)*2 + h.
__device__ float g_Qh[BATCH*NH*QL*DK];   // per head: qtile64 A-frag tiles
__device__ float g_Kh[BATCH*NH*KL*DK];   // per head: ktile64 B-frag paired (n=key,k=d)
__device__ float g_Vh[BATCH*NH*KL*DK];   // per head: ktile64 B-frag paired (n=d,k=key)
__device__ float g_valsA[BATCH*QL*DIMN]; // attn out, A-frag of [4096,1024]
__device__ float g_W2B[DIMN*DIMN];       // Wout@Wout, B-frag paired
__device__ float g_decA[BATCH*QL*DIMN];  // dec, A-frag
__device__ float g_encA[BATCH*KL*DIMN];  // enc, A-frag
__device__ float g_WqB[DIMN*DIMN];       // Wq, B-frag paired
__device__ float g_WkvB[2*DIMN*DIMN];    // Wkv, B-frag paired
__device__ float g_WoutA[DIMN*DIMN];     // Wout, A-frag
__device__ float g_WoutB[DIMN*DIMN];     // Wout^T, B-frag paired
__device__ unsigned char g_mask8[BATCH*QL*KL];
__device__ int g_isByte;
__device__ int g_allTrue;

// ---------------------------------------------------------------------------
__device__ __forceinline__ unsigned f2tf(float x) {
    unsigned r;
    asm("cvt.rna.tf32.f32 %0, %1;" : "=r"(r) : "f"(x));
    return r;
}

__device__ __forceinline__ void mma_tf32(float c[4], const unsigned a[4], const unsigned b[2]) {
    asm("mma.sync.aligned.m16n8k8.row.col.f32.tf32.tf32.f32 "
        "{%0,%1,%2,%3}, {%4,%5,%6,%7}, {%8,%9}, {%0,%1,%2,%3};"
        : "+f"(c[0]), "+f"(c[1]), "+f"(c[2]), "+f"(c[3])
        : "r"(a[0]), "r"(a[1]), "r"(a[2]), "r"(a[3]), "r"(b[0]), "r"(b[1]));
}

// mbarrier + bulk-copy primitives (sm_90 PTX; NOT sm_100a-gated)
#define MBAR_INIT(a, c) \
    asm volatile("mbarrier.init.shared.b64 [%0], %1;" :: "r"(a), "r"(c) : "memory")
#define MBAR_EXPTX(a, bytes) \
    asm volatile("mbarrier.arrive.expect_tx.shared.b64 _, [%0], %1;" :: "r"(a), "r"(bytes) : "memory")
#define MBAR_WAIT(addr, ph) do { \
    asm volatile( \
        "{\n\t.reg .pred P1;\n\t" \
        "WL%=:\n\t" \
        "mbarrier.try_wait.parity.acquire.cta.shared::cta.b64 P1, [%0], %1, 0x989680;\n\t" \
        "@P1 bra.uni WD%=;\n\t" \
        "bra.uni WL%=;\n\t" \
        "WD%=:\n\t}" \
        :: "r"(addr), "r"(ph) : "memory"); \
} while (0)
#define BULK_G2S(dst, src, bytes, mbar) \
    asm volatile("cp.async.bulk.shared::cluster.global.mbarrier::complete_tx::bytes " \
                 "[%0], [%1], %2, [%3];" \
                 :: "r"(dst), "l"(src), "r"(bytes), "r"(mbar) : "memory")

// ---------------------------------------------------------------------------
// cvt: tf32 pre-round + fragment-major transforms; scan blocks appended
// (bid >= 3328 run the all-true mask scan, reading g_isByte from detect).
// ---------------------------------------------------------------------------
#define CVT_BLOCKS 3328
#define SCAN_BLOCKS 4096
#define NMASKE (BATCH * QL * KL)

__global__ __launch_bounds__(256)
void cvt_frag_kernel(const float* __restrict__ dec, const float* __restrict__ enc,
                     const float* __restrict__ wq, const float* __restrict__ wkv,
                     const float* __restrict__ wout, const unsigned char* __restrict__ mk)
{
    __shared__ float tile[128 * 33];
    const int bid = blockIdx.x;
    const int tid = threadIdx.x;

    if (bid >= CVT_BLOCKS) {
        // ---- mask all-true scan (no writes) ----
        const int isB = g_isByte;
        const long limit = isB ? (long)NMASKE : (long)NMASKE * 4;
        long i = ((long)(bid - CVT_BLOCKS) * 256 + tid) * 16;
        int ok = 1;
        if (i < limit) {
            uint4 v = *(const uint4*)(mk + i);
            if (isB) {
                unsigned z = ((v.x - 0x01010101u) & ~v.x & 0x80808080u)
                           | ((v.y - 0x01010101u) & ~v.y & 0x80808080u)
                           | ((v.z - 0x01010101u) & ~v.z & 0x80808080u)
                           | ((v.w - 0x01010101u) & ~v.w & 0x80808080u);
                ok = (z == 0);
            } else {
                ok = (v.x != 0) && (v.y != 0) && (v.z != 0) && (v.w != 0);
            }
        }
        if (__syncthreads_and(ok) == 0 && tid == 0) g_allTrue = 0;
        return;
    }

    if (bid >= 3072) {
        // WoutB: paired B-frag of Wout^T. B[n][k] = Wout[k][n].
        int idx = bid - 3072;
        int mt = idx >> 5, kt = idx & 31;
#pragma unroll
        for (int ii = 0; ii < 4; ii++) {
            int fidx = tid + ii * 256;
            int kr = fidx >> 5, nq = (fidx & 31) * 4;
            float4 v = *(const float4*)&wout[(size_t)(kt * 32 + kr) * DIMN + mt * 128 + nq];
            float* d = &tile[kr * 132 + nq];
            d[0] = __uint_as_float(f2tf(v.x));
            d[1] = __uint_as_float(f2tf(v.y));
            d[2] = __uint_as_float(f2tf(v.z));
            d[3] = __uint_as_float(f2tf(v.w));
        }
        __syncthreads();
        float* outp = g_WoutB + (size_t)(mt * 32 + kt) * 4096;
#pragma unroll
        for (int ii = 0; ii < 4; ii++) {
            int cidx = tid + ii * 256;
            int pair = cidx >> 5;
            int bn = pair >> 1, bkp = pair & 1;
            int l = cidx & 31;
            uint4 o;
#pragma unroll
            for (int e = 0; e < 4; e++) {
                int bk = bkp * 2 + (e >> 1), h = e & 1;
                int n_loc = bn * 8 + (l >> 2);
                int k_loc = bk * 8 + h * 4 + (l & 3);
                ((unsigned*)&o)[e] = __float_as_uint(tile[k_loc * 132 + n_loc]);
            }
            *(uint4*)&outp[cidx * 4] = o;
        }
        return;
    }

    const float* src;
    float* dst;
    int mt, kt;
    bool isA;
    if (bid < 1024)      { src = dec;  dst = g_decA;  mt = bid >> 5;          kt = bid & 31; isA = true; }
    else if (bid < 2048) { src = enc;  dst = g_encA;  mt = (bid - 1024) >> 5; kt = bid & 31; isA = true; }
    else if (bid < 2304) { src = wq;   dst = g_WqB;   mt = (bid - 2048) >> 5; kt = bid & 31; isA = false; }
    else if (bid < 2816) { src = wkv;  dst = g_WkvB;  mt = (bid - 2304) >> 5; kt = bid & 31; isA = false; }
    else                 { src = wout; dst = g_WoutA; mt = (bid - 2816) >> 5; kt = bid & 31; isA = true; }

#pragma unroll
    for (int ii = 0; ii < 4; ii++) {
        int fidx = tid + ii * 256;
        int m = fidx >> 3, kq = (fidx & 7) * 4;
        float4 v = *(const float4*)&src[(size_t)(mt * 128 + m) * DIMN + kt * 32 + kq];
        float* d = &tile[m * 33 + kq];
        d[0] = __uint_as_float(f2tf(v.x));
        d[1] = __uint_as_float(f2tf(v.y));
        d[2] = __uint_as_float(f2tf(v.z));
        d[3] = __uint_as_float(f2tf(v.w));
    }
    __syncthreads();

    float* out = dst + (size_t)(mt * 32 + kt) * 4096;
    if (isA) {
#pragma unroll
        for (int ii = 0; ii < 4; ii++) {
            int cidx = tid + ii * 256;
            int l = cidx & 31, aidx = cidx >> 5;
            int am = aidx >> 2, ak = aidx & 3;
            int g = l >> 2, tt = l & 3;
            uint4 o;
            o.x = __float_as_uint(tile[(am * 16 + 0 + g) * 33 + ak * 8 + 0 + tt]);
            o.y = __float_as_uint(tile[(am * 16 + 8 + g) * 33 + ak * 8 + 0 + tt]);
            o.z = __float_as_uint(tile[(am * 16 + 0 + g) * 33 + ak * 8 + 4 + tt]);
            o.w = __float_as_uint(tile[(am * 16 + 8 + g) * 33 + ak * 8 + 4 + tt]);
            *(uint4*)&out[cidx * 4] = o;
        }
    } else {
#pragma unroll
        for (int ii = 0; ii < 4; ii++) {
            int cidx = tid + ii * 256;
            int pair = cidx >> 5;
            int bn = pair >> 1, bkp = pair & 1;
            int l = cidx & 31;
            uint4 o;
#pragma unroll
            for (int e = 0; e < 4; e++) {
                int bk = bkp * 2 + (e >> 1), h = e & 1;
                int n_loc = bn * 8 + (l >> 2);
                int k_loc = bk * 8 + h * 4 + (l & 3);
                ((unsigned*)&o)[e] = __float_as_uint(tile[n_loc * 33 + k_loc]);
            }
            *(uint4*)&out[cidx * 4] = o;
        }
    }
}

// ---------------------------------------------------------------------------
// Mask: detect dtype (16KB sample); convert (early-out when all-true)
// ---------------------------------------------------------------------------
__global__ void mask_detect_kernel(const unsigned char* __restrict__ m)
{
    __shared__ int found;
    if (threadIdx.x == 0) { found = 0; g_allTrue = 1; }
    __syncthreads();
    for (int i = threadIdx.x; i < 16384; i += blockDim.x)
        if ((i & 3) && m[i]) found = 1;
    __syncthreads();
    if (threadIdx.x == 0) g_isByte = found;
}

__global__ void mask_convert_kernel(const unsigned char* __restrict__ m, int n)
{
    if (g_allTrue) return;
    int i = blockIdx.x * blockDim.x + threadIdx.x;
    if (i < n)
        g_mask8[i] = g_isByte ? (m[i] ? 1 : 0) : (((const unsigned*)m)[i] ? 1 : 0);
}

// ---------------------------------------------------------------------------
// Fragment-major GEMM core (paired B) with cp.async.bulk staging.
// ---------------------------------------------------------------------------
#define FBUF 8192
#define FRAG_SMEM (3 * FBUF * 4 + 64)

__device__ __forceinline__ void compute_tile_frag(const unsigned* __restrict__ As,
                                                  const unsigned* __restrict__ Bs,
                                                  float c[4][8][4], int wm, int wn, int lane) {
#pragma unroll
    for (int ksp = 0; ksp < 2; ksp++) {
        unsigned a0[4][4], a1[4][4];
#pragma unroll
        for (int mt = 0; mt < 4; mt++) {
            uint4 av0 = *(const uint4*)&As[(((wm * 4 + mt) * 4 + 2 * ksp) << 7) + lane * 4];
            uint4 av1 = *(const uint4*)&As[(((wm * 4 + mt) * 4 + 2 * ksp + 1) << 7) + lane * 4];
            a0[mt][0] = av0.x; a0[mt][1] = av0.y; a0[mt][2] = av0.z; a0[mt][3] = av0.w;
            a1[mt][0] = av1.x; a1[mt][1] = av1.y; a1[mt][2] = av1.z; a1[mt][3] = av1.w;
        }
#pragma unroll
        for (int nt = 0; nt < 8; nt++) {
            uint4 bv = *(const uint4*)&Bs[(((wn * 8 + nt) * 2 + ksp) << 7) + lane * 4];
            unsigned bf0[2] = { bv.x, bv.y };
            unsigned bf1[2] = { bv.z, bv.w };
#pragma unroll
            for (int mt = 0; mt < 4; mt++) {
                mma_tf32(c[mt][nt], a0[mt], bf0);
                mma_tf32(c[mt][nt], a1[mt], bf1);
            }
        }
    }
}

__device__ __forceinline__ void pipe_frag(uint32_t shb, unsigned* sh,
                                          const float* __restrict__ Abase,
                                          const float* __restrict__ Bbase,
                                          float c[4][8][4], int wm, int wn,
                                          int lane, int tid)
{
    const uint32_t mb = shb + 3 * FBUF * 4;
    if (tid == 0) {
        MBAR_INIT(mb + 0, 1);
        MBAR_INIT(mb + 8, 1);
        MBAR_INIT(mb + 16, 1);
    }
    __syncthreads();
    if (tid == 0) {
        MBAR_EXPTX(mb + 0, 32768);
        BULK_G2S(shb,          Abase,        16384, mb + 0);
        BULK_G2S(shb + 16384,  Bbase,        16384, mb + 0);
        MBAR_EXPTX(mb + 8, 32768);
        BULK_G2S(shb + 32768,  Abase + 4096, 16384, mb + 8);
        BULK_G2S(shb + 49152,  Bbase + 4096, 16384, mb + 8);
    }

    const int NIT = 32;
    for (int kt = 0; kt < NIT; kt++) {
        int b = kt % 3;
        int ph = (kt / 3) & 1;
        MBAR_WAIT(mb + b * 8, ph);
        __syncthreads();
        if (kt + 2 < NIT && tid == 0) {
            int nb = b + 2; if (nb >= 3) nb -= 3;
            MBAR_EXPTX(mb + nb * 8, 32768);
            BULK_G2S(shb + nb * 32768,         Abase + (size_t)(kt + 2) * 4096, 16384, mb + nb * 8);
            BULK_G2S(shb + nb * 32768 + 16384, Bbase + (size_t)(kt + 2) * 4096, 16384, mb + nb * 8);
        }
        compute_tile_frag(sh + b * FBUF, sh + b * FBUF + 4096, c, wm, wn, lane);
    }
}

// ---------------------------------------------------------------------------
// Final GEMM: out = vals @ W2^T
// ---------------------------------------------------------------------------
__global__ __launch_bounds__(128, 2)
void final_gemm(float* __restrict__ C)
{
    extern __shared__ unsigned sh[];
    uint32_t shb = (uint32_t)__cvta_generic_to_shared(sh);
    const int tid = threadIdx.x;
    const int m0 = blockIdx.y * 128, n0 = blockIdx.x * 128;
    const int warp = tid >> 5, lane = tid & 31;
    const int wm = warp & 1, wn = warp >> 1;
    const int g = lane >> 2, t = lane & 3;

    float c[4][8][4];
#pragma unroll
    for (int mt = 0; mt < 4; mt++)
#pragma unroll
        for (int nt = 0; nt < 8; nt++)
#pragma unroll
            for (int i = 0; i < 4; i++) c[mt][nt][i] = 0.f;

    pipe_frag(shb, sh, g_valsA + (size_t)blockIdx.y * 32 * 4096,
              g_W2B + (size_t)blockIdx.x * 32 * 4096, c, wm, wn, lane, tid);

#pragma unroll
    for (int mt = 0; mt < 4; mt++) {
        int r0 = m0 + wm * 64 + mt * 16 + g;
        int r1 = r0 + 8;
#pragma unroll
        for (int nt = 0; nt < 8; nt++) {
            int col = n0 + wn * 64 + nt * 8 + 2 * t;
            *(float2*)&C[(size_t)r0 * DIMN + col] = make_float2(c[mt][nt][0], c[mt][nt][1]);
            *(float2*)&C[(size_t)r1 * DIMN + col] = make_float2(c[mt][nt][2], c[mt][nt][3]);
        }
    }
}

// ---------------------------------------------------------------------------
// Merged projections + W2, frag pipeline (bulk staging).
// ---------------------------------------------------------------------------
__global__ __launch_bounds__(128, 2)
void proj_w2_gemm()
{
    extern __shared__ unsigned sh[];
    uint32_t shb = (uint32_t)__cvta_generic_to_shared(sh);
    const int tid = threadIdx.x;
    const int bid = blockIdx.x;
    const int warp = tid >> 5, lane = tid & 31;
    const int wm = warp & 1, wn = warp >> 1;
    const int g = lane >> 2, t = lane & 3;

    float c[4][8][4];
#pragma unroll
    for (int mt = 0; mt < 4; mt++)
#pragma unroll
        for (int nt = 0; nt < 8; nt++)
#pragma unroll
            for (int i = 0; i < 4; i++) c[mt][nt][i] = 0.f;

    if (bid >= 768) {
        const int w = bid - 768;
        const int m0 = (w >> 3) * 128, n0 = (w & 7) * 128;
        pipe_frag(shb, sh, g_WoutA + (size_t)(w >> 3) * 32 * 4096,
                  g_WoutB + (size_t)(w & 7) * 32 * 4096, c, wm, wn, lane, tid);
        unsigned* W2u = (unsigned*)g_W2B;
#pragma unroll
        for (int mt = 0; mt < 4; mt++) {
            int r0 = m0 + wm * 64 + mt * 16 + g;
#pragma unroll
            for (int nt = 0; nt < 8; nt++) {
                int col = n0 + wn * 64 + nt * 8 + 2 * t;
#pragma unroll
                for (int e = 0; e < 4; e++) {
                    int r = (e < 2) ? r0 : (r0 + 8);
                    int cc = col + (e & 1);
                    int nt2 = r >> 7, kt2 = cc >> 5;
                    int pair = ((r >> 3) & 15) * 2 + ((cc >> 4) & 1);
                    int l = (r & 7) * 4 + (cc & 3);
                    int w4 = ((cc >> 3) & 1) * 2 + ((cc >> 2) & 1);
                    W2u[(size_t)(nt2 * 32 + kt2) * 4096 + pair * 128 + l * 4 + w4] =
                        f2tf(c[mt][nt][e]);
                }
            }
        }
        return;
    }

    const int bx = bid % 24, by = bid / 24;
    const bool isQ = bx < 8;
    const float* Abase = (isQ ? g_decA : g_encA) + (size_t)by * 32 * 4096;
    const float* Bbase = (isQ ? g_WqB : g_WkvB) + (size_t)(isQ ? bx : (bx - 8)) * 32 * 4096;
    const int n0 = (isQ ? bx : (bx - 8)) * 128;
    const int m0 = by * 128;

    pipe_frag(shb, sh, Abase, Bbase, c, wm, wn, lane, tid);

    unsigned* Qu = (unsigned*)g_Qh;
    unsigned* Ku = (unsigned*)g_Kh;
    unsigned* Vu = (unsigned*)g_Vh;
#pragma unroll
    for (int mt = 0; mt < 4; mt++) {
        int r0 = wm * 64 + mt * 16 + g;
#pragma unroll
        for (int nt = 0; nt < 8; nt++) {
            int col = n0 + wn * 64 + nt * 8 + 2 * t;
#pragma unroll
            for (int e = 0; e < 4; e++) {
                int m = m0 + ((e < 2) ? r0 : (r0 + 8));
                int n = col + (e & 1);
                float v = c[mt][nt][e];
                int b = m >> 10, q = m & 1023;
                if (isQ) {
                    int hh = n & 15, d = n >> 4;
                    size_t base = (size_t)(b * NH + hh) * (QL * DK);
                    int qt = q >> 6;
                    int am = (q >> 4) & 3;
                    int l = (q & 7) * 4 + (d & 3);
                    int j = ((q >> 3) & 1) + 2 * ((d >> 2) & 1);
                    Qu[base + qt * 4096 + (am * 8 + (d >> 3)) * 128 + l * 4 + j] =
                        f2tf(v * 0.125f);
                } else if (n < DIMN) {
                    int hh = n & 15, d = n >> 4;
                    size_t base = (size_t)(b * NH + hh) * (KL * DK);
                    int kt = q >> 6;
                    int pair = ((q >> 3) & 7) * 4 + (d >> 4);
                    int l = (q & 7) * 4 + (d & 3);
                    int w4 = ((d >> 3) & 1) * 2 + ((d >> 2) & 1);
                    Ku[base + kt * 4096 + pair * 128 + l * 4 + w4] = f2tf(v);
                } else {
                    int nn = n - DIMN;
                    int hh = nn & 15, d = nn >> 4;
                    size_t base = (size_t)(b * NH + hh) * (KL * DK);
                    int kt = q >> 6;
                    int pair = (d >> 3) * 4 + ((q >> 4) & 3);
                    int l = (d & 7) * 4 + (q & 3);
                    int w4 = ((q >> 3) & 1) * 2 + ((q >> 2) & 1);
                    Vu[base + kt * 4096 + pair * 128 + l * 4 + w4] = f2tf(v);
                }
            }
        }
    }
}

// ---------------------------------------------------------------------------
// Fused attention: all-frag, paired K/V, Q hoisted, bulk staging, STS.64 P.
// ---------------------------------------------------------------------------
#define AQOFF 0
#define AKOFF(buf) (4096 + (buf) * 4096)
#define AVOFF(buf) (12288 + (buf) * 4096)
#define APSOFF 20480
#define ATT_SMEM (24576 * 4 + 64)

__global__ __launch_bounds__(128, 2)
void attn_kernel()
{
    extern __shared__ unsigned smU[];
    uint32_t shb = (uint32_t)__cvta_generic_to_shared(smU);
    unsigned* Qs = smU + AQOFF;
    const uint32_t mb = shb + 24576 * 4;

    const int head = blockIdx.y;
    const int b = head >> 4, h = head & 15;
    const int q0 = blockIdx.x * 64;
    const int tid = threadIdx.x;
    const int w = tid >> 5, lane = tid & 31;
    const int g = lane >> 2, t = lane & 3;
    const int allTrue = g_allTrue;

    const float* Qp = g_Qh + (size_t)head * QL * DK + (size_t)blockIdx.x * 4096;
    const float* Kp = g_Kh + (size_t)head * KL * DK;
    const float* Vp = g_Vh + (size_t)head * KL * DK;
    unsigned* Pw = smU + APSOFF + w * 1024;

    if (tid == 0) {
        MBAR_INIT(mb + 0, 1);
        MBAR_INIT(mb + 8, 1);
    }
    __syncthreads();
    if (tid == 0) {
        MBAR_EXPTX(mb + 0, 49152);
        BULK_G2S(shb + AQOFF * 4,    Qp, 16384, mb + 0);
        BULK_G2S(shb + AKOFF(0) * 4, Kp, 16384, mb + 0);
        BULK_G2S(shb + AVOFF(0) * 4, Vp, 16384, mb + 0);
    }

    float o[8][4];
#pragma unroll
    for (int nt = 0; nt < 8; nt++)
#pragma unroll
        for (int i = 0; i < 4; i++) o[nt][i] = 0.f;
    float l0 = 0.f, l1 = 0.f;

    uint4 qa[8];

    const int NKT = KL / 64;  // 16
    for (int kt = 0; kt < NKT; kt++) {
        const int cur = kt & 1;
        MBAR_WAIT(mb + cur * 8, (kt >> 1) & 1);
        __syncthreads();
        if (kt == 0) {
#pragma unroll
            for (int ks = 0; ks < 8; ks++)
                qa[ks] = *(const uint4*)&Qs[((w * 8 + ks) << 7) + lane * 4];
        }
        if (kt + 1 < NKT && tid == 0) {
            int nb = cur ^ 1;
            MBAR_EXPTX(mb + nb * 8, 32768);
            BULK_G2S(shb + AKOFF(nb) * 4, Kp + (size_t)(kt + 1) * 4096, 16384, mb + nb * 8);
            BULK_G2S(shb + AVOFF(nb) * 4, Vp + (size_t)(kt + 1) * 4096, 16384, mb + nb * 8);
        }
        const unsigned* Kc = smU + AKOFF(cur);
        const unsigned* Vc = smU + AVOFF(cur);

        float s[8][4];
#pragma unroll
        for (int nt = 0; nt < 8; nt++)
#pragma unroll
            for (int i = 0; i < 4; i++) s[nt][i] = 0.f;

#pragma unroll
        for (int ksp = 0; ksp < 4; ksp++) {
            unsigned a0[4] = { qa[2*ksp].x, qa[2*ksp].y, qa[2*ksp].z, qa[2*ksp].w };
            unsigned a1[4] = { qa[2*ksp+1].x, qa[2*ksp+1].y, qa[2*ksp+1].z, qa[2*ksp+1].w };
#pragma unroll
            for (int nt = 0; nt < 8; nt++) {
                uint4 bv = *(const uint4*)&Kc[((nt * 4 + ksp) << 7) + lane * 4];
                unsigned bf0[2] = { bv.x, bv.y };
                unsigned bf1[2] = { bv.z, bv.w };
                mma_tf32(s[nt], a0, bf0);
                mma_tf32(s[nt], a1, bf1);
            }
        }

        int qr0 = w * 16 + g, qr1 = qr0 + 8;
        const unsigned char* m0p = g_mask8 + ((size_t)(b * QL + q0 + qr0)) * KL + kt * 64;
        const unsigned char* m1p = g_mask8 + ((size_t)(b * QL + q0 + qr1)) * KL + kt * 64;
        float rs0 = 0.f, rs1 = 0.f;
#pragma unroll
        for (int nt = 0; nt < 8; nt++) {
            int kc = 2 * t;
            float p00, p01, p10, p11;
            if (allTrue) {
                p00 = __expf(s[nt][0]); p01 = __expf(s[nt][1]);
                p10 = __expf(s[nt][2]); p11 = __expf(s[nt][3]);
            } else {
                int kg = nt * 8 + kc;
                p00 = m0p[kg]     ? __expf(s[nt][0]) : 0.f;
                p01 = m0p[kg + 1] ? __expf(s[nt][1]) : 0.f;
                p10 = m1p[kg]     ? __expf(s[nt][2]) : 0.f;
                p11 = m1p[kg + 1] ? __expf(s[nt][3]) : 0.f;
            }
            rs0 += p00 + p01;
            rs1 += p10 + p11;
            // P A-frag: pairs (j0, j0+1) are adjacent 8B-aligned words -> STS.64
            int l00 = g * 4 + (kc & 3);
            int l01 = g * 4 + ((kc + 1) & 3);
            int j0 = 2 * (kc >> 2);
            *(uint2*)&Pw[nt * 128 + l00 * 4 + j0] = make_uint2(f2tf(p00), f2tf(p10));
            *(uint2*)&Pw[nt * 128 + l01 * 4 + j0] = make_uint2(f2tf(p01), f2tf(p11));
        }
        rs0 += __shfl_xor_sync(0xffffffffu, rs0, 1);
        rs0 += __shfl_xor_sync(0xffffffffu, rs0, 2);
        rs1 += __shfl_xor_sync(0xffffffffu, rs1, 1);
        rs1 += __shfl_xor_sync(0xffffffffu, rs1, 2);
        l0 += rs0;
        l1 += rs1;
        __syncwarp();

#pragma unroll
        for (int ksp = 0; ksp < 4; ksp++) {
            uint4 pav0 = *(const uint4*)&Pw[((2 * ksp) << 7) + lane * 4];
            uint4 pav1 = *(const uint4*)&Pw[((2 * ksp + 1) << 7) + lane * 4];
            unsigned a0[4] = { pav0.x, pav0.y, pav0.z, pav0.w };
            unsigned a1[4] = { pav1.x, pav1.y, pav1.z, pav1.w };
#pragma unroll
            for (int nt = 0; nt < 8; nt++) {
                uint4 bv = *(const uint4*)&Vc[((nt * 4 + ksp) << 7) + lane * 4];
                unsigned bf0[2] = { bv.x, bv.y };
                unsigned bf1[2] = { bv.z, bv.w };
                mma_tf32(o[nt], a0, bf0);
                mma_tf32(o[nt], a1, bf1);
            }
        }
        __syncwarp();
    }

    float inv0 = 1.f / l0, inv1 = 1.f / l1;
    int ma = b * QL + q0 + w * 16 + g;
    int mbq = ma + 8;
    unsigned* Vo = (unsigned*)g_valsA;
#pragma unroll
    for (int nt = 0; nt < 8; nt++) {
        int d = nt * 8 + 2 * t;
#pragma unroll
        for (int e = 0; e < 4; e++) {
            int dd, mm;
            float val;
            if (e == 0)      { mm = ma;  dd = d;     val = o[nt][0] * inv0; }
            else if (e == 1) { mm = ma;  dd = d + 1; val = o[nt][1] * inv0; }
            else if (e == 2) { mm = mbq; dd = d;     val = o[nt][2] * inv1; }
            else             { mm = mbq; dd = d + 1; val = o[nt][3] * inv1; }
            int ncol = dd * NH + h;
            int mt2 = mm >> 7, kt2 = ncol >> 5;
            int am = (mm >> 4) & 7, ak = (ncol >> 3) & 3;
            int l = (mm & 7) * 4 + (ncol & 3);
            int j = ((mm >> 3) & 1) + 2 * ((ncol >> 2) & 1);
            Vo[(size_t)(mt2 * 32 + kt2) * 4096 + (am * 4 + ak) * 128 + l * 4 + j] = f2tf(val);
        }
    }
}

// ---------------------------------------------------------------------------
extern "C" void kernel_launch(void* const* d_in, const int* in_sizes, int n_in,
                              void* d_out, int out_size)
{
    const float* dec  = (const float*)d_in[0];
    const float* enc  = (const float*)d_in[1];
    const unsigned char* mask = (const unsigned char*)d_in[2];
    const float* Wq   = (const float*)d_in[3];
    const float* Wkv  = (const float*)d_in[4];
    const float* Wout = (const float*)d_in[5];
    float* out = (float*)d_out;

    cudaFuncSetAttribute(final_gemm,   cudaFuncAttributeMaxDynamicSharedMemorySize, FRAG_SMEM);
    cudaFuncSetAttribute(proj_w2_gemm, cudaFuncAttributeMaxDynamicSharedMemorySize, FRAG_SMEM);
    cudaFuncSetAttribute(attn_kernel,  cudaFuncAttributeMaxDynamicSharedMemorySize, ATT_SMEM);

    const int M = BATCH * QL; // 4096
    const int NMASK = BATCH * QL * KL;
    dim3 blk(128);

    mask_detect_kernel<<<1, 256>>>(mask);
    // cvt (frag transforms) + mask all-true scan, one launch
    cvt_frag_kernel<<<CVT_BLOCKS + SCAN_BLOCKS, 256>>>(dec, enc, Wq, Wkv, Wout, mask);
    mask_convert_kernel<<<(NMASK + 255) / 256, 256>>>(mask, NMASK);

    // merged Q + KV projections + W2, one wave
    proj_w2_gemm<<<dim3(832), blk, FRAG_SMEM>>>();
    // fused attention (all-frag, paired K/V) -> g_valsA
    attn_kernel<<<dim3(QL / 64, BATCH * NH), dim3(128), ATT_SMEM>>>();
    // out = vals @ W2^T
    final_gemm<<<dim3(8, M / 128), blk, FRAG_SMEM>>>(out);
}